// round 1
// baseline (speedup 1.0000x reference)
#include <cuda_runtime.h>

#define Bc 2
#define Sc 2048
#define Dc 1024
#define Hc 16
#define HDc 64
#define QT 16
#define KT 256

// Scratch (allocation-free: device globals)
__device__ float g_Q[Bc*Hc*Sc*HDc];
__device__ float g_K[Bc*Hc*Sc*HDc];
__device__ float g_V[Bc*Hc*Sc*HDc];
__device__ float g_Z[Bc*Sc*Dc];

// ---------------- QKV projection ----------------
// grid (S/64, H, B), 256 threads. Y[s][e] = sum_d X[s][d] * W[e][d], per head.
__global__ __launch_bounds__(256) void qkv_proj(
    const float* __restrict__ Xq, const float* __restrict__ Xk, const float* __restrict__ Xv,
    const float* __restrict__ Wq, const float* __restrict__ Wk, const float* __restrict__ Wv)
{
    __shared__ float Xs[64*65];
    __shared__ float Ws[64*65];
    int s0 = blockIdx.x*64, h = blockIdx.y, b = blockIdx.z;
    int tid = threadIdx.x;
    const float inv4 = 0.35355339059327373f; // HD^-0.25
    const float* Xin[3] = {Xq, Xk, Xv};
    const float* Win[3] = {Wq, Wk, Wv};
    float* Out[3] = {g_Q, g_K, g_V};
    int m  = tid & 15;   // e = m + 16*i
    int s4 = tid >> 4;   // s = s4 + 16*j

    for (int t = 0; t < 3; t++) {
        const float* W = Win[t] + h*64*64;
        const float* X = Xin[t] + ((size_t)b*Sc + s0)*Dc + h*64;
        for (int i = tid; i < 4096; i += 256) { int e=i>>6, d=i&63; Ws[e*65+d]=W[i]; }
        for (int i = tid; i < 4096; i += 256) { int r=i>>6, d=i&63; Xs[r*65+d]=X[(size_t)r*Dc+d]; }
        __syncthreads();
        float acc[4][4] = {};
        #pragma unroll 8
        for (int d = 0; d < 64; d++) {
            float wv[4], xv[4];
            #pragma unroll
            for (int i = 0; i < 4; i++) wv[i] = Ws[(m+16*i)*65 + d];
            #pragma unroll
            for (int j = 0; j < 4; j++) xv[j] = Xs[(s4+16*j)*65 + d];
            #pragma unroll
            for (int j = 0; j < 4; j++)
                #pragma unroll
                for (int i = 0; i < 4; i++)
                    acc[j][i] += xv[j]*wv[i];
        }
        float scl = (t < 2) ? inv4 : 1.0f;
        float* O = Out[t] + (((size_t)b*Hc + h)*Sc + s0)*64;
        #pragma unroll
        for (int j = 0; j < 4; j++)
            #pragma unroll
            for (int i = 0; i < 4; i++)
                O[(size_t)(s4+16*j)*64 + (m+16*i)] = acc[j][i]*scl;
        __syncthreads();
    }
}

// ---------------- Attention ----------------
// grid (S/QT, B), 256 threads, ~203KB dynamic smem.
// Per block: 16 queries, loop over all heads serially (deterministic attn_mean).
__global__ __launch_bounds__(256,1) void attn_kernel(float* __restrict__ attn_out)
{
    extern __shared__ float smem[];
    float* sc = smem;                 // QT * Sc        (score rows, fp32)
    float* kv = smem + QT*Sc;         // KT * 66        (K tile pad65 / V tile pad66)
    float* qs = kv + KT*66;           // QT * 65
    int q0g = blockIdx.x*QT;
    int b   = blockIdx.y;
    int tid = threadIdx.x;
    int lane = tid & 31, warp = tid >> 5;
    int k0 = tid & 63, qb = tid >> 6;     // score phase: k = k0+64i, q = qb+4j
    int e2 = tid & 31, qg2 = tid >> 5;    // Z phase: e = 2*e2(+1), q = qg2 / qg2+8
    const float invH = 1.0f/Hc;

    for (int h = 0; h < Hc; h++) {
        const float* Qg = g_Q + (((size_t)b*Hc+h)*Sc + q0g)*64;
        const float* Kg = g_K + (((size_t)b*Hc+h)*Sc)*64;
        const float* Vg = g_V + (((size_t)b*Hc+h)*Sc)*64;
        for (int i = tid; i < QT*64; i += 256) { int q=i>>6, d=i&63; qs[q*65+d]=Qg[i]; }
        __syncthreads();

        // ---- scores S[q][k] = Q . K ----
        for (int kb = 0; kb < Sc; kb += KT) {
            const float4* Ksrc = (const float4*)(Kg + (size_t)kb*64);
            for (int i = tid; i < KT*16; i += 256) {
                int r = i>>4, c4 = i&15;
                float4 v = Ksrc[i];
                float* dst = &kv[r*65 + c4*4];
                dst[0]=v.x; dst[1]=v.y; dst[2]=v.z; dst[3]=v.w;
            }
            __syncthreads();
            float acc[4][4] = {};
            #pragma unroll 8
            for (int d = 0; d < 64; d++) {
                float qv[4], kvv[4];
                #pragma unroll
                for (int j=0;j<4;j++) qv[j]  = qs[(qb+4*j)*65+d];
                #pragma unroll
                for (int i=0;i<4;i++) kvv[i] = kv[(k0+64*i)*65+d];
                #pragma unroll
                for (int j=0;j<4;j++)
                    #pragma unroll
                    for (int i=0;i<4;i++) acc[j][i] += qv[j]*kvv[i];
            }
            #pragma unroll
            for (int j=0;j<4;j++)
                #pragma unroll
                for (int i=0;i<4;i++)
                    sc[(qb+4*j)*Sc + kb + k0 + 64*i] = acc[j][i];
            __syncthreads();
        }

        // ---- softmax: warp w owns rows 2w, 2w+1 ----
        #pragma unroll
        for (int rr = 0; rr < 2; rr++) {
            int r = warp*2 + rr;
            float* row = sc + r*Sc;
            float mval = -1e30f;
            for (int t = lane; t < Sc; t += 32) mval = fmaxf(mval, row[t]);
            #pragma unroll
            for (int o=16;o;o>>=1) mval = fmaxf(mval, __shfl_xor_sync(0xffffffffu, mval, o));
            float sum = 0.f;
            for (int t = lane; t < Sc; t += 32) { float p = __expf(row[t]-mval); row[t]=p; sum+=p; }
            #pragma unroll
            for (int o=16;o;o>>=1) sum += __shfl_xor_sync(0xffffffffu, sum, o);
            float inv = 1.0f/sum;
            for (int t = lane; t < Sc; t += 32) row[t] *= inv;
        }
        __syncthreads();

        // ---- attn_mean accumulate (block owns these rows -> deterministic) ----
        float* am = attn_out + ((size_t)b*Sc + q0g)*Sc;
        if (h == 0) {
            for (int i = tid; i < QT*Sc; i += 256) am[i] = sc[i]*invH;
        } else {
            for (int i = tid; i < QT*Sc; i += 256) am[i] += sc[i]*invH;
        }

        // ---- Z = P @ V ----
        float z00=0.f, z01=0.f, z10=0.f, z11=0.f;
        const float* prow0 = sc + (size_t)qg2*Sc;
        const float* prow1 = sc + (size_t)(qg2+8)*Sc;
        for (int kb = 0; kb < Sc; kb += KT) {
            const float4* Vsrc = (const float4*)(Vg + (size_t)kb*64);
            for (int i = tid; i < KT*16; i += 256) {
                int r = i>>4, c4 = i&15;
                float4 v = Vsrc[i];
                float* dst = &kv[r*66 + c4*4];
                dst[0]=v.x; dst[1]=v.y; dst[2]=v.z; dst[3]=v.w;
            }
            __syncthreads();
            #pragma unroll 4
            for (int kk = 0; kk < KT; kk++) {
                float p0 = prow0[kb+kk];
                float p1 = prow1[kb+kk];
                float2 v = *(const float2*)&kv[kk*66 + 2*e2];
                z00 += p0*v.x; z01 += p0*v.y;
                z10 += p1*v.x; z11 += p1*v.y;
            }
            __syncthreads();
        }
        float* Zg = g_Z + ((size_t)b*Sc + q0g)*Dc + h*64;
        Zg[(size_t)qg2*Dc + 2*e2]       = z00;
        Zg[(size_t)qg2*Dc + 2*e2+1]     = z01;
        Zg[(size_t)(qg2+8)*Dc + 2*e2]   = z10;
        Zg[(size_t)(qg2+8)*Dc + 2*e2+1] = z11;
        __syncthreads();
    }
}

// ---------------- Output projection ----------------
// out[s][n] = sum_k Z[s][k]*Wz[n][k] + bz[n].  grid (D/64, B*S/64), 256 thr.
__global__ __launch_bounds__(256) void out_proj(
    const float* __restrict__ Wz, const float* __restrict__ bz, float* __restrict__ out)
{
    __shared__ float As[64*33];
    __shared__ float Bs[64*33];
    int n0 = blockIdx.x*64;
    int s0 = blockIdx.y*64;
    int tid = threadIdx.x;
    int m  = tid & 15;   // n = n0 + m + 16*i
    int s4 = tid >> 4;   // s = s0 + s4 + 16*j
    float acc[4][4] = {};
    for (int k0 = 0; k0 < Dc; k0 += 32) {
        for (int i = tid; i < 2048; i += 256) { int r=i>>5, c=i&31; As[r*33+c] = g_Z[(size_t)(s0+r)*Dc + k0 + c]; }
        for (int i = tid; i < 2048; i += 256) { int r=i>>5, c=i&31; Bs[r*33+c] = Wz[(size_t)(n0+r)*Dc + k0 + c]; }
        __syncthreads();
        #pragma unroll 8
        for (int d = 0; d < 32; d++) {
            float av[4], bv[4];
            #pragma unroll
            for (int j=0;j<4;j++) av[j]=As[(s4+16*j)*33+d];
            #pragma unroll
            for (int i=0;i<4;i++) bv[i]=Bs[(m+16*i)*33+d];
            #pragma unroll
            for (int j=0;j<4;j++)
                #pragma unroll
                for (int i=0;i<4;i++) acc[j][i] += av[j]*bv[i];
        }
        __syncthreads();
    }
    #pragma unroll
    for (int i=0;i<4;i++) {
        float bias = bz[n0 + m + 16*i];
        #pragma unroll
        for (int j=0;j<4;j++)
            out[(size_t)(s0+s4+16*j)*Dc + n0 + m + 16*i] = acc[j][i] + bias;
    }
}

extern "C" void kernel_launch(void* const* d_in, const int* in_sizes, int n_in,
                              void* d_out, int out_size)
{
    const float* Xq = (const float*)d_in[0];
    const float* Xk = (const float*)d_in[1];
    const float* Xv = (const float*)d_in[2];
    const float* Wq = (const float*)d_in[3];
    const float* Wk = (const float*)d_in[4];
    const float* Wv = (const float*)d_in[5];
    const float* Wz = (const float*)d_in[6];
    const float* bz = (const float*)d_in[7];
    float* out  = (float*)d_out;
    float* attn = out + (size_t)Bc*Sc*Dc;   // out first, then attn_mean

    const int smem_bytes = (QT*Sc + KT*66 + QT*65)*(int)sizeof(float); // 202816
    cudaFuncSetAttribute((const void*)attn_kernel,
                         cudaFuncAttributeMaxDynamicSharedMemorySize, smem_bytes);

    qkv_proj<<<dim3(Sc/64, Hc, Bc), 256>>>(Xq, Xk, Xv, Wq, Wk, Wv);
    attn_kernel<<<dim3(Sc/QT, Bc), 256, smem_bytes>>>(attn);
    out_proj<<<dim3(Dc/64, (Bc*Sc)/64), 256>>>(Wz, bz, out);
}

// round 3
// speedup vs baseline: 2.9785x; 2.9785x over previous
#include <cuda_runtime.h>
#include <cuda_bf16.h>
#include <cstdint>

#define Bc 2
#define Sc 2048
#define Dc 1024
#define Hc 16
#define HDc 64

// ---------------- scratch globals (allocation-free) ----------------
__device__ __nv_bfloat16 g_Qh[Bc*Hc*Sc*HDc];
__device__ __nv_bfloat16 g_Ql[Bc*Hc*Sc*HDc];
__device__ __nv_bfloat16 g_Kh[Bc*Hc*Sc*HDc];
__device__ __nv_bfloat16 g_Kl[Bc*Hc*Sc*HDc];
__device__ __nv_bfloat16 g_Vth[Bc*Hc*Sc*HDc];   // [b,h,e,s] transposed
__device__ __nv_bfloat16 g_Vtl[Bc*Hc*Sc*HDc];
__device__ float g_Z[Bc*Sc*Dc];
__device__ float g_S[134217728];                 // [b,h,q,k] unnormalized exp(score)
__device__ float g_isum[Bc*Hc*Sc];               // 1/rowsum

// ---------------- warp MMA helpers (base ISA: valid on sm_103 plain) ----------------
__device__ __forceinline__ void ldm4(uint32_t addr, uint32_t* r) {
    asm volatile("ldmatrix.sync.aligned.m8n8.x4.shared.b16 {%0,%1,%2,%3}, [%4];"
                 : "=r"(r[0]), "=r"(r[1]), "=r"(r[2]), "=r"(r[3]) : "r"(addr));
}
__device__ __forceinline__ void mma16816(float* c, const uint32_t* a, uint32_t b0, uint32_t b1) {
    asm volatile("mma.sync.aligned.m16n8k16.row.col.f32.bf16.bf16.f32 "
                 "{%0,%1,%2,%3}, {%4,%5,%6,%7}, {%8,%9}, {%0,%1,%2,%3};"
                 : "+f"(c[0]), "+f"(c[1]), "+f"(c[2]), "+f"(c[3])
                 : "r"(a[0]), "r"(a[1]), "r"(a[2]), "r"(a[3]), "r"(b0), "r"(b1));
}
__device__ __forceinline__ uint32_t pack_bf2(__nv_bfloat16 a, __nv_bfloat16 b) {
    return (uint32_t)__bfloat16_as_ushort(a) | ((uint32_t)__bfloat16_as_ushort(b) << 16);
}

// ---------------- QKV projection (writes bf16 hi/lo; V transposed; log2e folded into Q) ----
__global__ __launch_bounds__(256) void qkv_proj(
    const float* __restrict__ Xq, const float* __restrict__ Xk, const float* __restrict__ Xv,
    const float* __restrict__ Wq, const float* __restrict__ Wk, const float* __restrict__ Wv)
{
    __shared__ float Xs[64*65];
    __shared__ float Ws[64*65];
    int s0 = blockIdx.x*64, h = blockIdx.y, b = blockIdx.z;
    int tid = threadIdx.x;
    const float inv4 = 0.35355339059327373f; // HD^-0.25
    const float l2e  = 1.4426950408889634f;
    const float* Xin[3] = {Xq, Xk, Xv};
    const float* Win[3] = {Wq, Wk, Wv};
    int m  = tid & 15;   // e = m + 16*i
    int s4 = tid >> 4;   // s = s4 + 16*j

    for (int t = 0; t < 3; t++) {
        const float* W = Win[t] + h*64*64;
        const float* X = Xin[t] + ((size_t)b*Sc + s0)*Dc + h*64;
        for (int i = tid; i < 4096; i += 256) { int e=i>>6, d=i&63; Ws[e*65+d]=W[i]; }
        for (int i = tid; i < 4096; i += 256) { int r=i>>6, d=i&63; Xs[r*65+d]=X[(size_t)r*Dc+d]; }
        __syncthreads();
        float acc[4][4] = {};
        #pragma unroll 8
        for (int d = 0; d < 64; d++) {
            float wv[4], xv[4];
            #pragma unroll
            for (int i = 0; i < 4; i++) wv[i] = Ws[(m+16*i)*65 + d];
            #pragma unroll
            for (int j = 0; j < 4; j++) xv[j] = Xs[(s4+16*j)*65 + d];
            #pragma unroll
            for (int j = 0; j < 4; j++)
                #pragma unroll
                for (int i = 0; i < 4; i++)
                    acc[j][i] += xv[j]*wv[i];
        }
        float scl = (t == 0) ? inv4*l2e : (t == 1 ? inv4 : 1.0f);
        if (t < 2) {
            __nv_bfloat16* Oh = (t==0 ? g_Qh : g_Kh) + (((size_t)b*Hc + h)*Sc + s0)*64;
            __nv_bfloat16* Ol = (t==0 ? g_Ql : g_Kl) + (((size_t)b*Hc + h)*Sc + s0)*64;
            #pragma unroll
            for (int j = 0; j < 4; j++)
                #pragma unroll
                for (int i = 0; i < 4; i++) {
                    float x = acc[j][i]*scl;
                    __nv_bfloat16 hi = __float2bfloat16(x);
                    __nv_bfloat16 lo = __float2bfloat16(x - __bfloat162float(hi));
                    size_t idx = (size_t)(s4+16*j)*64 + (m+16*i);
                    Oh[idx] = hi; Ol[idx] = lo;
                }
        } else {
            __nv_bfloat16* Oh = g_Vth + ((size_t)b*Hc + h)*64*Sc;
            __nv_bfloat16* Ol = g_Vtl + ((size_t)b*Hc + h)*64*Sc;
            #pragma unroll
            for (int j = 0; j < 4; j++)
                #pragma unroll
                for (int i = 0; i < 4; i++) {
                    float x = acc[j][i];
                    __nv_bfloat16 hi = __float2bfloat16(x);
                    __nv_bfloat16 lo = __float2bfloat16(x - __bfloat162float(hi));
                    size_t idx = (size_t)(m+16*i)*Sc + s0 + s4 + 16*j;   // [e][s]
                    Oh[idx] = hi; Ol[idx] = lo;
                }
        }
        __syncthreads();
    }
}

// ---------------- flash attention (warp HMMA) ----------------
// grid (S/128, H, B), 256 threads (8 warps x 16 q-rows), ~174KB dyn smem.
// smem byte offsets (Q/K stride 144B = 72 elems; V^T/P stride 272B = 136 elems)
#define SM_QH 0
#define SM_QL 18432
#define SM_KH 36864
#define SM_KL 55296
#define SM_VH 73728
#define SM_VL 91136
#define SM_PH 108544
#define SM_PL 143360
#define SMEM_FL 178176

__device__ __forceinline__ void stage64(char* smem, int off, const __nv_bfloat16* gsrc, int tid) {
    const float4* gs = (const float4*)gsrc;
    #pragma unroll
    for (int it = 0; it < 4; it++) {
        int i = tid + it*256;
        int r = i >> 3, c = i & 7;
        *(float4*)(smem + off + r*144 + c*16) = gs[i];
    }
}
__device__ __forceinline__ void stageVt(char* smem, int off, const float4* gv, int kb, int tid) {
    #pragma unroll
    for (int it = 0; it < 4; it++) {
        int i = tid + it*256;
        int e = i >> 4, c = i & 15;
        *(float4*)(smem + off + e*272 + c*16) = gv[e*256 + kb*16 + c];
    }
}

__global__ __launch_bounds__(256,1) void flash_attn()
{
    extern __shared__ char smem[];
    uint32_t sb = (uint32_t)__cvta_generic_to_shared(smem);
    int tid = threadIdx.x, wid = tid >> 5, lane = tid & 31;
    int q0 = blockIdx.x*128, h = blockIdx.y, b = blockIdx.z;
    size_t bh = (size_t)b*Hc + h;
    int g = lane >> 2, t = lane & 3;
    int row0 = 16*wid + g;     // first q row owned by this thread (second is row0+8)

    stage64(smem, SM_QH, g_Qh + (bh*Sc + q0)*64, tid);
    stage64(smem, SM_QL, g_Ql + (bh*Sc + q0)*64, tid);
    __syncthreads();

    // Q fragments (persist across key tiles): 4 k-steps, hi + lo
    uint32_t qh[4][4], ql[4][4];
    #pragma unroll
    for (int ks = 0; ks < 4; ks++) {
        uint32_t aaddr = sb + SM_QH + (16*wid + (lane & 15))*144 + ks*32 + ((lane >> 4) << 4);
        ldm4(aaddr, qh[ks]);
        ldm4(aaddr + (SM_QL - SM_QH), ql[ks]);
    }

    float z[32];
    #pragma unroll
    for (int i = 0; i < 32; i++) z[i] = 0.f;
    float rs0 = 0.f, rs1 = 0.f;
    float* gS0 = g_S + (bh*Sc + q0 + row0)*Sc;
    float* gS1 = gS0 + (size_t)8*Sc;
    const float4* gvh = (const float4*)(g_Vth + bh*(size_t)64*Sc);
    const float4* gvl = (const float4*)(g_Vtl + bh*(size_t)64*Sc);

    for (int kb = 0; kb < Sc/128; kb++) {
        __syncthreads();   // prior iter's ldmatrix reads done before overwrite
        stage64(smem, SM_KH, g_Kh + (bh*Sc + (size_t)kb*128)*64, tid);
        stage64(smem, SM_KL, g_Kl + (bh*Sc + (size_t)kb*128)*64, tid);
        stageVt(smem, SM_VH, gvh, kb, tid);
        stageVt(smem, SM_VL, gvl, kb, tid);
        __syncthreads();

        // ---- scores: S = Qh*Kh + Ql*Kh + Qh*Kl  (128x128, contraction 64) ----
        float s[64];
        #pragma unroll
        for (int i = 0; i < 64; i++) s[i] = 0.f;
        #pragma unroll
        for (int ks = 0; ks < 4; ks++) {
            #pragma unroll
            for (int nb2 = 0; nb2 < 8; nb2++) {
                uint32_t baddr = sb + SM_KH + (nb2*16 + (lane & 7) + ((lane >> 4) << 3))*144
                               + ks*32 + (((lane >> 3) & 1) << 4);
                uint32_t bhf[4], blf[4];
                ldm4(baddr, bhf);
                ldm4(baddr + (SM_KL - SM_KH), blf);
                mma16816(s + (2*nb2)*4,   qh[ks], bhf[0], bhf[1]);
                mma16816(s + (2*nb2+1)*4, qh[ks], bhf[2], bhf[3]);
                mma16816(s + (2*nb2)*4,   ql[ks], bhf[0], bhf[1]);
                mma16816(s + (2*nb2+1)*4, ql[ks], bhf[2], bhf[3]);
                mma16816(s + (2*nb2)*4,   qh[ks], blf[0], blf[1]);
                mma16816(s + (2*nb2+1)*4, qh[ks], blf[2], blf[3]);
            }
        }

        // ---- epilogue: exp2, rowsum, g_S store, P hi/lo -> smem ----
        #pragma unroll
        for (int nb = 0; nb < 16; nb++) {
            float e0 = exp2f(s[nb*4+0]);
            float e1 = exp2f(s[nb*4+1]);
            float e2 = exp2f(s[nb*4+2]);
            float e3 = exp2f(s[nb*4+3]);
            rs0 += e0 + e1; rs1 += e2 + e3;
            int col = kb*128 + nb*8 + 2*t;
            *(float2*)(gS0 + col) = make_float2(e0, e1);
            *(float2*)(gS1 + col) = make_float2(e2, e3);
            __nv_bfloat16 h0 = __float2bfloat16(e0), h1 = __float2bfloat16(e1);
            __nv_bfloat16 h2 = __float2bfloat16(e2), h3 = __float2bfloat16(e3);
            __nv_bfloat16 l0 = __float2bfloat16(e0 - __bfloat162float(h0));
            __nv_bfloat16 l1 = __float2bfloat16(e1 - __bfloat162float(h1));
            __nv_bfloat16 l2 = __float2bfloat16(e2 - __bfloat162float(h2));
            __nv_bfloat16 l3 = __float2bfloat16(e3 - __bfloat162float(h3));
            int pc = (nb*8 + 2*t)*2;   // byte col
            char* p0 = smem + SM_PH + row0*272 + pc;
            char* p1 = p0 + 8*272;
            *(uint32_t*)p0 = pack_bf2(h0, h1);
            *(uint32_t*)p1 = pack_bf2(h2, h3);
            *(uint32_t*)(p0 + (SM_PL - SM_PH)) = pack_bf2(l0, l1);
            *(uint32_t*)(p1 + (SM_PL - SM_PH)) = pack_bf2(l2, l3);
        }
        __syncwarp();   // P rows are warp-local: warp-level visibility suffices

        // ---- Z += Ph*Vh + Pl*Vh + Ph*Vl  (128x64, contraction 128) ----
        #pragma unroll
        for (int ks = 0; ks < 8; ks++) {
            uint32_t paddr = sb + SM_PH + (16*wid + (lane & 15))*272 + ks*32 + ((lane >> 4) << 4);
            uint32_t ah[4], al[4];
            ldm4(paddr, ah);
            ldm4(paddr + (SM_PL - SM_PH), al);
            #pragma unroll
            for (int nb2 = 0; nb2 < 4; nb2++) {
                uint32_t vaddr = sb + SM_VH + (nb2*16 + (lane & 7) + ((lane >> 4) << 3))*272
                               + ks*32 + (((lane >> 3) & 1) << 4);
                uint32_t bhf[4], blf[4];
                ldm4(vaddr, bhf);
                ldm4(vaddr + (SM_VL - SM_VH), blf);
                mma16816(z + (2*nb2)*4,   ah, bhf[0], bhf[1]);
                mma16816(z + (2*nb2+1)*4, ah, bhf[2], bhf[3]);
                mma16816(z + (2*nb2)*4,   al, bhf[0], bhf[1]);
                mma16816(z + (2*nb2+1)*4, al, bhf[2], bhf[3]);
                mma16816(z + (2*nb2)*4,   ah, blf[0], blf[1]);
                mma16816(z + (2*nb2+1)*4, ah, blf[2], blf[3]);
            }
        }
    }

    // rowsum reduce within quad (t = lane&3)
    #pragma unroll
    for (int o = 1; o <= 2; o <<= 1) {
        rs0 += __shfl_xor_sync(0xffffffffu, rs0, o);
        rs1 += __shfl_xor_sync(0xffffffffu, rs1, o);
    }
    float inv0 = 1.f/rs0, inv1 = 1.f/rs1;
    float* z0 = g_Z + ((size_t)b*Sc + q0 + row0)*Dc + h*64;
    float* z1 = z0 + (size_t)8*Dc;
    #pragma unroll
    for (int nb = 0; nb < 8; nb++) {
        int col = nb*8 + 2*t;
        *(float2*)(z0 + col) = make_float2(z[nb*4+0]*inv0, z[nb*4+1]*inv0);
        *(float2*)(z1 + col) = make_float2(z[nb*4+2]*inv1, z[nb*4+3]*inv1);
    }
    if (t == 0) {
        g_isum[bh*Sc + q0 + row0]     = inv0;
        g_isum[bh*Sc + q0 + row0 + 8] = inv1;
    }
}

// ---------------- attn_mean: am[b,q,k] = (1/H) sum_h g_S[b,h,q,k]*isum[b,h,q] ----------------
__global__ __launch_bounds__(256) void attn_mean_kernel(float* __restrict__ am)
{
    int q = blockIdx.x, b = blockIdx.y, t = threadIdx.x;
    float4 a0 = make_float4(0,0,0,0), a1 = make_float4(0,0,0,0);
    #pragma unroll 1
    for (int h = 0; h < Hc; h++) {
        float w = g_isum[((size_t)b*Hc + h)*Sc + q];
        const float4* row = (const float4*)(g_S + (((size_t)b*Hc + h)*Sc + q)*Sc);
        float4 v0 = row[t], v1 = row[t + 256];
        a0.x += v0.x*w; a0.y += v0.y*w; a0.z += v0.z*w; a0.w += v0.w*w;
        a1.x += v1.x*w; a1.y += v1.y*w; a1.z += v1.z*w; a1.w += v1.w*w;
    }
    const float invH = 1.0f/Hc;
    float4* dst = (float4*)(am + ((size_t)b*Sc + q)*Sc);
    dst[t]       = make_float4(a0.x*invH, a0.y*invH, a0.z*invH, a0.w*invH);
    dst[t + 256] = make_float4(a1.x*invH, a1.y*invH, a1.z*invH, a1.w*invH);
}

// ---------------- Output projection ----------------
__global__ __launch_bounds__(256) void out_proj(
    const float* __restrict__ Wz, const float* __restrict__ bz, float* __restrict__ out)
{
    __shared__ float As[64*33];
    __shared__ float Bs[64*33];
    int n0 = blockIdx.x*64;
    int s0 = blockIdx.y*64;
    int tid = threadIdx.x;
    int m  = tid & 15;
    int s4 = tid >> 4;
    float acc[4][4] = {};
    for (int k0 = 0; k0 < Dc; k0 += 32) {
        for (int i = tid; i < 2048; i += 256) { int r=i>>5, c=i&31; As[r*33+c] = g_Z[(size_t)(s0+r)*Dc + k0 + c]; }
        for (int i = tid; i < 2048; i += 256) { int r=i>>5, c=i&31; Bs[r*33+c] = Wz[(size_t)(n0+r)*Dc + k0 + c]; }
        __syncthreads();
        #pragma unroll 8
        for (int d = 0; d < 32; d++) {
            float av[4], bv[4];
            #pragma unroll
            for (int j=0;j<4;j++) av[j]=As[(s4+16*j)*33+d];
            #pragma unroll
            for (int i=0;i<4;i++) bv[i]=Bs[(m+16*i)*33+d];
            #pragma unroll
            for (int j=0;j<4;j++)
                #pragma unroll
                for (int i=0;i<4;i++) acc[j][i] += av[j]*bv[i];
        }
        __syncthreads();
    }
    #pragma unroll
    for (int i=0;i<4;i++) {
        float bias = bz[n0 + m + 16*i];
        #pragma unroll
        for (int j=0;j<4;j++)
            out[(size_t)(s0+s4+16*j)*Dc + n0 + m + 16*i] = acc[j][i] + bias;
    }
}

extern "C" void kernel_launch(void* const* d_in, const int* in_sizes, int n_in,
                              void* d_out, int out_size)
{
    const float* Xq = (const float*)d_in[0];
    const float* Xk = (const float*)d_in[1];
    const float* Xv = (const float*)d_in[2];
    const float* Wq = (const float*)d_in[3];
    const float* Wk = (const float*)d_in[4];
    const float* Wv = (const float*)d_in[5];
    const float* Wz = (const float*)d_in[6];
    const float* bz = (const float*)d_in[7];
    float* out  = (float*)d_out;
    float* attn = out + (size_t)Bc*Sc*Dc;   // out first, then attn_mean

    cudaFuncSetAttribute((const void*)flash_attn,
                         cudaFuncAttributeMaxDynamicSharedMemorySize, SMEM_FL);

    qkv_proj<<<dim3(Sc/64, Hc, Bc), 256>>>(Xq, Xk, Xv, Wq, Wk, Wv);
    flash_attn<<<dim3(Sc/128, Hc, Bc), 256, SMEM_FL>>>();
    attn_mean_kernel<<<dim3(Sc, Bc), 256>>>(attn);
    out_proj<<<dim3(Dc/64, (Bc*Sc)/64), 256>>>(Wz, bz, out);
}

// round 4
// speedup vs baseline: 3.9276x; 1.3186x over previous
#include <cuda_runtime.h>
#include <cuda_bf16.h>
#include <cstdint>

#define Bc 2
#define Sc 2048
#define Dc 1024
#define Hc 16
#define HDc 64

// ---------------- scratch globals (allocation-free) ----------------
__device__ __nv_bfloat16 g_Qh[Bc*Hc*Sc*HDc];
__device__ __nv_bfloat16 g_Ql[Bc*Hc*Sc*HDc];
__device__ __nv_bfloat16 g_Kh[Bc*Hc*Sc*HDc];
__device__ __nv_bfloat16 g_Kl[Bc*Hc*Sc*HDc];
__device__ __nv_bfloat16 g_Vth[Bc*Hc*Sc*HDc];   // [b,h,e,s] transposed
__device__ __nv_bfloat16 g_Vtl[Bc*Hc*Sc*HDc];
__device__ __nv_bfloat16 g_Zh[Bc*Sc*Dc];        // Z bf16 hi/lo ([s][k], k contiguous)
__device__ __nv_bfloat16 g_Zl[Bc*Sc*Dc];
__device__ __nv_bfloat16 g_Wzh[Dc*Dc];          // Wz bf16 hi/lo ([n][k], k contiguous)
__device__ __nv_bfloat16 g_Wzl[Dc*Dc];
__device__ float g_S[134217728];                 // [b,h,q,k] unnormalized exp(score)
__device__ float g_isum[Bc*Hc*Sc];               // 1/rowsum

// ---------------- warp MMA helpers (base ISA: valid on sm_103 plain) ----------------
__device__ __forceinline__ void ldm4(uint32_t addr, uint32_t* r) {
    asm volatile("ldmatrix.sync.aligned.m8n8.x4.shared.b16 {%0,%1,%2,%3}, [%4];"
                 : "=r"(r[0]), "=r"(r[1]), "=r"(r[2]), "=r"(r[3]) : "r"(addr));
}
__device__ __forceinline__ void mma16816(float* c, const uint32_t* a, uint32_t b0, uint32_t b1) {
    asm volatile("mma.sync.aligned.m16n8k16.row.col.f32.bf16.bf16.f32 "
                 "{%0,%1,%2,%3}, {%4,%5,%6,%7}, {%8,%9}, {%0,%1,%2,%3};"
                 : "+f"(c[0]), "+f"(c[1]), "+f"(c[2]), "+f"(c[3])
                 : "r"(a[0]), "r"(a[1]), "r"(a[2]), "r"(a[3]), "r"(b0), "r"(b1));
}
__device__ __forceinline__ uint32_t pack_bf2(__nv_bfloat16 a, __nv_bfloat16 b) {
    return (uint32_t)__bfloat16_as_ushort(a) | ((uint32_t)__bfloat16_as_ushort(b) << 16);
}
__device__ __forceinline__ void split_bf(float x, __nv_bfloat16& hi, __nv_bfloat16& lo) {
    hi = __float2bfloat16(x);
    lo = __float2bfloat16(x - __bfloat162float(hi));
}

// ---------------- QKV projection (writes bf16 hi/lo; V transposed; log2e folded into Q) ----
__global__ __launch_bounds__(256) void qkv_proj(
    const float* __restrict__ Xq, const float* __restrict__ Xk, const float* __restrict__ Xv,
    const float* __restrict__ Wq, const float* __restrict__ Wk, const float* __restrict__ Wv)
{
    __shared__ float Xs[64*65];
    __shared__ float Ws[64*65];
    int s0 = blockIdx.x*64, h = blockIdx.y, b = blockIdx.z;
    int tid = threadIdx.x;
    const float inv4 = 0.35355339059327373f; // HD^-0.25
    const float l2e  = 1.4426950408889634f;
    const float* Xin[3] = {Xq, Xk, Xv};
    const float* Win[3] = {Wq, Wk, Wv};
    int m  = tid & 15;   // e = m + 16*i
    int s4 = tid >> 4;   // s = s4 + 16*j

    for (int t = 0; t < 3; t++) {
        const float* W = Win[t] + h*64*64;
        const float* X = Xin[t] + ((size_t)b*Sc + s0)*Dc + h*64;
        for (int i = tid; i < 4096; i += 256) { int e=i>>6, d=i&63; Ws[e*65+d]=W[i]; }
        for (int i = tid; i < 4096; i += 256) { int r=i>>6, d=i&63; Xs[r*65+d]=X[(size_t)r*Dc+d]; }
        __syncthreads();
        float acc[4][4] = {};
        #pragma unroll 8
        for (int d = 0; d < 64; d++) {
            float wv[4], xv[4];
            #pragma unroll
            for (int i = 0; i < 4; i++) wv[i] = Ws[(m+16*i)*65 + d];
            #pragma unroll
            for (int j = 0; j < 4; j++) xv[j] = Xs[(s4+16*j)*65 + d];
            #pragma unroll
            for (int j = 0; j < 4; j++)
                #pragma unroll
                for (int i = 0; i < 4; i++)
                    acc[j][i] += xv[j]*wv[i];
        }
        float scl = (t == 0) ? inv4*l2e : (t == 1 ? inv4 : 1.0f);
        if (t < 2) {
            __nv_bfloat16* Oh = (t==0 ? g_Qh : g_Kh) + (((size_t)b*Hc + h)*Sc + s0)*64;
            __nv_bfloat16* Ol = (t==0 ? g_Ql : g_Kl) + (((size_t)b*Hc + h)*Sc + s0)*64;
            #pragma unroll
            for (int j = 0; j < 4; j++)
                #pragma unroll
                for (int i = 0; i < 4; i++) {
                    float x = acc[j][i]*scl;
                    __nv_bfloat16 hi, lo; split_bf(x, hi, lo);
                    size_t idx = (size_t)(s4+16*j)*64 + (m+16*i);
                    Oh[idx] = hi; Ol[idx] = lo;
                }
        } else {
            __nv_bfloat16* Oh = g_Vth + ((size_t)b*Hc + h)*64*Sc;
            __nv_bfloat16* Ol = g_Vtl + ((size_t)b*Hc + h)*64*Sc;
            #pragma unroll
            for (int j = 0; j < 4; j++)
                #pragma unroll
                for (int i = 0; i < 4; i++) {
                    float x = acc[j][i];
                    __nv_bfloat16 hi, lo; split_bf(x, hi, lo);
                    size_t idx = (size_t)(m+16*i)*Sc + s0 + s4 + 16*j;   // [e][s]
                    Oh[idx] = hi; Ol[idx] = lo;
                }
        }
        __syncthreads();
    }
}

// ---------------- Wz -> bf16 hi/lo ----------------
__global__ __launch_bounds__(256) void wz_convert(const float* __restrict__ Wz)
{
    int i = (blockIdx.x*256 + threadIdx.x)*4;
    float4 v = *(const float4*)(Wz + i);
    __nv_bfloat16 h0,l0,h1,l1,h2,l2,h3,l3;
    split_bf(v.x,h0,l0); split_bf(v.y,h1,l1); split_bf(v.z,h2,l2); split_bf(v.w,h3,l3);
    *(uint32_t*)(g_Wzh + i)     = pack_bf2(h0,h1);
    *(uint32_t*)(g_Wzh + i + 2) = pack_bf2(h2,h3);
    *(uint32_t*)(g_Wzl + i)     = pack_bf2(l0,l1);
    *(uint32_t*)(g_Wzl + i + 2) = pack_bf2(l2,l3);
}

// ---------------- flash attention (warp HMMA) ----------------
// grid (S/128, H, B), 256 threads (8 warps x 16 q-rows), ~174KB dyn smem.
#define SM_QH 0
#define SM_QL 18432
#define SM_KH 36864
#define SM_KL 55296
#define SM_VH 73728
#define SM_VL 91136
#define SM_PH 108544
#define SM_PL 143360
#define SMEM_FL 178176

__device__ __forceinline__ void stage64(char* smem, int off, const __nv_bfloat16* gsrc, int tid) {
    const float4* gs = (const float4*)gsrc;
    #pragma unroll
    for (int it = 0; it < 4; it++) {
        int i = tid + it*256;
        int r = i >> 3, c = i & 7;
        *(float4*)(smem + off + r*144 + c*16) = gs[i];
    }
}
__device__ __forceinline__ void stageVt(char* smem, int off, const float4* gv, int kb, int tid) {
    #pragma unroll
    for (int it = 0; it < 4; it++) {
        int i = tid + it*256;
        int e = i >> 4, c = i & 15;
        *(float4*)(smem + off + e*272 + c*16) = gv[e*256 + kb*16 + c];
    }
}

__global__ __launch_bounds__(256,1) void flash_attn()
{
    extern __shared__ char smem[];
    uint32_t sb = (uint32_t)__cvta_generic_to_shared(smem);
    int tid = threadIdx.x, wid = tid >> 5, lane = tid & 31;
    int q0 = blockIdx.x*128, h = blockIdx.y, b = blockIdx.z;
    size_t bh = (size_t)b*Hc + h;
    int g = lane >> 2, t = lane & 3;
    int row0 = 16*wid + g;     // first q row owned by this thread (second is row0+8)

    stage64(smem, SM_QH, g_Qh + (bh*Sc + q0)*64, tid);
    stage64(smem, SM_QL, g_Ql + (bh*Sc + q0)*64, tid);
    __syncthreads();

    // Q fragments (persist across key tiles): 4 k-steps, hi + lo
    uint32_t qh[4][4], ql[4][4];
    #pragma unroll
    for (int ks = 0; ks < 4; ks++) {
        uint32_t aaddr = sb + SM_QH + (16*wid + (lane & 15))*144 + ks*32 + ((lane >> 4) << 4);
        ldm4(aaddr, qh[ks]);
        ldm4(aaddr + (SM_QL - SM_QH), ql[ks]);
    }

    float z[32];
    #pragma unroll
    for (int i = 0; i < 32; i++) z[i] = 0.f;
    float rs0 = 0.f, rs1 = 0.f;
    float* gS0 = g_S + (bh*Sc + q0 + row0)*Sc;
    float* gS1 = gS0 + (size_t)8*Sc;
    const float4* gvh = (const float4*)(g_Vth + bh*(size_t)64*Sc);
    const float4* gvl = (const float4*)(g_Vtl + bh*(size_t)64*Sc);

    for (int kb = 0; kb < Sc/128; kb++) {
        __syncthreads();   // prior iter's ldmatrix reads done before overwrite
        stage64(smem, SM_KH, g_Kh + (bh*Sc + (size_t)kb*128)*64, tid);
        stage64(smem, SM_KL, g_Kl + (bh*Sc + (size_t)kb*128)*64, tid);
        stageVt(smem, SM_VH, gvh, kb, tid);
        stageVt(smem, SM_VL, gvl, kb, tid);
        __syncthreads();

        // ---- scores: S = Qh*Kh + Ql*Kh + Qh*Kl  (128x128, contraction 64) ----
        float s[64];
        #pragma unroll
        for (int i = 0; i < 64; i++) s[i] = 0.f;
        #pragma unroll
        for (int ks = 0; ks < 4; ks++) {
            #pragma unroll
            for (int nb2 = 0; nb2 < 8; nb2++) {
                uint32_t baddr = sb + SM_KH + (nb2*16 + (lane & 7) + ((lane >> 4) << 3))*144
                               + ks*32 + (((lane >> 3) & 1) << 4);
                uint32_t bhf[4], blf[4];
                ldm4(baddr, bhf);
                ldm4(baddr + (SM_KL - SM_KH), blf);
                mma16816(s + (2*nb2)*4,   qh[ks], bhf[0], bhf[1]);
                mma16816(s + (2*nb2+1)*4, qh[ks], bhf[2], bhf[3]);
                mma16816(s + (2*nb2)*4,   ql[ks], bhf[0], bhf[1]);
                mma16816(s + (2*nb2+1)*4, ql[ks], bhf[2], bhf[3]);
                mma16816(s + (2*nb2)*4,   qh[ks], blf[0], blf[1]);
                mma16816(s + (2*nb2+1)*4, qh[ks], blf[2], blf[3]);
            }
        }

        // ---- epilogue: exp2, rowsum, g_S store, P hi/lo -> smem ----
        #pragma unroll
        for (int nb = 0; nb < 16; nb++) {
            float e0 = exp2f(s[nb*4+0]);
            float e1 = exp2f(s[nb*4+1]);
            float e2 = exp2f(s[nb*4+2]);
            float e3 = exp2f(s[nb*4+3]);
            rs0 += e0 + e1; rs1 += e2 + e3;
            int col = kb*128 + nb*8 + 2*t;
            *(float2*)(gS0 + col) = make_float2(e0, e1);
            *(float2*)(gS1 + col) = make_float2(e2, e3);
            __nv_bfloat16 h0,l0,h1,l1,h2,l2,h3,l3;
            split_bf(e0,h0,l0); split_bf(e1,h1,l1); split_bf(e2,h2,l2); split_bf(e3,h3,l3);
            int pc = (nb*8 + 2*t)*2;   // byte col
            char* p0 = smem + SM_PH + row0*272 + pc;
            char* p1 = p0 + 8*272;
            *(uint32_t*)p0 = pack_bf2(h0, h1);
            *(uint32_t*)p1 = pack_bf2(h2, h3);
            *(uint32_t*)(p0 + (SM_PL - SM_PH)) = pack_bf2(l0, l1);
            *(uint32_t*)(p1 + (SM_PL - SM_PH)) = pack_bf2(l2, l3);
        }
        __syncwarp();   // P rows are warp-local: warp-level visibility suffices

        // ---- Z += Ph*Vh + Pl*Vh + Ph*Vl  (128x64, contraction 128) ----
        #pragma unroll
        for (int ks = 0; ks < 8; ks++) {
            uint32_t paddr = sb + SM_PH + (16*wid + (lane & 15))*272 + ks*32 + ((lane >> 4) << 4);
            uint32_t ah[4], al[4];
            ldm4(paddr, ah);
            ldm4(paddr + (SM_PL - SM_PH), al);
            #pragma unroll
            for (int nb2 = 0; nb2 < 4; nb2++) {
                uint32_t vaddr = sb + SM_VH + (nb2*16 + (lane & 7) + ((lane >> 4) << 3))*272
                               + ks*32 + (((lane >> 3) & 1) << 4);
                uint32_t bhf[4], blf[4];
                ldm4(vaddr, bhf);
                ldm4(vaddr + (SM_VL - SM_VH), blf);
                mma16816(z + (2*nb2)*4,   ah, bhf[0], bhf[1]);
                mma16816(z + (2*nb2+1)*4, ah, bhf[2], bhf[3]);
                mma16816(z + (2*nb2)*4,   al, bhf[0], bhf[1]);
                mma16816(z + (2*nb2+1)*4, al, bhf[2], bhf[3]);
                mma16816(z + (2*nb2)*4,   ah, blf[0], blf[1]);
                mma16816(z + (2*nb2+1)*4, ah, blf[2], blf[3]);
            }
        }
    }

    // rowsum reduce within quad (t = lane&3)
    #pragma unroll
    for (int o = 1; o <= 2; o <<= 1) {
        rs0 += __shfl_xor_sync(0xffffffffu, rs0, o);
        rs1 += __shfl_xor_sync(0xffffffffu, rs1, o);
    }
    float inv0 = 1.f/rs0, inv1 = 1.f/rs1;
    __nv_bfloat16* zh0 = g_Zh + ((size_t)b*Sc + q0 + row0)*Dc + h*64;
    __nv_bfloat16* zl0 = g_Zl + ((size_t)b*Sc + q0 + row0)*Dc + h*64;
    #pragma unroll
    for (int nb = 0; nb < 8; nb++) {
        int col = nb*8 + 2*t;
        float f0 = z[nb*4+0]*inv0, f1 = z[nb*4+1]*inv0;
        float f2 = z[nb*4+2]*inv1, f3 = z[nb*4+3]*inv1;
        __nv_bfloat16 h0,l0,h1,l1,h2,l2,h3,l3;
        split_bf(f0,h0,l0); split_bf(f1,h1,l1); split_bf(f2,h2,l2); split_bf(f3,h3,l3);
        *(uint32_t*)(zh0 + col)          = pack_bf2(h0,h1);
        *(uint32_t*)(zh0 + 8*Dc + col)   = pack_bf2(h2,h3);
        *(uint32_t*)(zl0 + col)          = pack_bf2(l0,l1);
        *(uint32_t*)(zl0 + 8*Dc + col)   = pack_bf2(l2,l3);
    }
    if (t == 0) {
        g_isum[bh*Sc + q0 + row0]     = inv0;
        g_isum[bh*Sc + q0 + row0 + 8] = inv1;
    }
}

// ---------------- attn_mean: am[b,q,k] = (1/H) sum_h g_S[b,h,q,k]*isum[b,h,q] ----------------
__global__ __launch_bounds__(256) void attn_mean_kernel(float* __restrict__ am)
{
    int q = blockIdx.x, b = blockIdx.y, t = threadIdx.x;
    float4 a0 = make_float4(0,0,0,0), a1 = make_float4(0,0,0,0);
    #pragma unroll 1
    for (int h = 0; h < Hc; h++) {
        float w = g_isum[((size_t)b*Hc + h)*Sc + q];
        const float4* row = (const float4*)(g_S + (((size_t)b*Hc + h)*Sc + q)*Sc);
        float4 v0 = row[t], v1 = row[t + 256];
        a0.x += v0.x*w; a0.y += v0.y*w; a0.z += v0.z*w; a0.w += v0.w*w;
        a1.x += v1.x*w; a1.y += v1.y*w; a1.z += v1.z*w; a1.w += v1.w*w;
    }
    const float invH = 1.0f/Hc;
    float4* dst = (float4*)(am + ((size_t)b*Sc + q)*Sc);
    dst[t]       = make_float4(a0.x*invH, a0.y*invH, a0.z*invH, a0.w*invH);
    dst[t + 256] = make_float4(a1.x*invH, a1.y*invH, a1.z*invH, a1.w*invH);
}

// ---------------- Output projection (warp HMMA, hi/lo bf16) ----------------
// grid (Dc/128, B*S/128), 256 threads. Block tile 128(s) x 128(n), K=1024 in 16 chunks.
#define SM_ZH 0
#define SM_ZL 18432
#define SM_WH 36864
#define SM_WL 55296
#define SMEM_OP 73728

__device__ __forceinline__ void stage_op(char* smem, int off, const float4* gs,
                                         int base_row, int kc, int tid) {
    #pragma unroll
    for (int it = 0; it < 4; it++) {
        int i = tid + it*256;
        int r = i >> 3, c = i & 7;
        *(float4*)(smem + off + r*144 + c*16) = gs[(size_t)(base_row + r)*128 + kc*8 + c];
    }
}

__global__ __launch_bounds__(256,1) void out_proj_mma(
    const float* __restrict__ bz, float* __restrict__ out)
{
    extern __shared__ char smem[];
    uint32_t sb = (uint32_t)__cvta_generic_to_shared(smem);
    int tid = threadIdx.x, wid = tid >> 5, lane = tid & 31;
    int n0 = blockIdx.x*128, s0 = blockIdx.y*128;
    int g = lane >> 2, t = lane & 3;
    int row0 = 16*wid + g;

    const float4* gzh = (const float4*)g_Zh;
    const float4* gzl = (const float4*)g_Zl;
    const float4* gwh = (const float4*)g_Wzh;
    const float4* gwl = (const float4*)g_Wzl;

    float s[64];
    #pragma unroll
    for (int i = 0; i < 64; i++) s[i] = 0.f;

    for (int kc = 0; kc < 16; kc++) {
        if (kc) __syncthreads();
        stage_op(smem, SM_ZH, gzh, s0, kc, tid);
        stage_op(smem, SM_ZL, gzl, s0, kc, tid);
        stage_op(smem, SM_WH, gwh, n0, kc, tid);
        stage_op(smem, SM_WL, gwl, n0, kc, tid);
        __syncthreads();

        #pragma unroll
        for (int ks = 0; ks < 4; ks++) {
            uint32_t aaddr = sb + SM_ZH + (16*wid + (lane & 15))*144 + ks*32 + ((lane >> 4) << 4);
            uint32_t ah[4], al[4];
            ldm4(aaddr, ah);
            ldm4(aaddr + (SM_ZL - SM_ZH), al);
            #pragma unroll
            for (int nb2 = 0; nb2 < 8; nb2++) {
                uint32_t baddr = sb + SM_WH + (nb2*16 + (lane & 7) + ((lane >> 4) << 3))*144
                               + ks*32 + (((lane >> 3) & 1) << 4);
                uint32_t bhf[4], blf[4];
                ldm4(baddr, bhf);
                ldm4(baddr + (SM_WL - SM_WH), blf);
                mma16816(s + (2*nb2)*4,   ah, bhf[0], bhf[1]);
                mma16816(s + (2*nb2+1)*4, ah, bhf[2], bhf[3]);
                mma16816(s + (2*nb2)*4,   al, bhf[0], bhf[1]);
                mma16816(s + (2*nb2+1)*4, al, bhf[2], bhf[3]);
                mma16816(s + (2*nb2)*4,   ah, blf[0], blf[1]);
                mma16816(s + (2*nb2+1)*4, ah, blf[2], blf[3]);
            }
        }
    }

    float* o0 = out + (size_t)(s0 + row0)*Dc + n0;
    float* o1 = o0 + (size_t)8*Dc;
    #pragma unroll
    for (int nb = 0; nb < 16; nb++) {
        int col = nb*8 + 2*t;
        float b0 = bz[n0 + col], b1 = bz[n0 + col + 1];
        *(float2*)(o0 + col) = make_float2(s[nb*4+0] + b0, s[nb*4+1] + b1);
        *(float2*)(o1 + col) = make_float2(s[nb*4+2] + b0, s[nb*4+3] + b1);
    }
}

extern "C" void kernel_launch(void* const* d_in, const int* in_sizes, int n_in,
                              void* d_out, int out_size)
{
    const float* Xq = (const float*)d_in[0];
    const float* Xk = (const float*)d_in[1];
    const float* Xv = (const float*)d_in[2];
    const float* Wq = (const float*)d_in[3];
    const float* Wk = (const float*)d_in[4];
    const float* Wv = (const float*)d_in[5];
    const float* Wz = (const float*)d_in[6];
    const float* bz = (const float*)d_in[7];
    float* out  = (float*)d_out;
    float* attn = out + (size_t)Bc*Sc*Dc;   // out first, then attn_mean

    cudaFuncSetAttribute((const void*)flash_attn,
                         cudaFuncAttributeMaxDynamicSharedMemorySize, SMEM_FL);
    cudaFuncSetAttribute((const void*)out_proj_mma,
                         cudaFuncAttributeMaxDynamicSharedMemorySize, SMEM_OP);

    qkv_proj<<<dim3(Sc/64, Hc, Bc), 256>>>(Xq, Xk, Xv, Wq, Wk, Wv);
    wz_convert<<<Dc*Dc/1024, 256>>>(Wz);
    flash_attn<<<dim3(Sc/128, Hc, Bc), 256, SMEM_FL>>>();
    attn_mean_kernel<<<dim3(Sc, Bc), 256>>>(attn);
    out_proj_mma<<<dim3(Dc/128, (Bc*Sc)/128), 256, SMEM_OP>>>(bz, out);
}

// round 5
// speedup vs baseline: 4.6917x; 1.1945x over previous
#include <cuda_runtime.h>
#include <cuda_bf16.h>
#include <cuda_fp16.h>
#include <cstdint>

#define Bc 2
#define Sc 2048
#define Dc 1024
#define Hc 16
#define HDc 64

// ---------------- scratch globals (allocation-free) ----------------
__device__ __nv_bfloat16 g_Qh[Bc*Hc*Sc*HDc];
__device__ __nv_bfloat16 g_Ql[Bc*Hc*Sc*HDc];
__device__ __nv_bfloat16 g_Kh[Bc*Hc*Sc*HDc];
__device__ __nv_bfloat16 g_Kl[Bc*Hc*Sc*HDc];
__device__ __nv_bfloat16 g_Vth[Bc*Hc*Sc*HDc];   // [b,h,e,s] transposed
__device__ __nv_bfloat16 g_Vtl[Bc*Hc*Sc*HDc];
__device__ __nv_bfloat16 g_Zh[Bc*Sc*Dc];        // Z bf16 hi/lo ([s][k], k contiguous)
__device__ __nv_bfloat16 g_Zl[Bc*Sc*Dc];
__device__ __nv_bfloat16 g_Wzh[Dc*Dc];          // Wz bf16 hi/lo ([n][k], k contiguous)
__device__ __nv_bfloat16 g_Wzl[Dc*Dc];
__device__ __half g_S[134217728];                // [b,h,q,k] unnormalized exp(score), fp16
__device__ float g_isum[Bc*Hc*Sc];               // 1/rowsum

// ---------------- warp MMA helpers (base ISA: valid on sm_103 plain) ----------------
__device__ __forceinline__ void ldm4(uint32_t addr, uint32_t* r) {
    asm volatile("ldmatrix.sync.aligned.m8n8.x4.shared.b16 {%0,%1,%2,%3}, [%4];"
                 : "=r"(r[0]), "=r"(r[1]), "=r"(r[2]), "=r"(r[3]) : "r"(addr));
}
__device__ __forceinline__ void mma16816(float* c, const uint32_t* a, uint32_t b0, uint32_t b1) {
    asm volatile("mma.sync.aligned.m16n8k16.row.col.f32.bf16.bf16.f32 "
                 "{%0,%1,%2,%3}, {%4,%5,%6,%7}, {%8,%9}, {%0,%1,%2,%3};"
                 : "+f"(c[0]), "+f"(c[1]), "+f"(c[2]), "+f"(c[3])
                 : "r"(a[0]), "r"(a[1]), "r"(a[2]), "r"(a[3]), "r"(b0), "r"(b1));
}
__device__ __forceinline__ uint32_t pack_bf2(__nv_bfloat16 a, __nv_bfloat16 b) {
    return (uint32_t)__bfloat16_as_ushort(a) | ((uint32_t)__bfloat16_as_ushort(b) << 16);
}
__device__ __forceinline__ void split_bf(float x, __nv_bfloat16& hi, __nv_bfloat16& lo) {
    hi = __float2bfloat16(x);
    lo = __float2bfloat16(x - __bfloat162float(hi));
}
__device__ __forceinline__ void cpasync16(uint32_t daddr, const void* gptr) {
    asm volatile("cp.async.cg.shared.global [%0], [%1], 16;" :: "r"(daddr), "l"(gptr));
}
#define CP_COMMIT() asm volatile("cp.async.commit_group;" ::: "memory")
#define CP_WAIT1()  asm volatile("cp.async.wait_group 1;" ::: "memory")
#define CP_WAIT0()  asm volatile("cp.async.wait_group 0;" ::: "memory")

// ---------------- QKV projection (writes bf16 hi/lo; V transposed via smem) ----
__global__ __launch_bounds__(256) void qkv_proj(
    const float* __restrict__ Xq, const float* __restrict__ Xk, const float* __restrict__ Xv,
    const float* __restrict__ Wq, const float* __restrict__ Wk, const float* __restrict__ Wv)
{
    __shared__ float Xs[64*65];
    __shared__ float Ws[64*65];
    int s0 = blockIdx.x*64, h = blockIdx.y, b = blockIdx.z;
    int tid = threadIdx.x;
    const float inv4 = 0.35355339059327373f; // HD^-0.25
    const float l2e  = 1.4426950408889634f;
    const float* Xin[3] = {Xq, Xk, Xv};
    const float* Win[3] = {Wq, Wk, Wv};
    int m  = tid & 15;   // e = m + 16*i
    int s4 = tid >> 4;   // s = s4 + 16*j

    for (int t = 0; t < 3; t++) {
        const float* W = Win[t] + h*64*64;
        const float* X = Xin[t] + ((size_t)b*Sc + s0)*Dc + h*64;
        for (int i = tid; i < 4096; i += 256) { int e=i>>6, d=i&63; Ws[e*65+d]=W[i]; }
        for (int i = tid; i < 4096; i += 256) { int r=i>>6, d=i&63; Xs[r*65+d]=X[(size_t)r*Dc+d]; }
        __syncthreads();
        float acc[4][4] = {};
        #pragma unroll 8
        for (int d = 0; d < 64; d++) {
            float wv[4], xv[4];
            #pragma unroll
            for (int i = 0; i < 4; i++) wv[i] = Ws[(m+16*i)*65 + d];
            #pragma unroll
            for (int j = 0; j < 4; j++) xv[j] = Xs[(s4+16*j)*65 + d];
            #pragma unroll
            for (int j = 0; j < 4; j++)
                #pragma unroll
                for (int i = 0; i < 4; i++)
                    acc[j][i] += xv[j]*wv[i];
        }
        if (t < 2) {
            float scl = (t == 0) ? inv4*l2e : inv4;
            __nv_bfloat16* Oh = (t==0 ? g_Qh : g_Kh) + (((size_t)b*Hc + h)*Sc + s0)*64;
            __nv_bfloat16* Ol = (t==0 ? g_Ql : g_Kl) + (((size_t)b*Hc + h)*Sc + s0)*64;
            #pragma unroll
            for (int j = 0; j < 4; j++)
                #pragma unroll
                for (int i = 0; i < 4; i++) {
                    float x = acc[j][i]*scl;
                    __nv_bfloat16 hi, lo; split_bf(x, hi, lo);
                    size_t idx = (size_t)(s4+16*j)*64 + (m+16*i);
                    Oh[idx] = hi; Ol[idx] = lo;
                }
        } else {
            // transpose through smem for coalesced V^T stores
            __syncthreads();   // compute reads of Xs/Ws done in all warps
            __nv_bfloat16* Vhs = (__nv_bfloat16*)Xs;   // [64][66]
            __nv_bfloat16* Vls = (__nv_bfloat16*)Ws;
            #pragma unroll
            for (int j = 0; j < 4; j++)
                #pragma unroll
                for (int i = 0; i < 4; i++) {
                    float x = acc[j][i];
                    __nv_bfloat16 hi, lo; split_bf(x, hi, lo);
                    int e = m + 16*i, s = s4 + 16*j;
                    Vhs[e*66 + s] = hi;
                    Vls[e*66 + s] = lo;
                }
            __syncthreads();
            __nv_bfloat16* Oh = g_Vth + ((size_t)b*Hc + h)*64*Sc;
            __nv_bfloat16* Ol = g_Vtl + ((size_t)b*Hc + h)*64*Sc;
            #pragma unroll
            for (int it = 0; it < 8; it++) {
                int i2 = tid + it*256;
                int e = i2 >> 5, s2 = i2 & 31;
                uint32_t vh = *(uint32_t*)&Vhs[e*66 + 2*s2];
                uint32_t vl = *(uint32_t*)&Vls[e*66 + 2*s2];
                *(uint32_t*)(Oh + (size_t)e*Sc + s0 + 2*s2) = vh;
                *(uint32_t*)(Ol + (size_t)e*Sc + s0 + 2*s2) = vl;
            }
        }
        __syncthreads();
    }
}

// ---------------- Wz -> bf16 hi/lo ----------------
__global__ __launch_bounds__(256) void wz_convert(const float* __restrict__ Wz)
{
    int i = (blockIdx.x*256 + threadIdx.x)*4;
    float4 v = *(const float4*)(Wz + i);
    __nv_bfloat16 h0,l0,h1,l1,h2,l2,h3,l3;
    split_bf(v.x,h0,l0); split_bf(v.y,h1,l1); split_bf(v.z,h2,l2); split_bf(v.w,h3,l3);
    *(uint32_t*)(g_Wzh + i)     = pack_bf2(h0,h1);
    *(uint32_t*)(g_Wzh + i + 2) = pack_bf2(h2,h3);
    *(uint32_t*)(g_Wzl + i)     = pack_bf2(l0,l1);
    *(uint32_t*)(g_Wzl + i + 2) = pack_bf2(l2,l3);
}

// ---------------- flash attention (warp HMMA, cp.async double-buffered) ----------------
// grid (S/128, H, B), 256 threads (8 warps x 16 q-rows), 208KB dyn smem.
// P hi/lo at 0 / 34816; two KV buffers at 69632 / 141312.
// Buffer layout: KH +0 (18432), KL +18432, VH +36864 (17408), VL +54272. size 71680.
#define SM_PH   0
#define SM_PL   34816
#define SM_BUF0 69632
#define BUF_SZ  71680
#define SMEM_FL 212992

__device__ __forceinline__ void stage_k_async(uint32_t dst, const float4* gsrc, int tid) {
    #pragma unroll
    for (int it = 0; it < 4; it++) {
        int i = tid + it*256;
        int r = i >> 3, c = i & 7;
        cpasync16(dst + r*144 + c*16, gsrc + i);
    }
}
__device__ __forceinline__ void stage_v_async(uint32_t dst, const float4* gv, int kb, int tid) {
    #pragma unroll
    for (int it = 0; it < 4; it++) {
        int i = tid + it*256;
        int e = i >> 4, c = i & 15;
        cpasync16(dst + e*272 + c*16, gv + e*256 + kb*16 + c);
    }
}
__device__ __forceinline__ void issue_tile(uint32_t buf, size_t bh, int kb,
                                           const float4* gvh, const float4* gvl, int tid) {
    const float4* kh = (const float4*)g_Kh + ((bh*Sc + (size_t)kb*128) << 3);
    const float4* kl = (const float4*)g_Kl + ((bh*Sc + (size_t)kb*128) << 3);
    stage_k_async(buf,         kh, tid);
    stage_k_async(buf + 18432, kl, tid);
    stage_v_async(buf + 36864, gvh, kb, tid);
    stage_v_async(buf + 54272, gvl, kb, tid);
    CP_COMMIT();
}

__global__ __launch_bounds__(256,1) void flash_attn()
{
    extern __shared__ char smem[];
    uint32_t sb = (uint32_t)__cvta_generic_to_shared(smem);
    int tid = threadIdx.x, wid = tid >> 5, lane = tid & 31;
    int q0 = blockIdx.x*128, h = blockIdx.y, b = blockIdx.z;
    size_t bh = (size_t)b*Hc + h;
    int t = lane & 3;
    int row0 = 16*wid + (lane >> 2);   // first q row (second is row0+8)

    const float4* gvh = (const float4*)(g_Vth + bh*(size_t)64*Sc);
    const float4* gvl = (const float4*)(g_Vtl + bh*(size_t)64*Sc);

    // --- prologue: Q into buffer0 K regions, load fragments, then start pipeline ---
    stage_k_async(sb + SM_BUF0,         (const float4*)g_Qh + ((bh*Sc + q0) << 3), tid);
    stage_k_async(sb + SM_BUF0 + 18432, (const float4*)g_Ql + ((bh*Sc + q0) << 3), tid);
    CP_COMMIT(); CP_WAIT0();
    __syncthreads();

    uint32_t qh[4][4], ql[4][4];
    #pragma unroll
    for (int ks = 0; ks < 4; ks++) {
        uint32_t aaddr = sb + SM_BUF0 + (16*wid + (lane & 15))*144 + ks*32 + ((lane >> 4) << 4);
        ldm4(aaddr, qh[ks]);
        ldm4(aaddr + 18432, ql[ks]);
    }
    __syncthreads();   // Q reads done before buffer0 overwrite

    issue_tile(sb + SM_BUF0,          bh, 0, gvh, gvl, tid);
    issue_tile(sb + SM_BUF0 + BUF_SZ, bh, 1, gvh, gvl, tid);

    float z[32];
    #pragma unroll
    for (int i = 0; i < 32; i++) z[i] = 0.f;
    float rs0 = 0.f, rs1 = 0.f;
    __half* gS0 = g_S + (bh*Sc + q0 + row0)*Sc;
    __half* gS1 = gS0 + (size_t)8*Sc;

    for (int kb = 0; kb < Sc/128; kb++) {
        if (kb < 15) { CP_WAIT1(); } else { CP_WAIT0(); }
        __syncthreads();
        uint32_t buf = sb + SM_BUF0 + (kb & 1)*BUF_SZ;

        // ---- scores: S = Qh*Kh + Ql*Kh + Qh*Kl  (128x128, contraction 64) ----
        float s[64];
        #pragma unroll
        for (int i = 0; i < 64; i++) s[i] = 0.f;
        #pragma unroll
        for (int ks = 0; ks < 4; ks++) {
            #pragma unroll
            for (int nb2 = 0; nb2 < 8; nb2++) {
                uint32_t baddr = buf + (nb2*16 + (lane & 7) + ((lane >> 4) << 3))*144
                               + ks*32 + (((lane >> 3) & 1) << 4);
                uint32_t bhf[4], blf[4];
                ldm4(baddr, bhf);
                ldm4(baddr + 18432, blf);
                mma16816(s + (2*nb2)*4,   qh[ks], bhf[0], bhf[1]);
                mma16816(s + (2*nb2+1)*4, qh[ks], bhf[2], bhf[3]);
                mma16816(s + (2*nb2)*4,   ql[ks], bhf[0], bhf[1]);
                mma16816(s + (2*nb2+1)*4, ql[ks], bhf[2], bhf[3]);
                mma16816(s + (2*nb2)*4,   qh[ks], blf[0], blf[1]);
                mma16816(s + (2*nb2+1)*4, qh[ks], blf[2], blf[3]);
            }
        }

        // ---- epilogue: exp2, rowsum, g_S (fp16) store, P hi/lo -> smem ----
        #pragma unroll
        for (int nb = 0; nb < 16; nb++) {
            float e0 = exp2f(s[nb*4+0]);
            float e1 = exp2f(s[nb*4+1]);
            float e2 = exp2f(s[nb*4+2]);
            float e3 = exp2f(s[nb*4+3]);
            rs0 += e0 + e1; rs1 += e2 + e3;
            int col = kb*128 + nb*8 + 2*t;
            *(__half2*)(gS0 + col) = __floats2half2_rn(e0, e1);
            *(__half2*)(gS1 + col) = __floats2half2_rn(e2, e3);
            __nv_bfloat16 h0,l0,h1,l1,h2,l2,h3,l3;
            split_bf(e0,h0,l0); split_bf(e1,h1,l1); split_bf(e2,h2,l2); split_bf(e3,h3,l3);
            int pc = (nb*8 + 2*t)*2;   // byte col
            char* p0 = smem + SM_PH + row0*272 + pc;
            char* p1 = p0 + 8*272;
            *(uint32_t*)p0 = pack_bf2(h0, h1);
            *(uint32_t*)p1 = pack_bf2(h2, h3);
            *(uint32_t*)(p0 + (SM_PL - SM_PH)) = pack_bf2(l0, l1);
            *(uint32_t*)(p1 + (SM_PL - SM_PH)) = pack_bf2(l2, l3);
        }
        __syncwarp();   // P rows are warp-local

        // ---- Z += Ph*Vh + Pl*Vh + Ph*Vl  (128x64, contraction 128) ----
        #pragma unroll
        for (int ks = 0; ks < 8; ks++) {
            uint32_t paddr = sb + SM_PH + (16*wid + (lane & 15))*272 + ks*32 + ((lane >> 4) << 4);
            uint32_t ah[4], al[4];
            ldm4(paddr, ah);
            ldm4(paddr + (SM_PL - SM_PH), al);
            #pragma unroll
            for (int nb2 = 0; nb2 < 4; nb2++) {
                uint32_t vaddr = buf + 36864 + (nb2*16 + (lane & 7) + ((lane >> 4) << 3))*272
                               + ks*32 + (((lane >> 3) & 1) << 4);
                uint32_t bhf[4], blf[4];
                ldm4(vaddr, bhf);
                ldm4(vaddr + 17408, blf);
                mma16816(z + (2*nb2)*4,   ah, bhf[0], bhf[1]);
                mma16816(z + (2*nb2+1)*4, ah, bhf[2], bhf[3]);
                mma16816(z + (2*nb2)*4,   al, bhf[0], bhf[1]);
                mma16816(z + (2*nb2+1)*4, al, bhf[2], bhf[3]);
                mma16816(z + (2*nb2)*4,   ah, blf[0], blf[1]);
                mma16816(z + (2*nb2+1)*4, ah, blf[2], blf[3]);
            }
        }
        __syncthreads();   // all warps done with this buffer
        if (kb + 2 < 16)
            issue_tile(sb + SM_BUF0 + (kb & 1)*BUF_SZ, bh, kb + 2, gvh, gvl, tid);
    }

    // rowsum reduce within quad
    #pragma unroll
    for (int o = 1; o <= 2; o <<= 1) {
        rs0 += __shfl_xor_sync(0xffffffffu, rs0, o);
        rs1 += __shfl_xor_sync(0xffffffffu, rs1, o);
    }
    float inv0 = 1.f/rs0, inv1 = 1.f/rs1;
    __nv_bfloat16* zh0 = g_Zh + ((size_t)b*Sc + q0 + row0)*Dc + h*64;
    __nv_bfloat16* zl0 = g_Zl + ((size_t)b*Sc + q0 + row0)*Dc + h*64;
    #pragma unroll
    for (int nb = 0; nb < 8; nb++) {
        int col = nb*8 + 2*t;
        float f0 = z[nb*4+0]*inv0, f1 = z[nb*4+1]*inv0;
        float f2 = z[nb*4+2]*inv1, f3 = z[nb*4+3]*inv1;
        __nv_bfloat16 h0,l0,h1,l1,h2,l2,h3,l3;
        split_bf(f0,h0,l0); split_bf(f1,h1,l1); split_bf(f2,h2,l2); split_bf(f3,h3,l3);
        *(uint32_t*)(zh0 + col)          = pack_bf2(h0,h1);
        *(uint32_t*)(zh0 + 8*Dc + col)   = pack_bf2(h2,h3);
        *(uint32_t*)(zl0 + col)          = pack_bf2(l0,l1);
        *(uint32_t*)(zl0 + 8*Dc + col)   = pack_bf2(l2,l3);
    }
    if (t == 0) {
        g_isum[bh*Sc + q0 + row0]     = inv0;
        g_isum[bh*Sc + q0 + row0 + 8] = inv1;
    }
}

// ---------------- attn_mean: am[b,q,k] = (1/H) sum_h g_S[b,h,q,k]*isum[b,h,q] ----------------
__global__ __launch_bounds__(256) void attn_mean_kernel(float* __restrict__ am)
{
    int q = blockIdx.x, b = blockIdx.y, t = threadIdx.x;
    float a[8] = {0.f,0.f,0.f,0.f,0.f,0.f,0.f,0.f};
    #pragma unroll 1
    for (int h = 0; h < Hc; h++) {
        size_t bh = (size_t)b*Hc + h;
        float w = g_isum[bh*Sc + q];
        const float4* row = (const float4*)(g_S + (bh*Sc + q)*Sc);
        float4 v = row[t];
        const __half2* hp = (const __half2*)&v;
        #pragma unroll
        for (int j = 0; j < 4; j++) {
            float2 f = __half22float2(hp[j]);
            a[2*j]   += f.x*w;
            a[2*j+1] += f.y*w;
        }
    }
    const float invH = 1.0f/Hc;
    float4* dst = (float4*)(am + ((size_t)b*Sc + q)*Sc);
    dst[2*t]   = make_float4(a[0]*invH, a[1]*invH, a[2]*invH, a[3]*invH);
    dst[2*t+1] = make_float4(a[4]*invH, a[5]*invH, a[6]*invH, a[7]*invH);
}

// ---------------- Output projection (warp HMMA, hi/lo bf16) ----------------
#define SM_ZH 0
#define SM_ZL 18432
#define SM_WH 36864
#define SM_WL 55296
#define SMEM_OP 73728

__device__ __forceinline__ void stage_op(char* smem, int off, const float4* gs,
                                         int base_row, int kc, int tid) {
    #pragma unroll
    for (int it = 0; it < 4; it++) {
        int i = tid + it*256;
        int r = i >> 3, c = i & 7;
        *(float4*)(smem + off + r*144 + c*16) = gs[(size_t)(base_row + r)*128 + kc*8 + c];
    }
}

__global__ __launch_bounds__(256,1) void out_proj_mma(
    const float* __restrict__ bz, float* __restrict__ out)
{
    extern __shared__ char smem[];
    uint32_t sb = (uint32_t)__cvta_generic_to_shared(smem);
    int tid = threadIdx.x, wid = tid >> 5, lane = tid & 31;
    int n0 = blockIdx.x*128, s0 = blockIdx.y*128;
    int t = lane & 3;
    int row0 = 16*wid + (lane >> 2);

    const float4* gzh = (const float4*)g_Zh;
    const float4* gzl = (const float4*)g_Zl;
    const float4* gwh = (const float4*)g_Wzh;
    const float4* gwl = (const float4*)g_Wzl;

    float s[64];
    #pragma unroll
    for (int i = 0; i < 64; i++) s[i] = 0.f;

    for (int kc = 0; kc < 16; kc++) {
        if (kc) __syncthreads();
        stage_op(smem, SM_ZH, gzh, s0, kc, tid);
        stage_op(smem, SM_ZL, gzl, s0, kc, tid);
        stage_op(smem, SM_WH, gwh, n0, kc, tid);
        stage_op(smem, SM_WL, gwl, n0, kc, tid);
        __syncthreads();

        #pragma unroll
        for (int ks = 0; ks < 4; ks++) {
            uint32_t aaddr = sb + SM_ZH + (16*wid + (lane & 15))*144 + ks*32 + ((lane >> 4) << 4);
            uint32_t ah[4], al[4];
            ldm4(aaddr, ah);
            ldm4(aaddr + (SM_ZL - SM_ZH), al);
            #pragma unroll
            for (int nb2 = 0; nb2 < 8; nb2++) {
                uint32_t baddr = sb + SM_WH + (nb2*16 + (lane & 7) + ((lane >> 4) << 3))*144
                               + ks*32 + (((lane >> 3) & 1) << 4);
                uint32_t bhf[4], blf[4];
                ldm4(baddr, bhf);
                ldm4(baddr + (SM_WL - SM_WH), blf);
                mma16816(s + (2*nb2)*4,   ah, bhf[0], bhf[1]);
                mma16816(s + (2*nb2+1)*4, ah, bhf[2], bhf[3]);
                mma16816(s + (2*nb2)*4,   al, bhf[0], bhf[1]);
                mma16816(s + (2*nb2+1)*4, al, bhf[2], bhf[3]);
                mma16816(s + (2*nb2)*4,   ah, blf[0], blf[1]);
                mma16816(s + (2*nb2+1)*4, ah, blf[2], blf[3]);
            }
        }
    }

    float* o0 = out + (size_t)(s0 + row0)*Dc + n0;
    float* o1 = o0 + (size_t)8*Dc;
    #pragma unroll
    for (int nb = 0; nb < 16; nb++) {
        int col = nb*8 + 2*t;
        float b0 = bz[n0 + col], b1 = bz[n0 + col + 1];
        *(float2*)(o0 + col) = make_float2(s[nb*4+0] + b0, s[nb*4+1] + b1);
        *(float2*)(o1 + col) = make_float2(s[nb*4+2] + b0, s[nb*4+3] + b1);
    }
}

extern "C" void kernel_launch(void* const* d_in, const int* in_sizes, int n_in,
                              void* d_out, int out_size)
{
    const float* Xq = (const float*)d_in[0];
    const float* Xk = (const float*)d_in[1];
    const float* Xv = (const float*)d_in[2];
    const float* Wq = (const float*)d_in[3];
    const float* Wk = (const float*)d_in[4];
    const float* Wv = (const float*)d_in[5];
    const float* Wz = (const float*)d_in[6];
    const float* bz = (const float*)d_in[7];
    float* out  = (float*)d_out;
    float* attn = out + (size_t)Bc*Sc*Dc;   // out first, then attn_mean

    cudaFuncSetAttribute((const void*)flash_attn,
                         cudaFuncAttributeMaxDynamicSharedMemorySize, SMEM_FL);
    cudaFuncSetAttribute((const void*)out_proj_mma,
                         cudaFuncAttributeMaxDynamicSharedMemorySize, SMEM_OP);

    qkv_proj<<<dim3(Sc/64, Hc, Bc), 256>>>(Xq, Xk, Xv, Wq, Wk, Wv);
    wz_convert<<<Dc*Dc/1024, 256>>>(Wz);
    flash_attn<<<dim3(Sc/128, Hc, Bc), 256, SMEM_FL>>>();
    attn_mean_kernel<<<dim3(Sc, Bc), 256>>>(attn);
    out_proj_mma<<<dim3(Dc/128, (Bc*Sc)/128), 256, SMEM_OP>>>(bz, out);
}

// round 6
// speedup vs baseline: 5.0601x; 1.0785x over previous
#include <cuda_runtime.h>
#include <cuda_bf16.h>
#include <cuda_fp16.h>
#include <cstdint>

#define Bc 2
#define Sc 2048
#define Dc 1024
#define Hc 16
#define HDc 64

// ---------------- scratch globals (allocation-free) ----------------
__device__ __nv_bfloat16 g_Qh[Bc*Hc*Sc*HDc];
__device__ __nv_bfloat16 g_Ql[Bc*Hc*Sc*HDc];
__device__ __nv_bfloat16 g_Kh[Bc*Hc*Sc*HDc];
__device__ __nv_bfloat16 g_Kl[Bc*Hc*Sc*HDc];
__device__ __nv_bfloat16 g_Vth[Bc*Hc*Sc*HDc];   // [b,h,e,s] transposed
__device__ __nv_bfloat16 g_Vtl[Bc*Hc*Sc*HDc];
__device__ __nv_bfloat16 g_Zh[Bc*Sc*Dc];        // Z bf16 hi/lo ([s][k], k contiguous)
__device__ __nv_bfloat16 g_Zl[Bc*Sc*Dc];
__device__ __nv_bfloat16 g_Wzh[Dc*Dc];          // Wz bf16 hi/lo ([n][k], k contiguous)
__device__ __nv_bfloat16 g_Wzl[Dc*Dc];
__device__ __half g_S[134217728];                // [b,h,q,k] unnormalized exp(score), fp16
__device__ float g_isum[Bc*Hc*Sc];               // 1/rowsum

// ---------------- warp MMA helpers (base ISA: valid on sm_103 plain) ----------------
__device__ __forceinline__ void ldm4(uint32_t addr, uint32_t* r) {
    asm volatile("ldmatrix.sync.aligned.m8n8.x4.shared.b16 {%0,%1,%2,%3}, [%4];"
                 : "=r"(r[0]), "=r"(r[1]), "=r"(r[2]), "=r"(r[3]) : "r"(addr));
}
__device__ __forceinline__ void mma16816(float* c, const uint32_t* a, uint32_t b0, uint32_t b1) {
    asm volatile("mma.sync.aligned.m16n8k16.row.col.f32.bf16.bf16.f32 "
                 "{%0,%1,%2,%3}, {%4,%5,%6,%7}, {%8,%9}, {%0,%1,%2,%3};"
                 : "+f"(c[0]), "+f"(c[1]), "+f"(c[2]), "+f"(c[3])
                 : "r"(a[0]), "r"(a[1]), "r"(a[2]), "r"(a[3]), "r"(b0), "r"(b1));
}
__device__ __forceinline__ uint32_t pack_bf2(__nv_bfloat16 a, __nv_bfloat16 b) {
    return (uint32_t)__bfloat16_as_ushort(a) | ((uint32_t)__bfloat16_as_ushort(b) << 16);
}
__device__ __forceinline__ void split_bf(float x, __nv_bfloat16& hi, __nv_bfloat16& lo) {
    hi = __float2bfloat16(x);
    lo = __float2bfloat16(x - __bfloat162float(hi));
}
__device__ __forceinline__ void cpasync16(uint32_t daddr, const void* gptr) {
    asm volatile("cp.async.cg.shared.global [%0], [%1], 16;" :: "r"(daddr), "l"(gptr));
}
#define CP_COMMIT() asm volatile("cp.async.commit_group;" ::: "memory")
#define CP_WAIT1()  asm volatile("cp.async.wait_group 1;" ::: "memory")
#define CP_WAIT0()  asm volatile("cp.async.wait_group 0;" ::: "memory")

// ---------------- QKV projection (writes bf16 hi/lo; V transposed via smem) ----
__global__ __launch_bounds__(256) void qkv_proj(
    const float* __restrict__ Xq, const float* __restrict__ Xk, const float* __restrict__ Xv,
    const float* __restrict__ Wq, const float* __restrict__ Wk, const float* __restrict__ Wv)
{
    __shared__ float Xs[64*65];
    __shared__ float Ws[64*65];
    int s0 = blockIdx.x*64, h = blockIdx.y, b = blockIdx.z;
    int tid = threadIdx.x;
    const float inv4 = 0.35355339059327373f; // HD^-0.25
    const float l2e  = 1.4426950408889634f;
    const float* Xin[3] = {Xq, Xk, Xv};
    const float* Win[3] = {Wq, Wk, Wv};
    int m  = tid & 15;   // e = m + 16*i
    int s4 = tid >> 4;   // s = s4 + 16*j

    for (int t = 0; t < 3; t++) {
        const float* W = Win[t] + h*64*64;
        const float* X = Xin[t] + ((size_t)b*Sc + s0)*Dc + h*64;
        for (int i = tid; i < 4096; i += 256) { int e=i>>6, d=i&63; Ws[e*65+d]=W[i]; }
        for (int i = tid; i < 4096; i += 256) { int r=i>>6, d=i&63; Xs[r*65+d]=X[(size_t)r*Dc+d]; }
        __syncthreads();
        float acc[4][4] = {};
        #pragma unroll 8
        for (int d = 0; d < 64; d++) {
            float wv[4], xv[4];
            #pragma unroll
            for (int i = 0; i < 4; i++) wv[i] = Ws[(m+16*i)*65 + d];
            #pragma unroll
            for (int j = 0; j < 4; j++) xv[j] = Xs[(s4+16*j)*65 + d];
            #pragma unroll
            for (int j = 0; j < 4; j++)
                #pragma unroll
                for (int i = 0; i < 4; i++)
                    acc[j][i] += xv[j]*wv[i];
        }
        if (t < 2) {
            float scl = (t == 0) ? inv4*l2e : inv4;
            __nv_bfloat16* Oh = (t==0 ? g_Qh : g_Kh) + (((size_t)b*Hc + h)*Sc + s0)*64;
            __nv_bfloat16* Ol = (t==0 ? g_Ql : g_Kl) + (((size_t)b*Hc + h)*Sc + s0)*64;
            #pragma unroll
            for (int j = 0; j < 4; j++)
                #pragma unroll
                for (int i = 0; i < 4; i++) {
                    float x = acc[j][i]*scl;
                    __nv_bfloat16 hi, lo; split_bf(x, hi, lo);
                    size_t idx = (size_t)(s4+16*j)*64 + (m+16*i);
                    Oh[idx] = hi; Ol[idx] = lo;
                }
        } else {
            // transpose through smem for coalesced V^T stores
            __syncthreads();
            __nv_bfloat16* Vhs = (__nv_bfloat16*)Xs;   // [64][66]
            __nv_bfloat16* Vls = (__nv_bfloat16*)Ws;
            #pragma unroll
            for (int j = 0; j < 4; j++)
                #pragma unroll
                for (int i = 0; i < 4; i++) {
                    float x = acc[j][i];
                    __nv_bfloat16 hi, lo; split_bf(x, hi, lo);
                    int e = m + 16*i, s = s4 + 16*j;
                    Vhs[e*66 + s] = hi;
                    Vls[e*66 + s] = lo;
                }
            __syncthreads();
            __nv_bfloat16* Oh = g_Vth + ((size_t)b*Hc + h)*64*Sc;
            __nv_bfloat16* Ol = g_Vtl + ((size_t)b*Hc + h)*64*Sc;
            #pragma unroll
            for (int it = 0; it < 8; it++) {
                int i2 = tid + it*256;
                int e = i2 >> 5, s2 = i2 & 31;
                uint32_t vh = *(uint32_t*)&Vhs[e*66 + 2*s2];
                uint32_t vl = *(uint32_t*)&Vls[e*66 + 2*s2];
                *(uint32_t*)(Oh + (size_t)e*Sc + s0 + 2*s2) = vh;
                *(uint32_t*)(Ol + (size_t)e*Sc + s0 + 2*s2) = vl;
            }
        }
        __syncthreads();
    }
}

// ---------------- Wz -> bf16 hi/lo ----------------
__global__ __launch_bounds__(256) void wz_convert(const float* __restrict__ Wz)
{
    int i = (blockIdx.x*256 + threadIdx.x)*4;
    float4 v = *(const float4*)(Wz + i);
    __nv_bfloat16 h0,l0,h1,l1,h2,l2,h3,l3;
    split_bf(v.x,h0,l0); split_bf(v.y,h1,l1); split_bf(v.z,h2,l2); split_bf(v.w,h3,l3);
    *(uint32_t*)(g_Wzh + i)     = pack_bf2(h0,h1);
    *(uint32_t*)(g_Wzh + i + 2) = pack_bf2(h2,h3);
    *(uint32_t*)(g_Wzl + i)     = pack_bf2(l0,l1);
    *(uint32_t*)(g_Wzl + i + 2) = pack_bf2(l2,l3);
}

// ---------------- flash attention (warp HMMA, register-fragment P, cp.async) -----------
// grid (S/128, H, B), 256 threads (8 warps x 16 q-rows), 140KB dyn smem.
// Two KV buffers: KH +0 (18432), KL +18432, VH +36864 (17408), VL +54272. size 71680.
#define BUF_SZ  71680
#define SMEM_FL 143360

__device__ __forceinline__ void stage_k_async(uint32_t dst, const float4* gsrc, int tid) {
    #pragma unroll
    for (int it = 0; it < 4; it++) {
        int i = tid + it*256;
        int r = i >> 3, c = i & 7;
        cpasync16(dst + r*144 + c*16, gsrc + i);
    }
}
__device__ __forceinline__ void stage_v_async(uint32_t dst, const float4* gv, int kb, int tid) {
    #pragma unroll
    for (int it = 0; it < 4; it++) {
        int i = tid + it*256;
        int e = i >> 4, c = i & 15;
        cpasync16(dst + e*272 + c*16, gv + e*256 + kb*16 + c);
    }
}
__device__ __forceinline__ void issue_tile(uint32_t buf, size_t bh, int kb,
                                           const float4* gvh, const float4* gvl, int tid) {
    const float4* kh = (const float4*)g_Kh + ((bh*Sc + (size_t)kb*128) << 3);
    const float4* kl = (const float4*)g_Kl + ((bh*Sc + (size_t)kb*128) << 3);
    stage_k_async(buf,         kh, tid);
    stage_k_async(buf + 18432, kl, tid);
    stage_v_async(buf + 36864, gvh, kb, tid);
    stage_v_async(buf + 54272, gvl, kb, tid);
    CP_COMMIT();
}

__global__ __launch_bounds__(256,1) void flash_attn()
{
    extern __shared__ char smem[];
    uint32_t sb = (uint32_t)__cvta_generic_to_shared(smem);
    int tid = threadIdx.x, wid = tid >> 5, lane = tid & 31;
    int q0 = blockIdx.x*128, h = blockIdx.y, b = blockIdx.z;
    size_t bh = (size_t)b*Hc + h;
    int t = lane & 3;
    int row0 = 16*wid + (lane >> 2);   // first q row (second is row0+8)

    const float4* gvh = (const float4*)(g_Vth + bh*(size_t)64*Sc);
    const float4* gvl = (const float4*)(g_Vtl + bh*(size_t)64*Sc);

    // --- prologue: Q into buffer0 K regions, load fragments, then start pipeline ---
    stage_k_async(sb,         (const float4*)g_Qh + ((bh*Sc + q0) << 3), tid);
    stage_k_async(sb + 18432, (const float4*)g_Ql + ((bh*Sc + q0) << 3), tid);
    CP_COMMIT(); CP_WAIT0();
    __syncthreads();

    uint32_t qh[4][4], ql[4][4];
    #pragma unroll
    for (int ks = 0; ks < 4; ks++) {
        uint32_t aaddr = sb + (16*wid + (lane & 15))*144 + ks*32 + ((lane >> 4) << 4);
        ldm4(aaddr, qh[ks]);
        ldm4(aaddr + 18432, ql[ks]);
    }
    __syncthreads();   // Q reads done before buffer0 overwrite

    issue_tile(sb,          bh, 0, gvh, gvl, tid);
    issue_tile(sb + BUF_SZ, bh, 1, gvh, gvl, tid);

    float z[32];
    #pragma unroll
    for (int i = 0; i < 32; i++) z[i] = 0.f;
    float rs0 = 0.f, rs1 = 0.f;
    __half* gS0 = g_S + (bh*Sc + q0 + row0)*Sc;
    __half* gS1 = gS0 + (size_t)8*Sc;

    for (int kb = 0; kb < Sc/128; kb++) {
        if (kb < 15) { CP_WAIT1(); } else { CP_WAIT0(); }
        __syncthreads();
        uint32_t buf = sb + (kb & 1)*BUF_SZ;

        // ---- scores: S = Qh*Kh + Ql*Kh + Qh*Kl  (128x128, contraction 64) ----
        float s[64];
        #pragma unroll
        for (int i = 0; i < 64; i++) s[i] = 0.f;
        #pragma unroll
        for (int ks = 0; ks < 4; ks++) {
            #pragma unroll
            for (int nb2 = 0; nb2 < 8; nb2++) {
                uint32_t baddr = buf + (nb2*16 + (lane & 7) + ((lane >> 4) << 3))*144
                               + ks*32 + (((lane >> 3) & 1) << 4);
                uint32_t bhf[4], blf[4];
                ldm4(baddr, bhf);
                ldm4(baddr + 18432, blf);
                mma16816(s + (2*nb2)*4,   qh[ks], bhf[0], bhf[1]);
                mma16816(s + (2*nb2+1)*4, qh[ks], bhf[2], bhf[3]);
                mma16816(s + (2*nb2)*4,   ql[ks], bhf[0], bhf[1]);
                mma16816(s + (2*nb2+1)*4, ql[ks], bhf[2], bhf[3]);
                mma16816(s + (2*nb2)*4,   qh[ks], blf[0], blf[1]);
                mma16816(s + (2*nb2+1)*4, qh[ks], blf[2], blf[3]);
            }
        }

        // ---- fused epilogue + PV, per 16-key chunk m ----
        // C-fragment of chunk m (accumulators nb=2m,2m+1) IS the A-fragment of P·V:
        //   a0=(g, k=2t,2t+1), a1=(g+8, same), a2=(g, k=8+2t), a3=(g+8, same)
        #pragma unroll
        for (int m = 0; m < 8; m++) {
            float ea0 = exp2f(s[8*m+0]), ea1 = exp2f(s[8*m+1]);
            float ea2 = exp2f(s[8*m+2]), ea3 = exp2f(s[8*m+3]);
            float eb0 = exp2f(s[8*m+4]), eb1 = exp2f(s[8*m+5]);
            float eb2 = exp2f(s[8*m+6]), eb3 = exp2f(s[8*m+7]);
            rs0 += ea0 + ea1 + eb0 + eb1;
            rs1 += ea2 + ea3 + eb2 + eb3;
            int col = kb*128 + 16*m + 2*t;
            *(__half2*)(gS0 + col)     = __floats2half2_rn(ea0, ea1);
            *(__half2*)(gS0 + col + 8) = __floats2half2_rn(eb0, eb1);
            *(__half2*)(gS1 + col)     = __floats2half2_rn(ea2, ea3);
            *(__half2*)(gS1 + col + 8) = __floats2half2_rn(eb2, eb3);

            __nv_bfloat16 ha0,la0,ha1,la1,ha2,la2,ha3,la3;
            __nv_bfloat16 hb0,lb0,hb1,lb1,hb2,lb2,hb3,lb3;
            split_bf(ea0,ha0,la0); split_bf(ea1,ha1,la1);
            split_bf(ea2,ha2,la2); split_bf(ea3,ha3,la3);
            split_bf(eb0,hb0,lb0); split_bf(eb1,hb1,lb1);
            split_bf(eb2,hb2,lb2); split_bf(eb3,hb3,lb3);
            uint32_t ah[4], al[4];
            ah[0] = pack_bf2(ha0,ha1); ah[1] = pack_bf2(ha2,ha3);
            ah[2] = pack_bf2(hb0,hb1); ah[3] = pack_bf2(hb2,hb3);
            al[0] = pack_bf2(la0,la1); al[1] = pack_bf2(la2,la3);
            al[2] = pack_bf2(lb0,lb1); al[3] = pack_bf2(lb2,lb3);

            #pragma unroll
            for (int nb2 = 0; nb2 < 4; nb2++) {
                uint32_t vaddr = buf + 36864 + (nb2*16 + (lane & 7) + ((lane >> 4) << 3))*272
                               + m*32 + (((lane >> 3) & 1) << 4);
                uint32_t bhf[4], blf[4];
                ldm4(vaddr, bhf);
                ldm4(vaddr + 17408, blf);
                mma16816(z + (2*nb2)*4,   ah, bhf[0], bhf[1]);
                mma16816(z + (2*nb2+1)*4, ah, bhf[2], bhf[3]);
                mma16816(z + (2*nb2)*4,   al, bhf[0], bhf[1]);
                mma16816(z + (2*nb2+1)*4, al, bhf[2], bhf[3]);
                mma16816(z + (2*nb2)*4,   ah, blf[0], blf[1]);
                mma16816(z + (2*nb2+1)*4, ah, blf[2], blf[3]);
            }
        }
        __syncthreads();   // all warps done with this buffer
        if (kb + 2 < 16)
            issue_tile(sb + (kb & 1)*BUF_SZ, bh, kb + 2, gvh, gvl, tid);
    }

    // rowsum reduce within quad
    #pragma unroll
    for (int o = 1; o <= 2; o <<= 1) {
        rs0 += __shfl_xor_sync(0xffffffffu, rs0, o);
        rs1 += __shfl_xor_sync(0xffffffffu, rs1, o);
    }
    float inv0 = 1.f/rs0, inv1 = 1.f/rs1;
    __nv_bfloat16* zh0 = g_Zh + ((size_t)b*Sc + q0 + row0)*Dc + h*64;
    __nv_bfloat16* zl0 = g_Zl + ((size_t)b*Sc + q0 + row0)*Dc + h*64;
    #pragma unroll
    for (int nb = 0; nb < 8; nb++) {
        int col = nb*8 + 2*t;
        float f0 = z[nb*4+0]*inv0, f1 = z[nb*4+1]*inv0;
        float f2 = z[nb*4+2]*inv1, f3 = z[nb*4+3]*inv1;
        __nv_bfloat16 h0,l0,h1,l1,h2,l2,h3,l3;
        split_bf(f0,h0,l0); split_bf(f1,h1,l1); split_bf(f2,h2,l2); split_bf(f3,h3,l3);
        *(uint32_t*)(zh0 + col)          = pack_bf2(h0,h1);
        *(uint32_t*)(zh0 + 8*Dc + col)   = pack_bf2(h2,h3);
        *(uint32_t*)(zl0 + col)          = pack_bf2(l0,l1);
        *(uint32_t*)(zl0 + 8*Dc + col)   = pack_bf2(l2,l3);
    }
    if (t == 0) {
        g_isum[bh*Sc + q0 + row0]     = inv0;
        g_isum[bh*Sc + q0 + row0 + 8] = inv1;
    }
}

// ---------------- attn_mean: am[b,q,k] = (1/H) sum_h g_S[b,h,q,k]*isum[b,h,q] ----------------
__global__ __launch_bounds__(256) void attn_mean_kernel(float* __restrict__ am)
{
    int q = blockIdx.x, b = blockIdx.y, t = threadIdx.x;
    float a[8] = {0.f,0.f,0.f,0.f,0.f,0.f,0.f,0.f};
    #pragma unroll 1
    for (int h = 0; h < Hc; h++) {
        size_t bh = (size_t)b*Hc + h;
        float w = g_isum[bh*Sc + q];
        const float4* row = (const float4*)(g_S + (bh*Sc + q)*Sc);
        float4 v = row[t];
        const __half2* hp = (const __half2*)&v;
        #pragma unroll
        for (int j = 0; j < 4; j++) {
            float2 f = __half22float2(hp[j]);
            a[2*j]   += f.x*w;
            a[2*j+1] += f.y*w;
        }
    }
    const float invH = 1.0f/Hc;
    float4* dst = (float4*)(am + ((size_t)b*Sc + q)*Sc);
    dst[2*t]   = make_float4(a[0]*invH, a[1]*invH, a[2]*invH, a[3]*invH);
    dst[2*t+1] = make_float4(a[4]*invH, a[5]*invH, a[6]*invH, a[7]*invH);
}

// ---------------- Output projection (warp HMMA, hi/lo bf16) ----------------
#define SM_ZH 0
#define SM_ZL 18432
#define SM_WH 36864
#define SM_WL 55296
#define SMEM_OP 73728

__device__ __forceinline__ void stage_op(char* smem, int off, const float4* gs,
                                         int base_row, int kc, int tid) {
    #pragma unroll
    for (int it = 0; it < 4; it++) {
        int i = tid + it*256;
        int r = i >> 3, c = i & 7;
        *(float4*)(smem + off + r*144 + c*16) = gs[(size_t)(base_row + r)*128 + kc*8 + c];
    }
}

__global__ __launch_bounds__(256,1) void out_proj_mma(
    const float* __restrict__ bz, float* __restrict__ out)
{
    extern __shared__ char smem[];
    uint32_t sb = (uint32_t)__cvta_generic_to_shared(smem);
    int tid = threadIdx.x, wid = tid >> 5, lane = tid & 31;
    int n0 = blockIdx.x*128, s0 = blockIdx.y*128;
    int t = lane & 3;
    int row0 = 16*wid + (lane >> 2);

    const float4* gzh = (const float4*)g_Zh;
    const float4* gzl = (const float4*)g_Zl;
    const float4* gwh = (const float4*)g_Wzh;
    const float4* gwl = (const float4*)g_Wzl;

    float s[64];
    #pragma unroll
    for (int i = 0; i < 64; i++) s[i] = 0.f;

    for (int kc = 0; kc < 16; kc++) {
        if (kc) __syncthreads();
        stage_op(smem, SM_ZH, gzh, s0, kc, tid);
        stage_op(smem, SM_ZL, gzl, s0, kc, tid);
        stage_op(smem, SM_WH, gwh, n0, kc, tid);
        stage_op(smem, SM_WL, gwl, n0, kc, tid);
        __syncthreads();

        #pragma unroll
        for (int ks = 0; ks < 4; ks++) {
            uint32_t aaddr = sb + SM_ZH + (16*wid + (lane & 15))*144 + ks*32 + ((lane >> 4) << 4);
            uint32_t ah[4], al[4];
            ldm4(aaddr, ah);
            ldm4(aaddr + (SM_ZL - SM_ZH), al);
            #pragma unroll
            for (int nb2 = 0; nb2 < 8; nb2++) {
                uint32_t baddr = sb + SM_WH + (nb2*16 + (lane & 7) + ((lane >> 4) << 3))*144
                               + ks*32 + (((lane >> 3) & 1) << 4);
                uint32_t bhf[4], blf[4];
                ldm4(baddr, bhf);
                ldm4(baddr + (SM_WL - SM_WH), blf);
                mma16816(s + (2*nb2)*4,   ah, bhf[0], bhf[1]);
                mma16816(s + (2*nb2+1)*4, ah, bhf[2], bhf[3]);
                mma16816(s + (2*nb2)*4,   al, bhf[0], bhf[1]);
                mma16816(s + (2*nb2+1)*4, al, bhf[2], bhf[3]);
                mma16816(s + (2*nb2)*4,   ah, blf[0], blf[1]);
                mma16816(s + (2*nb2+1)*4, ah, blf[2], blf[3]);
            }
        }
    }

    float* o0 = out + (size_t)(s0 + row0)*Dc + n0;
    float* o1 = o0 + (size_t)8*Dc;
    #pragma unroll
    for (int nb = 0; nb < 16; nb++) {
        int col = nb*8 + 2*t;
        float b0 = bz[n0 + col], b1 = bz[n0 + col + 1];
        *(float2*)(o0 + col) = make_float2(s[nb*4+0] + b0, s[nb*4+1] + b1);
        *(float2*)(o1 + col) = make_float2(s[nb*4+2] + b0, s[nb*4+3] + b1);
    }
}

extern "C" void kernel_launch(void* const* d_in, const int* in_sizes, int n_in,
                              void* d_out, int out_size)
{
    const float* Xq = (const float*)d_in[0];
    const float* Xk = (const float*)d_in[1];
    const float* Xv = (const float*)d_in[2];
    const float* Wq = (const float*)d_in[3];
    const float* Wk = (const float*)d_in[4];
    const float* Wv = (const float*)d_in[5];
    const float* Wz = (const float*)d_in[6];
    const float* bz = (const float*)d_in[7];
    float* out  = (float*)d_out;
    float* attn = out + (size_t)Bc*Sc*Dc;   // out first, then attn_mean

    cudaFuncSetAttribute((const void*)flash_attn,
                         cudaFuncAttributeMaxDynamicSharedMemorySize, SMEM_FL);
    cudaFuncSetAttribute((const void*)out_proj_mma,
                         cudaFuncAttributeMaxDynamicSharedMemorySize, SMEM_OP);

    qkv_proj<<<dim3(Sc/64, Hc, Bc), 256>>>(Xq, Xk, Xv, Wq, Wk, Wv);
    wz_convert<<<Dc*Dc/1024, 256>>>(Wz);
    flash_attn<<<dim3(Sc/128, Hc, Bc), 256, SMEM_FL>>>();
    attn_mean_kernel<<<dim3(Sc, Bc), 256>>>(attn);
    out_proj_mma<<<dim3(Dc/128, (Bc*Sc)/128), 256, SMEM_OP>>>(bz, out);
}

// round 7
// speedup vs baseline: 5.9167x; 1.1693x over previous
#include <cuda_runtime.h>
#include <cuda_bf16.h>
#include <cuda_fp16.h>
#include <cstdint>

#define Bc 2
#define Sc 2048
#define Dc 1024
#define Hc 16
#define HDc 64

// ---------------- scratch globals (allocation-free) ----------------
__device__ __nv_bfloat16 g_Qh[Bc*Hc*Sc*HDc];
__device__ __nv_bfloat16 g_Ql[Bc*Hc*Sc*HDc];
__device__ __nv_bfloat16 g_Kh[Bc*Hc*Sc*HDc];
__device__ __nv_bfloat16 g_Kl[Bc*Hc*Sc*HDc];
__device__ __half        g_Vt[Bc*Hc*Sc*HDc];    // [b,h,e,s] transposed, fp16
__device__ __nv_bfloat16 g_Zh[Bc*Sc*Dc];        // Z bf16 hi/lo ([s][k], k contiguous)
__device__ __nv_bfloat16 g_Zl[Bc*Sc*Dc];
__device__ __nv_bfloat16 g_Wzh[Dc*Dc];          // Wz bf16 hi/lo ([n][k], k contiguous)
__device__ __nv_bfloat16 g_Wzl[Dc*Dc];
__device__ __half g_S[134217728];                // [b,h,q,k] unnormalized exp(score), fp16
__device__ float g_isum[Bc*Hc*Sc];               // 1/rowsum

// ---------------- warp MMA helpers (base ISA: valid on sm_103 plain) ----------------
__device__ __forceinline__ void ldm4(uint32_t addr, uint32_t* r) {
    asm volatile("ldmatrix.sync.aligned.m8n8.x4.shared.b16 {%0,%1,%2,%3}, [%4];"
                 : "=r"(r[0]), "=r"(r[1]), "=r"(r[2]), "=r"(r[3]) : "r"(addr));
}
__device__ __forceinline__ void mma16816(float* c, const uint32_t* a, uint32_t b0, uint32_t b1) {
    asm volatile("mma.sync.aligned.m16n8k16.row.col.f32.bf16.bf16.f32 "
                 "{%0,%1,%2,%3}, {%4,%5,%6,%7}, {%8,%9}, {%0,%1,%2,%3};"
                 : "+f"(c[0]), "+f"(c[1]), "+f"(c[2]), "+f"(c[3])
                 : "r"(a[0]), "r"(a[1]), "r"(a[2]), "r"(a[3]), "r"(b0), "r"(b1));
}
__device__ __forceinline__ void mma16816h(float* c, const uint32_t* a, uint32_t b0, uint32_t b1) {
    asm volatile("mma.sync.aligned.m16n8k16.row.col.f32.f16.f16.f32 "
                 "{%0,%1,%2,%3}, {%4,%5,%6,%7}, {%8,%9}, {%0,%1,%2,%3};"
                 : "+f"(c[0]), "+f"(c[1]), "+f"(c[2]), "+f"(c[3])
                 : "r"(a[0]), "r"(a[1]), "r"(a[2]), "r"(a[3]), "r"(b0), "r"(b1));
}
__device__ __forceinline__ uint32_t pack_bf2(__nv_bfloat16 a, __nv_bfloat16 b) {
    return (uint32_t)__bfloat16_as_ushort(a) | ((uint32_t)__bfloat16_as_ushort(b) << 16);
}
__device__ __forceinline__ void split_bf(float x, __nv_bfloat16& hi, __nv_bfloat16& lo) {
    hi = __float2bfloat16(x);
    lo = __float2bfloat16(x - __bfloat162float(hi));
}
__device__ __forceinline__ void cpasync16(uint32_t daddr, const void* gptr) {
    asm volatile("cp.async.cg.shared.global [%0], [%1], 16;" :: "r"(daddr), "l"(gptr));
}
#define CP_COMMIT() asm volatile("cp.async.commit_group;" ::: "memory")
#define CP_WAIT1()  asm volatile("cp.async.wait_group 1;" ::: "memory")
#define CP_WAIT0()  asm volatile("cp.async.wait_group 0;" ::: "memory")

// ---------------- QKV projection (Q/K bf16 hi/lo; V fp16 transposed via smem) ----
__global__ __launch_bounds__(256) void qkv_proj(
    const float* __restrict__ Xq, const float* __restrict__ Xk, const float* __restrict__ Xv,
    const float* __restrict__ Wq, const float* __restrict__ Wk, const float* __restrict__ Wv)
{
    __shared__ float Xs[64*65];
    __shared__ float Ws[64*65];
    int s0 = blockIdx.x*64, h = blockIdx.y, b = blockIdx.z;
    int tid = threadIdx.x;
    const float inv4 = 0.35355339059327373f; // HD^-0.25
    const float l2e  = 1.4426950408889634f;
    const float* Xin[3] = {Xq, Xk, Xv};
    const float* Win[3] = {Wq, Wk, Wv};
    int m  = tid & 15;   // e = m + 16*i
    int s4 = tid >> 4;   // s = s4 + 16*j

    for (int t = 0; t < 3; t++) {
        const float* W = Win[t] + h*64*64;
        const float* X = Xin[t] + ((size_t)b*Sc + s0)*Dc + h*64;
        for (int i = tid; i < 4096; i += 256) { int e=i>>6, d=i&63; Ws[e*65+d]=W[i]; }
        for (int i = tid; i < 4096; i += 256) { int r=i>>6, d=i&63; Xs[r*65+d]=X[(size_t)r*Dc+d]; }
        __syncthreads();
        float acc[4][4] = {};
        #pragma unroll 8
        for (int d = 0; d < 64; d++) {
            float wv[4], xv[4];
            #pragma unroll
            for (int i = 0; i < 4; i++) wv[i] = Ws[(m+16*i)*65 + d];
            #pragma unroll
            for (int j = 0; j < 4; j++) xv[j] = Xs[(s4+16*j)*65 + d];
            #pragma unroll
            for (int j = 0; j < 4; j++)
                #pragma unroll
                for (int i = 0; i < 4; i++)
                    acc[j][i] += xv[j]*wv[i];
        }
        if (t < 2) {
            float scl = (t == 0) ? inv4*l2e : inv4;
            __nv_bfloat16* Oh = (t==0 ? g_Qh : g_Kh) + (((size_t)b*Hc + h)*Sc + s0)*64;
            __nv_bfloat16* Ol = (t==0 ? g_Ql : g_Kl) + (((size_t)b*Hc + h)*Sc + s0)*64;
            #pragma unroll
            for (int j = 0; j < 4; j++)
                #pragma unroll
                for (int i = 0; i < 4; i++) {
                    float x = acc[j][i]*scl;
                    __nv_bfloat16 hi, lo; split_bf(x, hi, lo);
                    size_t idx = (size_t)(s4+16*j)*64 + (m+16*i);
                    Oh[idx] = hi; Ol[idx] = lo;
                }
        } else {
            // transpose through smem for coalesced V^T stores (fp16 single)
            __syncthreads();
            __half* Vhs = (__half*)Xs;   // [64][66]
            #pragma unroll
            for (int j = 0; j < 4; j++)
                #pragma unroll
                for (int i = 0; i < 4; i++) {
                    int e = m + 16*i, s = s4 + 16*j;
                    Vhs[e*66 + s] = __float2half_rn(acc[j][i]);
                }
            __syncthreads();
            __half* Oh = g_Vt + ((size_t)b*Hc + h)*64*Sc;
            #pragma unroll
            for (int it = 0; it < 8; it++) {
                int i2 = tid + it*256;
                int e = i2 >> 5, s2 = i2 & 31;
                uint32_t vh = *(uint32_t*)&Vhs[e*66 + 2*s2];
                *(uint32_t*)(Oh + (size_t)e*Sc + s0 + 2*s2) = vh;
            }
        }
        __syncthreads();
    }
}

// ---------------- Wz -> bf16 hi/lo ----------------
__global__ __launch_bounds__(256) void wz_convert(const float* __restrict__ Wz)
{
    int i = (blockIdx.x*256 + threadIdx.x)*4;
    float4 v = *(const float4*)(Wz + i);
    __nv_bfloat16 h0,l0,h1,l1,h2,l2,h3,l3;
    split_bf(v.x,h0,l0); split_bf(v.y,h1,l1); split_bf(v.z,h2,l2); split_bf(v.w,h3,l3);
    *(uint32_t*)(g_Wzh + i)     = pack_bf2(h0,h1);
    *(uint32_t*)(g_Wzh + i + 2) = pack_bf2(h2,h3);
    *(uint32_t*)(g_Wzl + i)     = pack_bf2(l0,l1);
    *(uint32_t*)(g_Wzl + i + 2) = pack_bf2(l2,l3);
}

// ---------------- flash attention (warp HMMA, fp16 single-pass PV) -----------
// grid (S/128, H, B), 256 threads (8 warps x 16 q-rows), 106KB dyn smem.
// Buffer: KH +0 (18432), KL +18432 (18432), VH +36864 (17408). size 54272.
#define BUF_SZ  54272
#define SMEM_FL 108544

__device__ __forceinline__ void stage_k_async(uint32_t dst, const float4* gsrc, int tid) {
    #pragma unroll
    for (int it = 0; it < 4; it++) {
        int i = tid + it*256;
        int r = i >> 3, c = i & 7;
        cpasync16(dst + r*144 + c*16, gsrc + i);
    }
}
__device__ __forceinline__ void stage_v_async(uint32_t dst, const float4* gv, int kb, int tid) {
    #pragma unroll
    for (int it = 0; it < 4; it++) {
        int i = tid + it*256;
        int e = i >> 4, c = i & 15;
        cpasync16(dst + e*272 + c*16, gv + e*256 + kb*16 + c);
    }
}
__device__ __forceinline__ void issue_tile(uint32_t buf, size_t bh, int kb,
                                           const float4* gv, int tid) {
    const float4* kh = (const float4*)g_Kh + ((bh*Sc + (size_t)kb*128) << 3);
    const float4* kl = (const float4*)g_Kl + ((bh*Sc + (size_t)kb*128) << 3);
    stage_k_async(buf,         kh, tid);
    stage_k_async(buf + 18432, kl, tid);
    stage_v_async(buf + 36864, gv, kb, tid);
    CP_COMMIT();
}

__global__ __launch_bounds__(256,1) void flash_attn()
{
    extern __shared__ char smem[];
    uint32_t sb = (uint32_t)__cvta_generic_to_shared(smem);
    int tid = threadIdx.x, wid = tid >> 5, lane = tid & 31;
    int q0 = blockIdx.x*128, h = blockIdx.y, b = blockIdx.z;
    size_t bh = (size_t)b*Hc + h;
    int t = lane & 3;
    int row0 = 16*wid + (lane >> 2);   // first q row (second is row0+8)

    const float4* gv = (const float4*)(g_Vt + bh*(size_t)64*Sc);

    // --- prologue: Q into buffer0 K regions, load fragments, then start pipeline ---
    stage_k_async(sb,         (const float4*)g_Qh + ((bh*Sc + q0) << 3), tid);
    stage_k_async(sb + 18432, (const float4*)g_Ql + ((bh*Sc + q0) << 3), tid);
    CP_COMMIT(); CP_WAIT0();
    __syncthreads();

    uint32_t qh[4][4], ql[4][4];
    #pragma unroll
    for (int ks = 0; ks < 4; ks++) {
        uint32_t aaddr = sb + (16*wid + (lane & 15))*144 + ks*32 + ((lane >> 4) << 4);
        ldm4(aaddr, qh[ks]);
        ldm4(aaddr + 18432, ql[ks]);
    }
    __syncthreads();   // Q reads done before buffer0 overwrite

    issue_tile(sb,          bh, 0, gv, tid);
    issue_tile(sb + BUF_SZ, bh, 1, gv, tid);

    float z[32];
    #pragma unroll
    for (int i = 0; i < 32; i++) z[i] = 0.f;
    float rs0 = 0.f, rs1 = 0.f;
    __half* gS0 = g_S + (bh*Sc + q0 + row0)*Sc;
    __half* gS1 = gS0 + (size_t)8*Sc;

    for (int kb = 0; kb < Sc/128; kb++) {
        if (kb < 15) { CP_WAIT1(); } else { CP_WAIT0(); }
        __syncthreads();
        uint32_t buf = sb + (kb & 1)*BUF_SZ;

        // ---- scores: S = Qh*Kh + Ql*Kh + Qh*Kl  (128x128, contraction 64) ----
        float s[64];
        #pragma unroll
        for (int i = 0; i < 64; i++) s[i] = 0.f;
        #pragma unroll
        for (int ks = 0; ks < 4; ks++) {
            #pragma unroll
            for (int nb2 = 0; nb2 < 8; nb2++) {
                uint32_t baddr = buf + (nb2*16 + (lane & 7) + ((lane >> 4) << 3))*144
                               + ks*32 + (((lane >> 3) & 1) << 4);
                uint32_t bhf[4], blf[4];
                ldm4(baddr, bhf);
                ldm4(baddr + 18432, blf);
                mma16816(s + (2*nb2)*4,   qh[ks], bhf[0], bhf[1]);
                mma16816(s + (2*nb2+1)*4, qh[ks], bhf[2], bhf[3]);
                mma16816(s + (2*nb2)*4,   ql[ks], bhf[0], bhf[1]);
                mma16816(s + (2*nb2+1)*4, ql[ks], bhf[2], bhf[3]);
                mma16816(s + (2*nb2)*4,   qh[ks], blf[0], blf[1]);
                mma16816(s + (2*nb2+1)*4, qh[ks], blf[2], blf[3]);
            }
        }

        // ---- fused epilogue + fp16 PV, per 16-key chunk m ----
        // C-fragment of chunk m IS the A-fragment of P·V; the half2 pairs we
        // store to g_S are exactly the fp16 A registers.
        #pragma unroll
        for (int m = 0; m < 8; m++) {
            float ea0 = exp2f(s[8*m+0]), ea1 = exp2f(s[8*m+1]);
            float ea2 = exp2f(s[8*m+2]), ea3 = exp2f(s[8*m+3]);
            float eb0 = exp2f(s[8*m+4]), eb1 = exp2f(s[8*m+5]);
            float eb2 = exp2f(s[8*m+6]), eb3 = exp2f(s[8*m+7]);
            rs0 += ea0 + ea1 + eb0 + eb1;
            rs1 += ea2 + ea3 + eb2 + eb3;
            uint32_t ah[4];
            __half2 p0 = __floats2half2_rn(ea0, ea1);
            __half2 p1 = __floats2half2_rn(ea2, ea3);
            __half2 p2 = __floats2half2_rn(eb0, eb1);
            __half2 p3 = __floats2half2_rn(eb2, eb3);
            ah[0] = *(uint32_t*)&p0; ah[1] = *(uint32_t*)&p1;
            ah[2] = *(uint32_t*)&p2; ah[3] = *(uint32_t*)&p3;
            int col = kb*128 + 16*m + 2*t;
            *(__half2*)(gS0 + col)     = p0;
            *(__half2*)(gS1 + col)     = p1;
            *(__half2*)(gS0 + col + 8) = p2;
            *(__half2*)(gS1 + col + 8) = p3;

            #pragma unroll
            for (int nb2 = 0; nb2 < 4; nb2++) {
                uint32_t vaddr = buf + 36864 + (nb2*16 + (lane & 7) + ((lane >> 4) << 3))*272
                               + m*32 + (((lane >> 3) & 1) << 4);
                uint32_t bhf[4];
                ldm4(vaddr, bhf);
                mma16816h(z + (2*nb2)*4,   ah, bhf[0], bhf[1]);
                mma16816h(z + (2*nb2+1)*4, ah, bhf[2], bhf[3]);
            }
        }
        __syncthreads();   // all warps done with this buffer
        if (kb + 2 < 16)
            issue_tile(sb + (kb & 1)*BUF_SZ, bh, kb + 2, gv, tid);
    }

    // rowsum reduce within quad
    #pragma unroll
    for (int o = 1; o <= 2; o <<= 1) {
        rs0 += __shfl_xor_sync(0xffffffffu, rs0, o);
        rs1 += __shfl_xor_sync(0xffffffffu, rs1, o);
    }
    float inv0 = 1.f/rs0, inv1 = 1.f/rs1;
    __nv_bfloat16* zh0 = g_Zh + ((size_t)b*Sc + q0 + row0)*Dc + h*64;
    __nv_bfloat16* zl0 = g_Zl + ((size_t)b*Sc + q0 + row0)*Dc + h*64;
    #pragma unroll
    for (int nb = 0; nb < 8; nb++) {
        int col = nb*8 + 2*t;
        float f0 = z[nb*4+0]*inv0, f1 = z[nb*4+1]*inv0;
        float f2 = z[nb*4+2]*inv1, f3 = z[nb*4+3]*inv1;
        __nv_bfloat16 h0,l0,h1,l1,h2,l2,h3,l3;
        split_bf(f0,h0,l0); split_bf(f1,h1,l1); split_bf(f2,h2,l2); split_bf(f3,h3,l3);
        *(uint32_t*)(zh0 + col)          = pack_bf2(h0,h1);
        *(uint32_t*)(zh0 + 8*Dc + col)   = pack_bf2(h2,h3);
        *(uint32_t*)(zl0 + col)          = pack_bf2(l0,l1);
        *(uint32_t*)(zl0 + 8*Dc + col)   = pack_bf2(l2,l3);
    }
    if (t == 0) {
        g_isum[bh*Sc + q0 + row0]     = inv0;
        g_isum[bh*Sc + q0 + row0 + 8] = inv1;
    }
}

// ---------------- attn_mean: am[b,q,k] = (1/H) sum_h g_S[b,h,q,k]*isum[b,h,q] ----------------
__global__ __launch_bounds__(256) void attn_mean_kernel(float* __restrict__ am)
{
    int q = blockIdx.x, b = blockIdx.y, t = threadIdx.x;
    float a[8] = {0.f,0.f,0.f,0.f,0.f,0.f,0.f,0.f};
    #pragma unroll 1
    for (int h = 0; h < Hc; h++) {
        size_t bh = (size_t)b*Hc + h;
        float w = g_isum[bh*Sc + q];
        const float4* row = (const float4*)(g_S + (bh*Sc + q)*Sc);
        float4 v = row[t];
        const __half2* hp = (const __half2*)&v;
        #pragma unroll
        for (int j = 0; j < 4; j++) {
            float2 f = __half22float2(hp[j]);
            a[2*j]   += f.x*w;
            a[2*j+1] += f.y*w;
        }
    }
    const float invH = 1.0f/Hc;
    float4* dst = (float4*)(am + ((size_t)b*Sc + q)*Sc);
    dst[2*t]   = make_float4(a[0]*invH, a[1]*invH, a[2]*invH, a[3]*invH);
    dst[2*t+1] = make_float4(a[4]*invH, a[5]*invH, a[6]*invH, a[7]*invH);
}

// ---------------- Output projection (warp HMMA, hi/lo bf16) ----------------
#define SM_ZH 0
#define SM_ZL 18432
#define SM_WH 36864
#define SM_WL 55296
#define SMEM_OP 73728

__device__ __forceinline__ void stage_op(char* smem, int off, const float4* gs,
                                         int base_row, int kc, int tid) {
    #pragma unroll
    for (int it = 0; it < 4; it++) {
        int i = tid + it*256;
        int r = i >> 3, c = i & 7;
        *(float4*)(smem + off + r*144 + c*16) = gs[(size_t)(base_row + r)*128 + kc*8 + c];
    }
}

__global__ __launch_bounds__(256,1) void out_proj_mma(
    const float* __restrict__ bz, float* __restrict__ out)
{
    extern __shared__ char smem[];
    uint32_t sb = (uint32_t)__cvta_generic_to_shared(smem);
    int tid = threadIdx.x, wid = tid >> 5, lane = tid & 31;
    int n0 = blockIdx.x*128, s0 = blockIdx.y*128;
    int t = lane & 3;
    int row0 = 16*wid + (lane >> 2);

    const float4* gzh = (const float4*)g_Zh;
    const float4* gzl = (const float4*)g_Zl;
    const float4* gwh = (const float4*)g_Wzh;
    const float4* gwl = (const float4*)g_Wzl;

    float s[64];
    #pragma unroll
    for (int i = 0; i < 64; i++) s[i] = 0.f;

    for (int kc = 0; kc < 16; kc++) {
        if (kc) __syncthreads();
        stage_op(smem, SM_ZH, gzh, s0, kc, tid);
        stage_op(smem, SM_ZL, gzl, s0, kc, tid);
        stage_op(smem, SM_WH, gwh, n0, kc, tid);
        stage_op(smem, SM_WL, gwl, n0, kc, tid);
        __syncthreads();

        #pragma unroll
        for (int ks = 0; ks < 4; ks++) {
            uint32_t aaddr = sb + SM_ZH + (16*wid + (lane & 15))*144 + ks*32 + ((lane >> 4) << 4);
            uint32_t ah[4], al[4];
            ldm4(aaddr, ah);
            ldm4(aaddr + (SM_ZL - SM_ZH), al);
            #pragma unroll
            for (int nb2 = 0; nb2 < 8; nb2++) {
                uint32_t baddr = sb + SM_WH + (nb2*16 + (lane & 7) + ((lane >> 4) << 3))*144
                               + ks*32 + (((lane >> 3) & 1) << 4);
                uint32_t bhf[4], blf[4];
                ldm4(baddr, bhf);
                ldm4(baddr + (SM_WL - SM_WH), blf);
                mma16816(s + (2*nb2)*4,   ah, bhf[0], bhf[1]);
                mma16816(s + (2*nb2+1)*4, ah, bhf[2], bhf[3]);
                mma16816(s + (2*nb2)*4,   al, bhf[0], bhf[1]);
                mma16816(s + (2*nb2+1)*4, al, bhf[2], bhf[3]);
                mma16816(s + (2*nb2)*4,   ah, blf[0], blf[1]);
                mma16816(s + (2*nb2+1)*4, ah, blf[2], blf[3]);
            }
        }
    }

    float* o0 = out + (size_t)(s0 + row0)*Dc + n0;
    float* o1 = o0 + (size_t)8*Dc;
    #pragma unroll
    for (int nb = 0; nb < 16; nb++) {
        int col = nb*8 + 2*t;
        float b0 = bz[n0 + col], b1 = bz[n0 + col + 1];
        *(float2*)(o0 + col) = make_float2(s[nb*4+0] + b0, s[nb*4+1] + b1);
        *(float2*)(o1 + col) = make_float2(s[nb*4+2] + b0, s[nb*4+3] + b1);
    }
}

extern "C" void kernel_launch(void* const* d_in, const int* in_sizes, int n_in,
                              void* d_out, int out_size)
{
    const float* Xq = (const float*)d_in[0];
    const float* Xk = (const float*)d_in[1];
    const float* Xv = (const float*)d_in[2];
    const float* Wq = (const float*)d_in[3];
    const float* Wk = (const float*)d_in[4];
    const float* Wv = (const float*)d_in[5];
    const float* Wz = (const float*)d_in[6];
    const float* bz = (const float*)d_in[7];
    float* out  = (float*)d_out;
    float* attn = out + (size_t)Bc*Sc*Dc;   // out first, then attn_mean

    cudaFuncSetAttribute((const void*)flash_attn,
                         cudaFuncAttributeMaxDynamicSharedMemorySize, SMEM_FL);
    cudaFuncSetAttribute((const void*)out_proj_mma,
                         cudaFuncAttributeMaxDynamicSharedMemorySize, SMEM_OP);

    qkv_proj<<<dim3(Sc/64, Hc, Bc), 256>>>(Xq, Xk, Xv, Wq, Wk, Wv);
    wz_convert<<<Dc*Dc/1024, 256>>>(Wz);
    flash_attn<<<dim3(Sc/128, Hc, Bc), 256, SMEM_FL>>>();
    attn_mean_kernel<<<dim3(Sc, Bc), 256>>>(attn);
    out_proj_mma<<<dim3(Dc/128, (Bc*Sc)/128), 256, SMEM_OP>>>(bz, out);
}

// round 9
// speedup vs baseline: 7.4367x; 1.2569x over previous
#include <cuda_runtime.h>
#include <cuda_bf16.h>
#include <cuda_fp16.h>
#include <cstdint>

#define Bc 2
#define Sc 2048
#define Dc 1024
#define Hc 16
#define HDc 64

// ---------------- scratch globals (allocation-free) ----------------
__device__ __half g_Qh[Bc*Hc*Sc*HDc];           // Q fp16 hi  (scaled by inv4*log2e)
__device__ __half g_Ql[Bc*Hc*Sc*HDc];           // Q fp16 lo
__device__ __half g_K [Bc*Hc*Sc*HDc];           // K fp16 (scaled by inv4)
__device__ __half g_Vt[Bc*Hc*Sc*HDc];           // V^T [b,h,e,s], fp16
__device__ __half g_Zh[Bc*Sc*Dc];               // Z fp16 hi ([s][k])
__device__ __half g_Zl[Bc*Sc*Dc];               // Z fp16 lo
__device__ __half g_Wz[Dc*Dc];                  // Wz fp16 ([n][k])
__device__ __half g_S[134217728];               // [b,h,q,k] unnormalized exp(score)
__device__ float g_isum[Bc*Hc*Sc];              // 1/rowsum

// ---------------- warp MMA helpers (base ISA: valid on sm_103 plain) ----------------
__device__ __forceinline__ void ldm4(uint32_t addr, uint32_t* r) {
    asm volatile("ldmatrix.sync.aligned.m8n8.x4.shared.b16 {%0,%1,%2,%3}, [%4];"
                 : "=r"(r[0]), "=r"(r[1]), "=r"(r[2]), "=r"(r[3]) : "r"(addr));
}
__device__ __forceinline__ void mma16816h(float* c, const uint32_t* a, uint32_t b0, uint32_t b1) {
    asm volatile("mma.sync.aligned.m16n8k16.row.col.f32.f16.f16.f32 "
                 "{%0,%1,%2,%3}, {%4,%5,%6,%7}, {%8,%9}, {%0,%1,%2,%3};"
                 : "+f"(c[0]), "+f"(c[1]), "+f"(c[2]), "+f"(c[3])
                 : "r"(a[0]), "r"(a[1]), "r"(a[2]), "r"(a[3]), "r"(b0), "r"(b1));
}
__device__ __forceinline__ void split_h(float x, __half& hi, __half& lo) {
    hi = __float2half_rn(x);
    lo = __float2half_rn(x - __half2float(hi));
}
__device__ __forceinline__ void cpasync16(uint32_t daddr, const void* gptr) {
    asm volatile("cp.async.cg.shared.global [%0], [%1], 16;" :: "r"(daddr), "l"(gptr));
}
#define CP_COMMIT() asm volatile("cp.async.commit_group;" ::: "memory")
#define CP_WAIT1()  asm volatile("cp.async.wait_group 1;" ::: "memory")
#define CP_WAIT0()  asm volatile("cp.async.wait_group 0;" ::: "memory")

// ---------------- QKV projection (Q fp16 hi/lo; K fp16; V fp16 transposed) ----
__global__ __launch_bounds__(256) void qkv_proj(
    const float* __restrict__ Xq, const float* __restrict__ Xk, const float* __restrict__ Xv,
    const float* __restrict__ Wq, const float* __restrict__ Wk, const float* __restrict__ Wv)
{
    __shared__ float Xs[64*65];
    __shared__ float Ws[64*65];
    int s0 = blockIdx.x*64, h = blockIdx.y, b = blockIdx.z;
    int tid = threadIdx.x;
    const float inv4 = 0.35355339059327373f; // HD^-0.25
    const float l2e  = 1.4426950408889634f;
    const float* Xin[3] = {Xq, Xk, Xv};
    const float* Win[3] = {Wq, Wk, Wv};
    int m  = tid & 15;   // e = m + 16*i
    int s4 = tid >> 4;   // s = s4 + 16*j

    for (int t = 0; t < 3; t++) {
        const float* W = Win[t] + h*64*64;
        const float* X = Xin[t] + ((size_t)b*Sc + s0)*Dc + h*64;
        for (int i = tid; i < 4096; i += 256) { int e=i>>6, d=i&63; Ws[e*65+d]=W[i]; }
        for (int i = tid; i < 4096; i += 256) { int r=i>>6, d=i&63; Xs[r*65+d]=X[(size_t)r*Dc+d]; }
        __syncthreads();
        float acc[4][4] = {};
        #pragma unroll 8
        for (int d = 0; d < 64; d++) {
            float wv[4], xv[4];
            #pragma unroll
            for (int i = 0; i < 4; i++) wv[i] = Ws[(m+16*i)*65 + d];
            #pragma unroll
            for (int j = 0; j < 4; j++) xv[j] = Xs[(s4+16*j)*65 + d];
            #pragma unroll
            for (int j = 0; j < 4; j++)
                #pragma unroll
                for (int i = 0; i < 4; i++)
                    acc[j][i] += xv[j]*wv[i];
        }
        if (t == 0) {
            __half* Oh = g_Qh + (((size_t)b*Hc + h)*Sc + s0)*64;
            __half* Ol = g_Ql + (((size_t)b*Hc + h)*Sc + s0)*64;
            #pragma unroll
            for (int j = 0; j < 4; j++)
                #pragma unroll
                for (int i = 0; i < 4; i++) {
                    float x = acc[j][i]*(inv4*l2e);
                    __half hi, lo; split_h(x, hi, lo);
                    size_t idx = (size_t)(s4+16*j)*64 + (m+16*i);
                    Oh[idx] = hi; Ol[idx] = lo;
                }
        } else if (t == 1) {
            __half* O = g_K + (((size_t)b*Hc + h)*Sc + s0)*64;
            #pragma unroll
            for (int j = 0; j < 4; j++)
                #pragma unroll
                for (int i = 0; i < 4; i++)
                    O[(size_t)(s4+16*j)*64 + (m+16*i)] = __float2half_rn(acc[j][i]*inv4);
        } else {
            // transpose through smem for coalesced V^T stores
            __syncthreads();
            __half* Vhs = (__half*)Xs;   // [64][66]
            #pragma unroll
            for (int j = 0; j < 4; j++)
                #pragma unroll
                for (int i = 0; i < 4; i++) {
                    int e = m + 16*i, s = s4 + 16*j;
                    Vhs[e*66 + s] = __float2half_rn(acc[j][i]);
                }
            __syncthreads();
            __half* Oh = g_Vt + ((size_t)b*Hc + h)*64*Sc;
            #pragma unroll
            for (int it = 0; it < 8; it++) {
                int i2 = tid + it*256;
                int e = i2 >> 5, s2 = i2 & 31;
                uint32_t vh = *(uint32_t*)&Vhs[e*66 + 2*s2];
                *(uint32_t*)(Oh + (size_t)e*Sc + s0 + 2*s2) = vh;
            }
        }
        __syncthreads();
    }
}

// ---------------- Wz -> fp16 ----------------
__global__ __launch_bounds__(256) void wz_convert(const float* __restrict__ Wz)
{
    int i = (blockIdx.x*256 + threadIdx.x)*4;
    float4 v = *(const float4*)(Wz + i);
    __half2 a = __floats2half2_rn(v.x, v.y);
    __half2 b = __floats2half2_rn(v.z, v.w);
    *(uint32_t*)(g_Wz + i)     = *(uint32_t*)&a;
    *(uint32_t*)(g_Wz + i + 2) = *(uint32_t*)&b;
}

// ---------------- flash attention (fp16 HMMA, 64-key tiles, 2 blocks/SM) -----------
// grid (S/128, H, B), 256 threads (8 warps x 16 q-rows), 36KB dyn smem.
// Buffer: K +0 (9216 = 64 rows x 144), V +9216 (9216). BUF_SZ 18432, two buffers.
// Prologue reuses the whole 36864 region for Qh (18432) + Ql (18432).
#define BUF_SZ  18432
#define SMEM_FL 36864

__device__ __forceinline__ void stage_k_async(uint32_t dst, const float4* gsrc, int tid) {
    // 64 rows x 8 float4 of data (padded 144B rows)
    for (int i = tid; i < 512; i += 256) {
        int r = i >> 3, c = i & 7;
        cpasync16(dst + r*144 + c*16, gsrc + i);
    }
}
__device__ __forceinline__ void stage_q_async(uint32_t dst, const float4* gsrc, int tid) {
    // 128 rows x 8 float4 of data
    for (int i = tid; i < 1024; i += 256) {
        int r = i >> 3, c = i & 7;
        cpasync16(dst + r*144 + c*16, gsrc + i);
    }
}
__device__ __forceinline__ void stage_v_async(uint32_t dst, const float4* gv, int kb, int tid) {
    // 64 e-rows x 8 float4 (64 keys) of data
    for (int i = tid; i < 512; i += 256) {
        int e = i >> 3, c = i & 7;
        cpasync16(dst + e*144 + c*16, gv + e*256 + kb*8 + c);
    }
}
__device__ __forceinline__ void issue_tile(uint32_t buf, size_t bh, int kb,
                                           const float4* gv, int tid) {
    const float4* kh = (const float4*)g_K + ((bh*Sc + (size_t)kb*64) << 3);
    stage_k_async(buf,        kh, tid);
    stage_v_async(buf + 9216, gv, kb, tid);
    CP_COMMIT();
}

__global__ __launch_bounds__(256,2) void flash_attn()
{
    extern __shared__ char smem[];
    uint32_t sb = (uint32_t)__cvta_generic_to_shared(smem);
    int tid = threadIdx.x, wid = tid >> 5, lane = tid & 31;
    int q0 = blockIdx.x*128, h = blockIdx.y, b = blockIdx.z;
    size_t bh = (size_t)b*Hc + h;
    int t = lane & 3;
    int row0 = 16*wid + (lane >> 2);   // first q row (second is row0+8)

    const float4* gv = (const float4*)(g_Vt + bh*(size_t)64*Sc);

    // --- prologue: Q into full smem region, load fragments, start pipeline ---
    stage_q_async(sb,         (const float4*)g_Qh + ((bh*Sc + q0) << 3), tid);
    stage_q_async(sb + 18432, (const float4*)g_Ql + ((bh*Sc + q0) << 3), tid);
    CP_COMMIT(); CP_WAIT0();
    __syncthreads();

    uint32_t qh[4][4], ql[4][4];
    #pragma unroll
    for (int ks = 0; ks < 4; ks++) {
        uint32_t aaddr = sb + (16*wid + (lane & 15))*144 + ks*32 + ((lane >> 4) << 4);
        ldm4(aaddr, qh[ks]);
        ldm4(aaddr + 18432, ql[ks]);
    }
    __syncthreads();   // Q reads done before overwrite

    issue_tile(sb,          bh, 0, gv, tid);
    issue_tile(sb + BUF_SZ, bh, 1, gv, tid);

    float z[32];
    #pragma unroll
    for (int i = 0; i < 32; i++) z[i] = 0.f;
    float rs0 = 0.f, rs1 = 0.f;
    __half* gS0 = g_S + (bh*Sc + q0 + row0)*Sc;
    __half* gS1 = gS0 + (size_t)8*Sc;

    for (int kb = 0; kb < Sc/64; kb++) {
        if (kb < Sc/64 - 1) { CP_WAIT1(); } else { CP_WAIT0(); }
        __syncthreads();
        uint32_t buf = sb + (kb & 1)*BUF_SZ;

        // ---- scores: S = Qh*K + Ql*K  (128x64, contraction 64) ----
        float s[32];
        #pragma unroll
        for (int i = 0; i < 32; i++) s[i] = 0.f;
        #pragma unroll
        for (int ks = 0; ks < 4; ks++) {
            #pragma unroll
            for (int nb2 = 0; nb2 < 4; nb2++) {
                uint32_t baddr = buf + (nb2*16 + (lane & 7) + ((lane >> 4) << 3))*144
                               + ks*32 + (((lane >> 3) & 1) << 4);
                uint32_t bhf[4];
                ldm4(baddr, bhf);
                mma16816h(s + (2*nb2)*4,   qh[ks], bhf[0], bhf[1]);
                mma16816h(s + (2*nb2+1)*4, qh[ks], bhf[2], bhf[3]);
                mma16816h(s + (2*nb2)*4,   ql[ks], bhf[0], bhf[1]);
                mma16816h(s + (2*nb2+1)*4, ql[ks], bhf[2], bhf[3]);
            }
        }

        // ---- fused epilogue + fp16 PV, per 16-key chunk m (C-frag == A-frag) ----
        #pragma unroll
        for (int m = 0; m < 4; m++) {
            float ea0 = exp2f(s[8*m+0]), ea1 = exp2f(s[8*m+1]);
            float ea2 = exp2f(s[8*m+2]), ea3 = exp2f(s[8*m+3]);
            float eb0 = exp2f(s[8*m+4]), eb1 = exp2f(s[8*m+5]);
            float eb2 = exp2f(s[8*m+6]), eb3 = exp2f(s[8*m+7]);
            rs0 += ea0 + ea1 + eb0 + eb1;
            rs1 += ea2 + ea3 + eb2 + eb3;
            uint32_t ah[4];
            __half2 p0 = __floats2half2_rn(ea0, ea1);
            __half2 p1 = __floats2half2_rn(ea2, ea3);
            __half2 p2 = __floats2half2_rn(eb0, eb1);
            __half2 p3 = __floats2half2_rn(eb2, eb3);
            ah[0] = *(uint32_t*)&p0; ah[1] = *(uint32_t*)&p1;
            ah[2] = *(uint32_t*)&p2; ah[3] = *(uint32_t*)&p3;
            int col = kb*64 + 16*m + 2*t;
            *(__half2*)(gS0 + col)     = p0;
            *(__half2*)(gS1 + col)     = p1;
            *(__half2*)(gS0 + col + 8) = p2;
            *(__half2*)(gS1 + col + 8) = p3;

            #pragma unroll
            for (int nb2 = 0; nb2 < 4; nb2++) {
                uint32_t vaddr = buf + 9216 + (nb2*16 + (lane & 7) + ((lane >> 4) << 3))*144
                               + m*32 + (((lane >> 3) & 1) << 4);
                uint32_t bhf[4];
                ldm4(vaddr, bhf);
                mma16816h(z + (2*nb2)*4,   ah, bhf[0], bhf[1]);
                mma16816h(z + (2*nb2+1)*4, ah, bhf[2], bhf[3]);
            }
        }
        __syncthreads();   // all warps done with this buffer
        if (kb + 2 < Sc/64)
            issue_tile(sb + (kb & 1)*BUF_SZ, bh, kb + 2, gv, tid);
    }

    // rowsum reduce within quad
    #pragma unroll
    for (int o = 1; o <= 2; o <<= 1) {
        rs0 += __shfl_xor_sync(0xffffffffu, rs0, o);
        rs1 += __shfl_xor_sync(0xffffffffu, rs1, o);
    }
    float inv0 = 1.f/rs0, inv1 = 1.f/rs1;
    __half* zh0 = g_Zh + ((size_t)b*Sc + q0 + row0)*Dc + h*64;
    __half* zl0 = g_Zl + ((size_t)b*Sc + q0 + row0)*Dc + h*64;
    #pragma unroll
    for (int nb = 0; nb < 8; nb++) {
        int col = nb*8 + 2*t;
        float f0 = z[nb*4+0]*inv0, f1 = z[nb*4+1]*inv0;
        float f2 = z[nb*4+2]*inv1, f3 = z[nb*4+3]*inv1;
        __half h0,l0,h1,l1,h2,l2,h3,l3;
        split_h(f0,h0,l0); split_h(f1,h1,l1); split_h(f2,h2,l2); split_h(f3,h3,l3);
        __half2 ph0 = __halves2half2(h0,h1), ph1 = __halves2half2(h2,h3);
        __half2 pl0 = __halves2half2(l0,l1), pl1 = __halves2half2(l2,l3);
        *(uint32_t*)(zh0 + col)        = *(uint32_t*)&ph0;
        *(uint32_t*)(zh0 + 8*Dc + col) = *(uint32_t*)&ph1;
        *(uint32_t*)(zl0 + col)        = *(uint32_t*)&pl0;
        *(uint32_t*)(zl0 + 8*Dc + col) = *(uint32_t*)&pl1;
    }
    if (t == 0) {
        g_isum[bh*Sc + q0 + row0]     = inv0;
        g_isum[bh*Sc + q0 + row0 + 8] = inv1;
    }
}

// ---------------- attn_mean: am[b,q,k] = (1/H) sum_h g_S[b,h,q,k]*isum[b,h,q] ----------------
__global__ __launch_bounds__(256) void attn_mean_kernel(float* __restrict__ am)
{
    int q = blockIdx.x, b = blockIdx.y, t = threadIdx.x;
    float a[8] = {0.f,0.f,0.f,0.f,0.f,0.f,0.f,0.f};
    #pragma unroll 1
    for (int h = 0; h < Hc; h++) {
        size_t bh = (size_t)b*Hc + h;
        float w = g_isum[bh*Sc + q];
        const float4* row = (const float4*)(g_S + (bh*Sc + q)*Sc);
        float4 v = row[t];
        const __half2* hp = (const __half2*)&v;
        #pragma unroll
        for (int j = 0; j < 4; j++) {
            float2 f = __half22float2(hp[j]);
            a[2*j]   += f.x*w;
            a[2*j+1] += f.y*w;
        }
    }
    const float invH = 1.0f/Hc;
    float4* dst = (float4*)(am + ((size_t)b*Sc + q)*Sc);
    dst[2*t]   = make_float4(a[0]*invH, a[1]*invH, a[2]*invH, a[3]*invH);
    dst[2*t+1] = make_float4(a[4]*invH, a[5]*invH, a[6]*invH, a[7]*invH);
}

// ---------------- Output projection (fp16 HMMA: Zh/Zl x W, 2 passes) ----------------
#define SM_ZH 0
#define SM_ZL 18432
#define SM_W  36864
#define SMEM_OP 55296

__device__ __forceinline__ void stage_op(char* smem, int off, const float4* gs,
                                         int base_row, int kc, int tid) {
    #pragma unroll
    for (int it = 0; it < 4; it++) {
        int i = tid + it*256;
        int r = i >> 3, c = i & 7;
        *(float4*)(smem + off + r*144 + c*16) = gs[(size_t)(base_row + r)*128 + kc*8 + c];
    }
}

__global__ __launch_bounds__(256,1) void out_proj_mma(
    const float* __restrict__ bz, float* __restrict__ out)
{
    extern __shared__ char smem[];
    uint32_t sb = (uint32_t)__cvta_generic_to_shared(smem);
    int tid = threadIdx.x, wid = tid >> 5, lane = tid & 31;
    int n0 = blockIdx.x*128, s0 = blockIdx.y*128;
    int t = lane & 3;
    int row0 = 16*wid + (lane >> 2);

    const float4* gzh = (const float4*)g_Zh;
    const float4* gzl = (const float4*)g_Zl;
    const float4* gw  = (const float4*)g_Wz;

    float s[64];
    #pragma unroll
    for (int i = 0; i < 64; i++) s[i] = 0.f;

    for (int kc = 0; kc < 16; kc++) {
        if (kc) __syncthreads();
        stage_op(smem, SM_ZH, gzh, s0, kc, tid);
        stage_op(smem, SM_ZL, gzl, s0, kc, tid);
        stage_op(smem, SM_W,  gw,  n0, kc, tid);
        __syncthreads();

        #pragma unroll
        for (int ks = 0; ks < 4; ks++) {
            uint32_t aaddr = sb + SM_ZH + (16*wid + (lane & 15))*144 + ks*32 + ((lane >> 4) << 4);
            uint32_t ah[4], al[4];
            ldm4(aaddr, ah);
            ldm4(aaddr + (SM_ZL - SM_ZH), al);
            #pragma unroll
            for (int nb2 = 0; nb2 < 8; nb2++) {
                uint32_t baddr = sb + SM_W + (nb2*16 + (lane & 7) + ((lane >> 4) << 3))*144
                               + ks*32 + (((lane >> 3) & 1) << 4);
                uint32_t bhf[4];
                ldm4(baddr, bhf);
                mma16816h(s + (2*nb2)*4,   ah, bhf[0], bhf[1]);
                mma16816h(s + (2*nb2+1)*4, ah, bhf[2], bhf[3]);
                mma16816h(s + (2*nb2)*4,   al, bhf[0], bhf[1]);
                mma16816h(s + (2*nb2+1)*4, al, bhf[2], bhf[3]);
            }
        }
    }

    float* o0 = out + (size_t)(s0 + row0)*Dc + n0;
    float* o1 = o0 + (size_t)8*Dc;
    #pragma unroll
    for (int nb = 0; nb < 16; nb++) {
        int col = nb*8 + 2*t;
        float b0 = bz[n0 + col], b1 = bz[n0 + col + 1];
        *(float2*)(o0 + col) = make_float2(s[nb*4+0] + b0, s[nb*4+1] + b1);
        *(float2*)(o1 + col) = make_float2(s[nb*4+2] + b0, s[nb*4+3] + b1);
    }
}

extern "C" void kernel_launch(void* const* d_in, const int* in_sizes, int n_in,
                              void* d_out, int out_size)
{
    const float* Xq = (const float*)d_in[0];
    const float* Xk = (const float*)d_in[1];
    const float* Xv = (const float*)d_in[2];
    const float* Wq = (const float*)d_in[3];
    const float* Wk = (const float*)d_in[4];
    const float* Wv = (const float*)d_in[5];
    const float* Wz = (const float*)d_in[6];
    const float* bz = (const float*)d_in[7];
    float* out  = (float*)d_out;
    float* attn = out + (size_t)Bc*Sc*Dc;   // out first, then attn_mean

    cudaFuncSetAttribute((const void*)flash_attn,
                         cudaFuncAttributeMaxDynamicSharedMemorySize, SMEM_FL);
    cudaFuncSetAttribute((const void*)out_proj_mma,
                         cudaFuncAttributeMaxDynamicSharedMemorySize, SMEM_OP);

    qkv_proj<<<dim3(Sc/64, Hc, Bc), 256>>>(Xq, Xk, Xv, Wq, Wk, Wv);
    wz_convert<<<Dc*Dc/1024, 256>>>(Wz);
    flash_attn<<<dim3(Sc/128, Hc, Bc), 256, SMEM_FL>>>();
    attn_mean_kernel<<<dim3(Sc, Bc), 256>>>(attn);
    out_proj_mma<<<dim3(Dc/128, (Bc*Sc)/128), 256, SMEM_OP>>>(bz, out);
}

// round 11
// speedup vs baseline: 9.4128x; 1.2657x over previous
#include <cuda_runtime.h>
#include <cuda_bf16.h>
#include <cuda_fp16.h>
#include <cstdint>

#define Bc 2
#define Sc 2048
#define Dc 1024
#define Hc 16
#define HDc 64

// ---------------- scratch globals (allocation-free) ----------------
__device__ __half g_Q [Bc*Hc*Sc*HDc];           // Q fp16 (scaled by inv4*log2e)
__device__ __half g_K [Bc*Hc*Sc*HDc];           // K fp16 (scaled by inv4)
__device__ __half g_Vt[Bc*Hc*Sc*HDc];           // V^T [b,h,e,s], fp16
__device__ __half g_Zh[Bc*Sc*Dc];               // Z fp16 hi ([s][k])
__device__ __half g_Zl[Bc*Sc*Dc];               // Z fp16 lo
__device__ __half g_Wz[Dc*Dc];                  // Wz fp16 ([n][k])
__device__ __half g_W3h[3*Hc*HDc*HDc];          // Wq/Wk/Wv fp16 hi (concat)
__device__ __half g_W3l[3*Hc*HDc*HDc];          // Wq/Wk/Wv fp16 lo
__device__ __half g_S[134217728];               // [b,h,q,k] unnormalized exp(score)
__device__ float g_isum[Bc*Hc*Sc];              // 1/rowsum

// ---------------- warp MMA helpers (base ISA: valid on sm_103 plain) ----------------
__device__ __forceinline__ void ldm4(uint32_t addr, uint32_t* r) {
    asm volatile("ldmatrix.sync.aligned.m8n8.x4.shared.b16 {%0,%1,%2,%3}, [%4];"
                 : "=r"(r[0]), "=r"(r[1]), "=r"(r[2]), "=r"(r[3]) : "r"(addr));
}
__device__ __forceinline__ void mma16816h(float* c, const uint32_t* a, uint32_t b0, uint32_t b1) {
    asm volatile("mma.sync.aligned.m16n8k16.row.col.f32.f16.f16.f32 "
                 "{%0,%1,%2,%3}, {%4,%5,%6,%7}, {%8,%9}, {%0,%1,%2,%3};"
                 : "+f"(c[0]), "+f"(c[1]), "+f"(c[2]), "+f"(c[3])
                 : "r"(a[0]), "r"(a[1]), "r"(a[2]), "r"(a[3]), "r"(b0), "r"(b1));
}
__device__ __forceinline__ void split_h(float x, __half& hi, __half& lo) {
    hi = __float2half_rn(x);
    lo = __float2half_rn(x - __half2float(hi));
}
__device__ __forceinline__ void cpasync16(uint32_t daddr, const void* gptr) {
    asm volatile("cp.async.cg.shared.global [%0], [%1], 16;" :: "r"(daddr), "l"(gptr));
}
#define CP_COMMIT() asm volatile("cp.async.commit_group;" ::: "memory")
#define CP_WAIT1()  asm volatile("cp.async.wait_group 1;" ::: "memory")
#define CP_WAIT0()  asm volatile("cp.async.wait_group 0;" ::: "memory")

// ---------------- W converts ----------------
__global__ __launch_bounds__(256) void w3_convert(
    const float* __restrict__ Wq, const float* __restrict__ Wk, const float* __restrict__ Wv)
{
    const float* src = (blockIdx.y == 0) ? Wq : (blockIdx.y == 1 ? Wk : Wv);
    int i = (blockIdx.x*256 + threadIdx.x)*4;          // over 65536 elems
    int o = blockIdx.y*65536 + i;
    float4 v = *(const float4*)(src + i);
    __half h0,l0,h1,l1,h2,l2,h3,l3;
    split_h(v.x,h0,l0); split_h(v.y,h1,l1); split_h(v.z,h2,l2); split_h(v.w,h3,l3);
    __half2 a = __halves2half2(h0,h1), b2 = __halves2half2(h2,h3);
    __half2 c = __halves2half2(l0,l1), d = __halves2half2(l2,l3);
    *(uint32_t*)(g_W3h + o)     = *(uint32_t*)&a;
    *(uint32_t*)(g_W3h + o + 2) = *(uint32_t*)&b2;
    *(uint32_t*)(g_W3l + o)     = *(uint32_t*)&c;
    *(uint32_t*)(g_W3l + o + 2) = *(uint32_t*)&d;
}
__global__ __launch_bounds__(256) void wz_convert(const float* __restrict__ Wz)
{
    int i = (blockIdx.x*256 + threadIdx.x)*4;
    float4 v = *(const float4*)(Wz + i);
    __half2 a = __floats2half2_rn(v.x, v.y);
    __half2 b = __floats2half2_rn(v.z, v.w);
    *(uint32_t*)(g_Wz + i)     = *(uint32_t*)&a;
    *(uint32_t*)(g_Wz + i + 2) = *(uint32_t*)&b;
}

// ---------------- QKV projection (warp HMMA, X hi/lo x W hi/lo 3-pass) ----------------
// grid (S/128, H, B), 256 threads, 90112B dyn smem.
// smem: XH 0 (18432 = 128x144), XL 18432, WH 36864 (9216 = 64x144), WL 46080,
//       XF 55296 (fp32 staging 128x272; reused as V-transpose buffer 64x136 fp16)
#define QP_XH 0
#define QP_XL 18432
#define QP_WH 36864
#define QP_WL 46080
#define QP_XF 55296
#define SMEM_QP 90112

__global__ __launch_bounds__(256,1) void qkv_mma(
    const float* __restrict__ Xq, const float* __restrict__ Xk, const float* __restrict__ Xv)
{
    extern __shared__ char smem[];
    uint32_t sb = (uint32_t)__cvta_generic_to_shared(smem);
    int tid = threadIdx.x, wid = tid >> 5, lane = tid & 31;
    int s0 = blockIdx.x*128, h = blockIdx.y, b = blockIdx.z;
    size_t bh = (size_t)b*Hc + h;
    int tq = lane & 3;
    int row0 = 16*wid + (lane >> 2);

    const float inv4 = 0.35355339059327373f;
    const float l2e  = 1.4426950408889634f;
    const float* Xp[3] = {Xq, Xk, Xv};
    const float scl[3] = {inv4*l2e, inv4, 1.0f};

    for (int t = 0; t < 3; t++) {
        // --- stage X fp32 + W fp16 hi/lo ---
        const float* X = Xp[t];
        for (int i = tid; i < 2048; i += 256) {
            int r = i >> 4, c = i & 15;
            cpasync16(sb + QP_XF + r*272 + c*16,
                      (const float4*)(X + ((size_t)(b*Sc + s0 + r))*Dc + h*64) + c);
        }
        int toff = t*65536 + h*4096;
        for (int i = tid; i < 512; i += 256) {
            int r = i >> 3, c = i & 7;
            cpasync16(sb + QP_WH + r*144 + c*16, (const float4*)(g_W3h + toff + r*64) + c);
            cpasync16(sb + QP_WL + r*144 + c*16, (const float4*)(g_W3l + toff + r*64) + c);
        }
        CP_COMMIT(); CP_WAIT0();
        __syncthreads();

        // --- convert X to fp16 hi/lo in padded layout ---
        const float* xf = (const float*)(smem + QP_XF);
        for (int p = tid; p < 4096; p += 256) {
            int r = p >> 5, dp = p & 31;
            float f0 = xf[r*68 + 2*dp], f1 = xf[r*68 + 2*dp + 1];
            __half h0,l0,h1,l1; split_h(f0,h0,l0); split_h(f1,h1,l1);
            __half2 hh = __halves2half2(h0,h1), ll = __halves2half2(l0,l1);
            *(uint32_t*)(smem + QP_XH + r*144 + 4*dp) = *(uint32_t*)&hh;
            *(uint32_t*)(smem + QP_XL + r*144 + 4*dp) = *(uint32_t*)&ll;
        }
        __syncthreads();

        // --- A fragments ---
        uint32_t xh[4][4], xl[4][4];
        #pragma unroll
        for (int ks = 0; ks < 4; ks++) {
            uint32_t aaddr = sb + QP_XH + (16*wid + (lane & 15))*144 + ks*32 + ((lane >> 4) << 4);
            ldm4(aaddr, xh[ks]);
            ldm4(aaddr + (QP_XL - QP_XH), xl[ks]);
        }

        // --- 3-pass MMA: Y = Xh*Wh + Xl*Wh + Xh*Wl ---
        float s[32];
        #pragma unroll
        for (int i = 0; i < 32; i++) s[i] = 0.f;
        #pragma unroll
        for (int ks = 0; ks < 4; ks++) {
            #pragma unroll
            for (int nb2 = 0; nb2 < 4; nb2++) {
                uint32_t baddr = sb + QP_WH + (nb2*16 + (lane & 7) + ((lane >> 4) << 3))*144
                               + ks*32 + (((lane >> 3) & 1) << 4);
                uint32_t wh4[4], wl4[4];
                ldm4(baddr, wh4);
                ldm4(baddr + (QP_WL - QP_WH), wl4);
                mma16816h(s + 8*nb2,     xh[ks], wh4[0], wh4[1]);
                mma16816h(s + 8*nb2 + 4, xh[ks], wh4[2], wh4[3]);
                mma16816h(s + 8*nb2,     xl[ks], wh4[0], wh4[1]);
                mma16816h(s + 8*nb2 + 4, xl[ks], wh4[2], wh4[3]);
                mma16816h(s + 8*nb2,     xh[ks], wl4[0], wl4[1]);
                mma16816h(s + 8*nb2 + 4, xh[ks], wl4[2], wl4[3]);
            }
        }

        // --- epilogue ---
        if (t < 2) {
            __half* O = (t == 0 ? g_Q : g_K) + (bh*Sc + s0 + row0)*64;
            float sc = scl[t];
            #pragma unroll
            for (int nb = 0; nb < 8; nb++) {
                int col = nb*8 + 2*tq;
                __half2 a = __floats2half2_rn(s[4*nb+0]*sc, s[4*nb+1]*sc);
                __half2 c = __floats2half2_rn(s[4*nb+2]*sc, s[4*nb+3]*sc);
                *(uint32_t*)(O + col)          = *(uint32_t*)&a;
                *(uint32_t*)(O + 8*64 + col)   = *(uint32_t*)&c;
            }
        } else {
            // V: transpose through smem (reuse XF area), coalesced V^T store
            __half* vb = (__half*)(smem + QP_XF);   // [64 e][136 s]
            #pragma unroll
            for (int nb = 0; nb < 8; nb++) {
                int col = nb*8 + 2*tq;
                vb[col*136 + row0]           = __float2half_rn(s[4*nb+0]);
                vb[(col+1)*136 + row0]       = __float2half_rn(s[4*nb+1]);
                vb[col*136 + row0 + 8]       = __float2half_rn(s[4*nb+2]);
                vb[(col+1)*136 + row0 + 8]   = __float2half_rn(s[4*nb+3]);
            }
            __syncthreads();
            __half* Ov = g_Vt + bh*(size_t)64*Sc;
            for (int u = tid; u < 4096; u += 256) {
                int e = u >> 6, sc2 = u & 63;
                uint32_t v = *(uint32_t*)&vb[e*136 + 2*sc2];
                *(uint32_t*)(Ov + (size_t)e*Sc + s0 + 2*sc2) = v;
            }
        }
        __syncthreads();   // all reads of this iter's buffers done before next staging
    }
}

// ---------------- flash attention (fp16 HMMA, single-pass QK, 64-key tiles) -----------
// grid (S/128, H, B), 256 threads (8 warps x 16 q-rows), 36KB dyn smem.
// Buffer: K +0 (9216 = 64x144), V +9216 (9216). BUF_SZ 18432, two buffers.
// Prologue stages Q (128x144 = 18432) at sb, read into regs, then overwritten.
#define BUF_SZ  18432
#define SMEM_FL 36864

__device__ __forceinline__ void stage_k_async(uint32_t dst, const float4* gsrc, int tid) {
    for (int i = tid; i < 512; i += 256) {
        int r = i >> 3, c = i & 7;
        cpasync16(dst + r*144 + c*16, gsrc + i);
    }
}
__device__ __forceinline__ void stage_q_async(uint32_t dst, const float4* gsrc, int tid) {
    for (int i = tid; i < 1024; i += 256) {
        int r = i >> 3, c = i & 7;
        cpasync16(dst + r*144 + c*16, gsrc + i);
    }
}
__device__ __forceinline__ void stage_v_async(uint32_t dst, const float4* gv, int kb, int tid) {
    for (int i = tid; i < 512; i += 256) {
        int e = i >> 3, c = i & 7;
        cpasync16(dst + e*144 + c*16, gv + e*256 + kb*8 + c);
    }
}
__device__ __forceinline__ void issue_tile(uint32_t buf, size_t bh, int kb,
                                           const float4* gv, int tid) {
    const float4* kh = (const float4*)g_K + ((bh*Sc + (size_t)kb*64) << 3);
    stage_k_async(buf,        kh, tid);
    stage_v_async(buf + 9216, gv, kb, tid);
    CP_COMMIT();
}

__global__ __launch_bounds__(256,2) void flash_attn()
{
    extern __shared__ char smem[];
    uint32_t sb = (uint32_t)__cvta_generic_to_shared(smem);
    int tid = threadIdx.x, wid = tid >> 5, lane = tid & 31;
    int q0 = blockIdx.x*128, h = blockIdx.y, b = blockIdx.z;
    size_t bh = (size_t)b*Hc + h;
    int t = lane & 3;
    int row0 = 16*wid + (lane >> 2);   // first q row (second is row0+8)

    const float4* gv = (const float4*)(g_Vt + bh*(size_t)64*Sc);

    // --- prologue: Q into smem, load fragments, start pipeline ---
    stage_q_async(sb, (const float4*)g_Q + ((bh*Sc + q0) << 3), tid);
    CP_COMMIT(); CP_WAIT0();
    __syncthreads();

    uint32_t qh[4][4];
    #pragma unroll
    for (int ks = 0; ks < 4; ks++) {
        uint32_t aaddr = sb + (16*wid + (lane & 15))*144 + ks*32 + ((lane >> 4) << 4);
        ldm4(aaddr, qh[ks]);
    }
    __syncthreads();   // Q reads done before overwrite

    issue_tile(sb,          bh, 0, gv, tid);
    issue_tile(sb + BUF_SZ, bh, 1, gv, tid);

    float z[32];
    #pragma unroll
    for (int i = 0; i < 32; i++) z[i] = 0.f;
    float rs0 = 0.f, rs1 = 0.f;
    __half* gS0 = g_S + (bh*Sc + q0 + row0)*Sc;
    __half* gS1 = gS0 + (size_t)8*Sc;

    for (int kb = 0; kb < Sc/64; kb++) {
        if (kb < Sc/64 - 1) { CP_WAIT1(); } else { CP_WAIT0(); }
        __syncthreads();
        uint32_t buf = sb + (kb & 1)*BUF_SZ;

        // ---- scores: S = Q*K  (128x64, contraction 64, single pass) ----
        float s[32];
        #pragma unroll
        for (int i = 0; i < 32; i++) s[i] = 0.f;
        #pragma unroll
        for (int ks = 0; ks < 4; ks++) {
            #pragma unroll
            for (int nb2 = 0; nb2 < 4; nb2++) {
                uint32_t baddr = buf + (nb2*16 + (lane & 7) + ((lane >> 4) << 3))*144
                               + ks*32 + (((lane >> 3) & 1) << 4);
                uint32_t bhf[4];
                ldm4(baddr, bhf);
                mma16816h(s + 8*nb2,     qh[ks], bhf[0], bhf[1]);
                mma16816h(s + 8*nb2 + 4, qh[ks], bhf[2], bhf[3]);
            }
        }

        // ---- fused epilogue + fp16 PV, per 16-key chunk m (C-frag == A-frag) ----
        #pragma unroll
        for (int m = 0; m < 4; m++) {
            float ea0 = exp2f(s[8*m+0]), ea1 = exp2f(s[8*m+1]);
            float ea2 = exp2f(s[8*m+2]), ea3 = exp2f(s[8*m+3]);
            float eb0 = exp2f(s[8*m+4]), eb1 = exp2f(s[8*m+5]);
            float eb2 = exp2f(s[8*m+6]), eb3 = exp2f(s[8*m+7]);
            rs0 += ea0 + ea1 + eb0 + eb1;
            rs1 += ea2 + ea3 + eb2 + eb3;
            uint32_t ah[4];
            __half2 p0 = __floats2half2_rn(ea0, ea1);
            __half2 p1 = __floats2half2_rn(ea2, ea3);
            __half2 p2 = __floats2half2_rn(eb0, eb1);
            __half2 p3 = __floats2half2_rn(eb2, eb3);
            ah[0] = *(uint32_t*)&p0; ah[1] = *(uint32_t*)&p1;
            ah[2] = *(uint32_t*)&p2; ah[3] = *(uint32_t*)&p3;
            int col = kb*64 + 16*m + 2*t;
            *(__half2*)(gS0 + col)     = p0;
            *(__half2*)(gS1 + col)     = p1;
            *(__half2*)(gS0 + col + 8) = p2;
            *(__half2*)(gS1 + col + 8) = p3;

            #pragma unroll
            for (int nb2 = 0; nb2 < 4; nb2++) {
                uint32_t vaddr = buf + 9216 + (nb2*16 + (lane & 7) + ((lane >> 4) << 3))*144
                               + m*32 + (((lane >> 3) & 1) << 4);
                uint32_t bhf[4];
                ldm4(vaddr, bhf);
                mma16816h(z + 8*nb2,     ah, bhf[0], bhf[1]);
                mma16816h(z + 8*nb2 + 4, ah, bhf[2], bhf[3]);
            }
        }
        __syncthreads();   // all warps done with this buffer
        if (kb + 2 < Sc/64)
            issue_tile(sb + (kb & 1)*BUF_SZ, bh, kb + 2, gv, tid);
    }

    // rowsum reduce within quad
    #pragma unroll
    for (int o = 1; o <= 2; o <<= 1) {
        rs0 += __shfl_xor_sync(0xffffffffu, rs0, o);
        rs1 += __shfl_xor_sync(0xffffffffu, rs1, o);
    }
    float inv0 = 1.f/rs0, inv1 = 1.f/rs1;
    __half* zh0 = g_Zh + ((size_t)b*Sc + q0 + row0)*Dc + h*64;
    __half* zl0 = g_Zl + ((size_t)b*Sc + q0 + row0)*Dc + h*64;
    #pragma unroll
    for (int nb = 0; nb < 8; nb++) {
        int col = nb*8 + 2*t;
        float f0 = z[nb*4+0]*inv0, f1 = z[nb*4+1]*inv0;
        float f2 = z[nb*4+2]*inv1, f3 = z[nb*4+3]*inv1;
        __half h0,l0,h1,l1,h2,l2,h3,l3;
        split_h(f0,h0,l0); split_h(f1,h1,l1); split_h(f2,h2,l2); split_h(f3,h3,l3);
        __half2 ph0 = __halves2half2(h0,h1), ph1 = __halves2half2(h2,h3);
        __half2 pl0 = __halves2half2(l0,l1), pl1 = __halves2half2(l2,l3);
        *(uint32_t*)(zh0 + col)        = *(uint32_t*)&ph0;
        *(uint32_t*)(zh0 + 8*Dc + col) = *(uint32_t*)&ph1;
        *(uint32_t*)(zl0 + col)        = *(uint32_t*)&pl0;
        *(uint32_t*)(zl0 + 8*Dc + col) = *(uint32_t*)&pl1;
    }
    if (t == 0) {
        g_isum[bh*Sc + q0 + row0]     = inv0;
        g_isum[bh*Sc + q0 + row0 + 8] = inv1;
    }
}

// ---------------- attn_mean: am[b,q,k] = (1/H) sum_h g_S[b,h,q,k]*isum[b,h,q] ----------------
__global__ __launch_bounds__(256) void attn_mean_kernel(float* __restrict__ am)
{
    int q = blockIdx.x, b = blockIdx.y, t = threadIdx.x;
    float a[8] = {0.f,0.f,0.f,0.f,0.f,0.f,0.f,0.f};
    #pragma unroll 1
    for (int h = 0; h < Hc; h++) {
        size_t bh = (size_t)b*Hc + h;
        float w = g_isum[bh*Sc + q];
        const float4* row = (const float4*)(g_S + (bh*Sc + q)*Sc);
        float4 v = row[t];
        const __half2* hp = (const __half2*)&v;
        #pragma unroll
        for (int j = 0; j < 4; j++) {
            float2 f = __half22float2(hp[j]);
            a[2*j]   += f.x*w;
            a[2*j+1] += f.y*w;
        }
    }
    const float invH = 1.0f/Hc;
    float4* dst = (float4*)(am + ((size_t)b*Sc + q)*Sc);
    dst[2*t]   = make_float4(a[0]*invH, a[1]*invH, a[2]*invH, a[3]*invH);
    dst[2*t+1] = make_float4(a[4]*invH, a[5]*invH, a[6]*invH, a[7]*invH);
}

// ---------------- Output projection (fp16 HMMA: Zh/Zl x W, 2 passes) ----------------
#define SM_ZH 0
#define SM_ZL 18432
#define SM_W  36864
#define SMEM_OP 55296

__device__ __forceinline__ void stage_op(char* smem, int off, const float4* gs,
                                         int base_row, int kc, int tid) {
    #pragma unroll
    for (int it = 0; it < 4; it++) {
        int i = tid + it*256;
        int r = i >> 3, c = i & 7;
        *(float4*)(smem + off + r*144 + c*16) = gs[(size_t)(base_row + r)*128 + kc*8 + c];
    }
}

__global__ __launch_bounds__(256,1) void out_proj_mma(
    const float* __restrict__ bz, float* __restrict__ out)
{
    extern __shared__ char smem[];
    uint32_t sb = (uint32_t)__cvta_generic_to_shared(smem);
    int tid = threadIdx.x, wid = tid >> 5, lane = tid & 31;
    int n0 = blockIdx.x*128, s0 = blockIdx.y*128;
    int t = lane & 3;
    int row0 = 16*wid + (lane >> 2);

    const float4* gzh = (const float4*)g_Zh;
    const float4* gzl = (const float4*)g_Zl;
    const float4* gw  = (const float4*)g_Wz;

    float s[64];
    #pragma unroll
    for (int i = 0; i < 64; i++) s[i] = 0.f;

    for (int kc = 0; kc < 16; kc++) {
        if (kc) __syncthreads();
        stage_op(smem, SM_ZH, gzh, s0, kc, tid);
        stage_op(smem, SM_ZL, gzl, s0, kc, tid);
        stage_op(smem, SM_W,  gw,  n0, kc, tid);
        __syncthreads();

        #pragma unroll
        for (int ks = 0; ks < 4; ks++) {
            uint32_t aaddr = sb + SM_ZH + (16*wid + (lane & 15))*144 + ks*32 + ((lane >> 4) << 4);
            uint32_t ah[4], al[4];
            ldm4(aaddr, ah);
            ldm4(aaddr + (SM_ZL - SM_ZH), al);
            #pragma unroll
            for (int nb2 = 0; nb2 < 8; nb2++) {
                uint32_t baddr = sb + SM_W + (nb2*16 + (lane & 7) + ((lane >> 4) << 3))*144
                               + ks*32 + (((lane >> 3) & 1) << 4);
                uint32_t bhf[4];
                ldm4(baddr, bhf);
                mma16816h(s + (2*nb2)*4,   ah, bhf[0], bhf[1]);
                mma16816h(s + (2*nb2+1)*4, ah, bhf[2], bhf[3]);
                mma16816h(s + (2*nb2)*4,   al, bhf[0], bhf[1]);
                mma16816h(s + (2*nb2+1)*4, al, bhf[2], bhf[3]);
            }
        }
    }

    float* o0 = out + (size_t)(s0 + row0)*Dc + n0;
    float* o1 = o0 + (size_t)8*Dc;
    #pragma unroll
    for (int nb = 0; nb < 16; nb++) {
        int col = nb*8 + 2*t;
        float b0 = bz[n0 + col], b1 = bz[n0 + col + 1];
        *(float2*)(o0 + col) = make_float2(s[nb*4+0] + b0, s[nb*4+1] + b1);
        *(float2*)(o1 + col) = make_float2(s[nb*4+2] + b0, s[nb*4+3] + b1);
    }
}

extern "C" void kernel_launch(void* const* d_in, const int* in_sizes, int n_in,
                              void* d_out, int out_size)
{
    const float* Xq = (const float*)d_in[0];
    const float* Xk = (const float*)d_in[1];
    const float* Xv = (const float*)d_in[2];
    const float* Wq = (const float*)d_in[3];
    const float* Wk = (const float*)d_in[4];
    const float* Wv = (const float*)d_in[5];
    const float* Wz = (const float*)d_in[6];
    const float* bz = (const float*)d_in[7];
    float* out  = (float*)d_out;
    float* attn = out + (size_t)Bc*Sc*Dc;   // out first, then attn_mean

    cudaFuncSetAttribute((const void*)qkv_mma,
                         cudaFuncAttributeMaxDynamicSharedMemorySize, SMEM_QP);
    cudaFuncSetAttribute((const void*)flash_attn,
                         cudaFuncAttributeMaxDynamicSharedMemorySize, SMEM_FL);
    cudaFuncSetAttribute((const void*)out_proj_mma,
                         cudaFuncAttributeMaxDynamicSharedMemorySize, SMEM_OP);

    w3_convert<<<dim3(64, 3), 256>>>(Wq, Wk, Wv);
    wz_convert<<<Dc*Dc/1024, 256>>>(Wz);
    qkv_mma<<<dim3(Sc/128, Hc, Bc), 256, SMEM_QP>>>(Xq, Xk, Xv);
    flash_attn<<<dim3(Sc/128, Hc, Bc), 256, SMEM_FL>>>();
    attn_mean_kernel<<<dim3(Sc, Bc), 256>>>(attn);
    out_proj_mma<<<dim3(Dc/128, (Bc*Sc)/128), 256, SMEM_OP>>>(bz, out);
}

// round 12
// speedup vs baseline: 10.1638x; 1.0798x over previous
#include <cuda_runtime.h>
#include <cuda_bf16.h>
#include <cuda_fp16.h>
#include <cstdint>

#define Bc 2
#define Sc 2048
#define Dc 1024
#define Hc 16
#define HDc 64

// ---------------- scratch globals (allocation-free) ----------------
__device__ __half g_Q [Bc*Hc*Sc*HDc];           // Q fp16 (scaled by inv4*log2e)
__device__ __half g_K [Bc*Hc*Sc*HDc];           // K fp16 (scaled by inv4)
__device__ __half g_Vt[Bc*Hc*Sc*HDc];           // V^T [b,h,e,s], fp16
__device__ __half g_Z [Bc*Sc*Dc];               // Z fp16 ([s][k])
__device__ __half g_Wz[Dc*Dc];                  // Wz fp16 ([n][k])
__device__ __half g_W3[3*Hc*HDc*HDc];           // Wq/Wk/Wv fp16 (concat)
__device__ __half g_S[134217728];               // [b,h,q,k] unnormalized exp(score)
__device__ float g_isum[Bc*Hc*Sc];              // 1/rowsum

// ---------------- warp MMA helpers (base ISA: valid on sm_103 plain) ----------------
__device__ __forceinline__ void ldm4(uint32_t addr, uint32_t* r) {
    asm volatile("ldmatrix.sync.aligned.m8n8.x4.shared.b16 {%0,%1,%2,%3}, [%4];"
                 : "=r"(r[0]), "=r"(r[1]), "=r"(r[2]), "=r"(r[3]) : "r"(addr));
}
__device__ __forceinline__ void mma16816h(float* c, const uint32_t* a, uint32_t b0, uint32_t b1) {
    asm volatile("mma.sync.aligned.m16n8k16.row.col.f32.f16.f16.f32 "
                 "{%0,%1,%2,%3}, {%4,%5,%6,%7}, {%8,%9}, {%0,%1,%2,%3};"
                 : "+f"(c[0]), "+f"(c[1]), "+f"(c[2]), "+f"(c[3])
                 : "r"(a[0]), "r"(a[1]), "r"(a[2]), "r"(a[3]), "r"(b0), "r"(b1));
}
__device__ __forceinline__ void split_h(float x, __half& hi, __half& lo) {
    hi = __float2half_rn(x);
    lo = __float2half_rn(x - __half2float(hi));
}
__device__ __forceinline__ void cpasync16(uint32_t daddr, const void* gptr) {
    asm volatile("cp.async.cg.shared.global [%0], [%1], 16;" :: "r"(daddr), "l"(gptr));
}
#define CP_COMMIT() asm volatile("cp.async.commit_group;" ::: "memory")
#define CP_WAIT1()  asm volatile("cp.async.wait_group 1;" ::: "memory")
#define CP_WAIT0()  asm volatile("cp.async.wait_group 0;" ::: "memory")

// ---------------- W converts (single fp16) ----------------
__global__ __launch_bounds__(256) void w3_convert(
    const float* __restrict__ Wq, const float* __restrict__ Wk, const float* __restrict__ Wv)
{
    const float* src = (blockIdx.y == 0) ? Wq : (blockIdx.y == 1 ? Wk : Wv);
    int i = (blockIdx.x*256 + threadIdx.x)*4;          // over 65536 elems
    int o = blockIdx.y*65536 + i;
    float4 v = *(const float4*)(src + i);
    __half2 a = __floats2half2_rn(v.x, v.y);
    __half2 b = __floats2half2_rn(v.z, v.w);
    *(uint32_t*)(g_W3 + o)     = *(uint32_t*)&a;
    *(uint32_t*)(g_W3 + o + 2) = *(uint32_t*)&b;
}
__global__ __launch_bounds__(256) void wz_convert(const float* __restrict__ Wz)
{
    int i = (blockIdx.x*256 + threadIdx.x)*4;
    float4 v = *(const float4*)(Wz + i);
    __half2 a = __floats2half2_rn(v.x, v.y);
    __half2 b = __floats2half2_rn(v.z, v.w);
    *(uint32_t*)(g_Wz + i)     = *(uint32_t*)&a;
    *(uint32_t*)(g_Wz + i + 2) = *(uint32_t*)&b;
}

// ---------------- QKV projection (warp HMMA, X hi/lo x W, 2-pass) ----------------
// grid (S/128, H, B), 256 threads, 80896B dyn smem.
// smem: XH 0 (18432 = 128x144), XL 18432, WH 36864 (9216 = 64x144),
//       XF 46080 (fp32 staging 128x272 = 34816; reused as V-transpose 64x136 fp16)
#define QP_XH 0
#define QP_XL 18432
#define QP_WH 36864
#define QP_XF 46080
#define SMEM_QP 80896

__global__ __launch_bounds__(256,1) void qkv_mma(
    const float* __restrict__ Xq, const float* __restrict__ Xk, const float* __restrict__ Xv)
{
    extern __shared__ char smem[];
    uint32_t sb = (uint32_t)__cvta_generic_to_shared(smem);
    int tid = threadIdx.x, wid = tid >> 5, lane = tid & 31;
    int s0 = blockIdx.x*128, h = blockIdx.y, b = blockIdx.z;
    size_t bh = (size_t)b*Hc + h;
    int tq = lane & 3;
    int row0 = 16*wid + (lane >> 2);

    const float inv4 = 0.35355339059327373f;
    const float l2e  = 1.4426950408889634f;
    const float* Xp[3] = {Xq, Xk, Xv};
    const float scl[3] = {inv4*l2e, inv4, 1.0f};

    for (int t = 0; t < 3; t++) {
        // --- stage X fp32 + W fp16 ---
        const float* X = Xp[t];
        for (int i = tid; i < 2048; i += 256) {
            int r = i >> 4, c = i & 15;
            cpasync16(sb + QP_XF + r*272 + c*16,
                      (const float4*)(X + ((size_t)(b*Sc + s0 + r))*Dc + h*64) + c);
        }
        int toff = t*65536 + h*4096;
        for (int i = tid; i < 512; i += 256) {
            int r = i >> 3, c = i & 7;
            cpasync16(sb + QP_WH + r*144 + c*16, (const float4*)(g_W3 + toff + r*64) + c);
        }
        CP_COMMIT(); CP_WAIT0();
        __syncthreads();

        // --- convert X to fp16 hi/lo in padded layout ---
        const float* xf = (const float*)(smem + QP_XF);
        for (int p = tid; p < 4096; p += 256) {
            int r = p >> 5, dp = p & 31;
            float f0 = xf[r*68 + 2*dp], f1 = xf[r*68 + 2*dp + 1];
            __half h0,l0,h1,l1; split_h(f0,h0,l0); split_h(f1,h1,l1);
            __half2 hh = __halves2half2(h0,h1), ll = __halves2half2(l0,l1);
            *(uint32_t*)(smem + QP_XH + r*144 + 4*dp) = *(uint32_t*)&hh;
            *(uint32_t*)(smem + QP_XL + r*144 + 4*dp) = *(uint32_t*)&ll;
        }
        __syncthreads();

        // --- A fragments ---
        uint32_t xh[4][4], xl[4][4];
        #pragma unroll
        for (int ks = 0; ks < 4; ks++) {
            uint32_t aaddr = sb + QP_XH + (16*wid + (lane & 15))*144 + ks*32 + ((lane >> 4) << 4);
            ldm4(aaddr, xh[ks]);
            ldm4(aaddr + (QP_XL - QP_XH), xl[ks]);
        }

        // --- 2-pass MMA: Y = Xh*W + Xl*W ---
        float s[32];
        #pragma unroll
        for (int i = 0; i < 32; i++) s[i] = 0.f;
        #pragma unroll
        for (int ks = 0; ks < 4; ks++) {
            #pragma unroll
            for (int nb2 = 0; nb2 < 4; nb2++) {
                uint32_t baddr = sb + QP_WH + (nb2*16 + (lane & 7) + ((lane >> 4) << 3))*144
                               + ks*32 + (((lane >> 3) & 1) << 4);
                uint32_t wh4[4];
                ldm4(baddr, wh4);
                mma16816h(s + 8*nb2,     xh[ks], wh4[0], wh4[1]);
                mma16816h(s + 8*nb2 + 4, xh[ks], wh4[2], wh4[3]);
                mma16816h(s + 8*nb2,     xl[ks], wh4[0], wh4[1]);
                mma16816h(s + 8*nb2 + 4, xl[ks], wh4[2], wh4[3]);
            }
        }

        // --- epilogue ---
        if (t < 2) {
            __half* O = (t == 0 ? g_Q : g_K) + (bh*Sc + s0 + row0)*64;
            float sc = scl[t];
            #pragma unroll
            for (int nb = 0; nb < 8; nb++) {
                int col = nb*8 + 2*tq;
                __half2 a = __floats2half2_rn(s[4*nb+0]*sc, s[4*nb+1]*sc);
                __half2 c = __floats2half2_rn(s[4*nb+2]*sc, s[4*nb+3]*sc);
                *(uint32_t*)(O + col)          = *(uint32_t*)&a;
                *(uint32_t*)(O + 8*64 + col)   = *(uint32_t*)&c;
            }
        } else {
            // V: transpose through smem (reuse XF area), coalesced V^T store
            __half* vb = (__half*)(smem + QP_XF);   // [64 e][136 s]
            #pragma unroll
            for (int nb = 0; nb < 8; nb++) {
                int col = nb*8 + 2*tq;
                vb[col*136 + row0]           = __float2half_rn(s[4*nb+0]);
                vb[(col+1)*136 + row0]       = __float2half_rn(s[4*nb+1]);
                vb[col*136 + row0 + 8]       = __float2half_rn(s[4*nb+2]);
                vb[(col+1)*136 + row0 + 8]   = __float2half_rn(s[4*nb+3]);
            }
            __syncthreads();
            __half* Ov = g_Vt + bh*(size_t)64*Sc;
            for (int u = tid; u < 4096; u += 256) {
                int e = u >> 6, sc2 = u & 63;
                uint32_t v = *(uint32_t*)&vb[e*136 + 2*sc2];
                *(uint32_t*)(Ov + (size_t)e*Sc + s0 + 2*sc2) = v;
            }
        }
        __syncthreads();   // all reads of this iter's buffers done before next staging
    }
}

// ---------------- flash attention (fp16 HMMA, single-pass QK, 64-key tiles) -----------
// grid (S/128, H, B), 256 threads (8 warps x 16 q-rows), 36KB dyn smem.
#define BUF_SZ  18432
#define SMEM_FL 36864

__device__ __forceinline__ void stage_k_async(uint32_t dst, const float4* gsrc, int tid) {
    for (int i = tid; i < 512; i += 256) {
        int r = i >> 3, c = i & 7;
        cpasync16(dst + r*144 + c*16, gsrc + i);
    }
}
__device__ __forceinline__ void stage_q_async(uint32_t dst, const float4* gsrc, int tid) {
    for (int i = tid; i < 1024; i += 256) {
        int r = i >> 3, c = i & 7;
        cpasync16(dst + r*144 + c*16, gsrc + i);
    }
}
__device__ __forceinline__ void stage_v_async(uint32_t dst, const float4* gv, int kb, int tid) {
    for (int i = tid; i < 512; i += 256) {
        int e = i >> 3, c = i & 7;
        cpasync16(dst + e*144 + c*16, gv + e*256 + kb*8 + c);
    }
}
__device__ __forceinline__ void issue_tile(uint32_t buf, size_t bh, int kb,
                                           const float4* gv, int tid) {
    const float4* kh = (const float4*)g_K + ((bh*Sc + (size_t)kb*64) << 3);
    stage_k_async(buf,        kh, tid);
    stage_v_async(buf + 9216, gv, kb, tid);
    CP_COMMIT();
}

__global__ __launch_bounds__(256,2) void flash_attn()
{
    extern __shared__ char smem[];
    uint32_t sb = (uint32_t)__cvta_generic_to_shared(smem);
    int tid = threadIdx.x, wid = tid >> 5, lane = tid & 31;
    int q0 = blockIdx.x*128, h = blockIdx.y, b = blockIdx.z;
    size_t bh = (size_t)b*Hc + h;
    int t = lane & 3;
    int row0 = 16*wid + (lane >> 2);   // first q row (second is row0+8)

    const float4* gv = (const float4*)(g_Vt + bh*(size_t)64*Sc);

    // --- prologue: Q into smem, load fragments, start pipeline ---
    stage_q_async(sb, (const float4*)g_Q + ((bh*Sc + q0) << 3), tid);
    CP_COMMIT(); CP_WAIT0();
    __syncthreads();

    uint32_t qh[4][4];
    #pragma unroll
    for (int ks = 0; ks < 4; ks++) {
        uint32_t aaddr = sb + (16*wid + (lane & 15))*144 + ks*32 + ((lane >> 4) << 4);
        ldm4(aaddr, qh[ks]);
    }
    __syncthreads();   // Q reads done before overwrite

    issue_tile(sb,          bh, 0, gv, tid);
    issue_tile(sb + BUF_SZ, bh, 1, gv, tid);

    float z[32];
    #pragma unroll
    for (int i = 0; i < 32; i++) z[i] = 0.f;
    float rs0 = 0.f, rs1 = 0.f;
    __half* gS0 = g_S + (bh*Sc + q0 + row0)*Sc;
    __half* gS1 = gS0 + (size_t)8*Sc;

    for (int kb = 0; kb < Sc/64; kb++) {
        if (kb < Sc/64 - 1) { CP_WAIT1(); } else { CP_WAIT0(); }
        __syncthreads();
        uint32_t buf = sb + (kb & 1)*BUF_SZ;

        // ---- scores: S = Q*K  (128x64, contraction 64, single pass) ----
        float s[32];
        #pragma unroll
        for (int i = 0; i < 32; i++) s[i] = 0.f;
        #pragma unroll
        for (int ks = 0; ks < 4; ks++) {
            #pragma unroll
            for (int nb2 = 0; nb2 < 4; nb2++) {
                uint32_t baddr = buf + (nb2*16 + (lane & 7) + ((lane >> 4) << 3))*144
                               + ks*32 + (((lane >> 3) & 1) << 4);
                uint32_t bhf[4];
                ldm4(baddr, bhf);
                mma16816h(s + 8*nb2,     qh[ks], bhf[0], bhf[1]);
                mma16816h(s + 8*nb2 + 4, qh[ks], bhf[2], bhf[3]);
            }
        }

        // ---- fused epilogue + fp16 PV, per 16-key chunk m (C-frag == A-frag) ----
        #pragma unroll
        for (int m = 0; m < 4; m++) {
            float ea0 = exp2f(s[8*m+0]), ea1 = exp2f(s[8*m+1]);
            float ea2 = exp2f(s[8*m+2]), ea3 = exp2f(s[8*m+3]);
            float eb0 = exp2f(s[8*m+4]), eb1 = exp2f(s[8*m+5]);
            float eb2 = exp2f(s[8*m+6]), eb3 = exp2f(s[8*m+7]);
            rs0 += ea0 + ea1 + eb0 + eb1;
            rs1 += ea2 + ea3 + eb2 + eb3;
            uint32_t ah[4];
            __half2 p0 = __floats2half2_rn(ea0, ea1);
            __half2 p1 = __floats2half2_rn(ea2, ea3);
            __half2 p2 = __floats2half2_rn(eb0, eb1);
            __half2 p3 = __floats2half2_rn(eb2, eb3);
            ah[0] = *(uint32_t*)&p0; ah[1] = *(uint32_t*)&p1;
            ah[2] = *(uint32_t*)&p2; ah[3] = *(uint32_t*)&p3;
            int col = kb*64 + 16*m + 2*t;
            *(__half2*)(gS0 + col)     = p0;
            *(__half2*)(gS1 + col)     = p1;
            *(__half2*)(gS0 + col + 8) = p2;
            *(__half2*)(gS1 + col + 8) = p3;

            #pragma unroll
            for (int nb2 = 0; nb2 < 4; nb2++) {
                uint32_t vaddr = buf + 9216 + (nb2*16 + (lane & 7) + ((lane >> 4) << 3))*144
                               + m*32 + (((lane >> 3) & 1) << 4);
                uint32_t bhf[4];
                ldm4(vaddr, bhf);
                mma16816h(z + 8*nb2,     ah, bhf[0], bhf[1]);
                mma16816h(z + 8*nb2 + 4, ah, bhf[2], bhf[3]);
            }
        }
        __syncthreads();   // all warps done with this buffer
        if (kb + 2 < Sc/64)
            issue_tile(sb + (kb & 1)*BUF_SZ, bh, kb + 2, gv, tid);
    }

    // rowsum reduce within quad
    #pragma unroll
    for (int o = 1; o <= 2; o <<= 1) {
        rs0 += __shfl_xor_sync(0xffffffffu, rs0, o);
        rs1 += __shfl_xor_sync(0xffffffffu, rs1, o);
    }
    float inv0 = 1.f/rs0, inv1 = 1.f/rs1;
    __half* z0 = g_Z + ((size_t)b*Sc + q0 + row0)*Dc + h*64;
    #pragma unroll
    for (int nb = 0; nb < 8; nb++) {
        int col = nb*8 + 2*t;
        __half2 a = __floats2half2_rn(z[nb*4+0]*inv0, z[nb*4+1]*inv0);
        __half2 c = __floats2half2_rn(z[nb*4+2]*inv1, z[nb*4+3]*inv1);
        *(uint32_t*)(z0 + col)        = *(uint32_t*)&a;
        *(uint32_t*)(z0 + 8*Dc + col) = *(uint32_t*)&c;
    }
    if (t == 0) {
        g_isum[bh*Sc + q0 + row0]     = inv0;
        g_isum[bh*Sc + q0 + row0 + 8] = inv1;
    }
}

// ---------------- attn_mean: am[b,q,k] = (1/H) sum_h g_S[b,h,q,k]*isum[b,h,q] ----------------
__global__ __launch_bounds__(256) void attn_mean_kernel(float* __restrict__ am)
{
    int q = blockIdx.x, b = blockIdx.y, t = threadIdx.x;
    float a[8] = {0.f,0.f,0.f,0.f,0.f,0.f,0.f,0.f};
    #pragma unroll 1
    for (int h = 0; h < Hc; h++) {
        size_t bh = (size_t)b*Hc + h;
        float w = g_isum[bh*Sc + q];
        const float4* row = (const float4*)(g_S + (bh*Sc + q)*Sc);
        float4 v = row[t];
        const __half2* hp = (const __half2*)&v;
        #pragma unroll
        for (int j = 0; j < 4; j++) {
            float2 f = __half22float2(hp[j]);
            a[2*j]   += f.x*w;
            a[2*j+1] += f.y*w;
        }
    }
    const float invH = 1.0f/Hc;
    float4* dst = (float4*)(am + ((size_t)b*Sc + q)*Sc);
    dst[2*t]   = make_float4(a[0]*invH, a[1]*invH, a[2]*invH, a[3]*invH);
    dst[2*t+1] = make_float4(a[4]*invH, a[5]*invH, a[6]*invH, a[7]*invH);
}

// ---------------- Output projection (fp16 HMMA, single pass Z x W) ----------------
#define SM_Z 0
#define SM_W 18432
#define SMEM_OP 36864

__device__ __forceinline__ void stage_op(char* smem, int off, const float4* gs,
                                         int base_row, int kc, int tid) {
    #pragma unroll
    for (int it = 0; it < 4; it++) {
        int i = tid + it*256;
        int r = i >> 3, c = i & 7;
        *(float4*)(smem + off + r*144 + c*16) = gs[(size_t)(base_row + r)*128 + kc*8 + c];
    }
}

__global__ __launch_bounds__(256,1) void out_proj_mma(
    const float* __restrict__ bz, float* __restrict__ out)
{
    extern __shared__ char smem[];
    uint32_t sb = (uint32_t)__cvta_generic_to_shared(smem);
    int tid = threadIdx.x, wid = tid >> 5, lane = tid & 31;
    int n0 = blockIdx.x*128, s0 = blockIdx.y*128;
    int t = lane & 3;
    int row0 = 16*wid + (lane >> 2);

    const float4* gz = (const float4*)g_Z;
    const float4* gw = (const float4*)g_Wz;

    float s[64];
    #pragma unroll
    for (int i = 0; i < 64; i++) s[i] = 0.f;

    for (int kc = 0; kc < 16; kc++) {
        if (kc) __syncthreads();
        stage_op(smem, SM_Z, gz, s0, kc, tid);
        stage_op(smem, SM_W, gw, n0, kc, tid);
        __syncthreads();

        #pragma unroll
        for (int ks = 0; ks < 4; ks++) {
            uint32_t aaddr = sb + SM_Z + (16*wid + (lane & 15))*144 + ks*32 + ((lane >> 4) << 4);
            uint32_t ah[4];
            ldm4(aaddr, ah);
            #pragma unroll
            for (int nb2 = 0; nb2 < 8; nb2++) {
                uint32_t baddr = sb + SM_W + (nb2*16 + (lane & 7) + ((lane >> 4) << 3))*144
                               + ks*32 + (((lane >> 3) & 1) << 4);
                uint32_t bhf[4];
                ldm4(baddr, bhf);
                mma16816h(s + (2*nb2)*4,   ah, bhf[0], bhf[1]);
                mma16816h(s + (2*nb2+1)*4, ah, bhf[2], bhf[3]);
            }
        }
    }

    float* o0 = out + (size_t)(s0 + row0)*Dc + n0;
    float* o1 = o0 + (size_t)8*Dc;
    #pragma unroll
    for (int nb = 0; nb < 16; nb++) {
        int col = nb*8 + 2*t;
        float b0 = bz[n0 + col], b1 = bz[n0 + col + 1];
        *(float2*)(o0 + col) = make_float2(s[nb*4+0] + b0, s[nb*4+1] + b1);
        *(float2*)(o1 + col) = make_float2(s[nb*4+2] + b0, s[nb*4+3] + b1);
    }
}

extern "C" void kernel_launch(void* const* d_in, const int* in_sizes, int n_in,
                              void* d_out, int out_size)
{
    const float* Xq = (const float*)d_in[0];
    const float* Xk = (const float*)d_in[1];
    const float* Xv = (const float*)d_in[2];
    const float* Wq = (const float*)d_in[3];
    const float* Wk = (const float*)d_in[4];
    const float* Wv = (const float*)d_in[5];
    const float* Wz = (const float*)d_in[6];
    const float* bz = (const float*)d_in[7];
    float* out  = (float*)d_out;
    float* attn = out + (size_t)Bc*Sc*Dc;   // out first, then attn_mean

    cudaFuncSetAttribute((const void*)qkv_mma,
                         cudaFuncAttributeMaxDynamicSharedMemorySize, SMEM_QP);
    cudaFuncSetAttribute((const void*)flash_attn,
                         cudaFuncAttributeMaxDynamicSharedMemorySize, SMEM_FL);
    cudaFuncSetAttribute((const void*)out_proj_mma,
                         cudaFuncAttributeMaxDynamicSharedMemorySize, SMEM_OP);

    w3_convert<<<dim3(64, 3), 256>>>(Wq, Wk, Wv);
    wz_convert<<<Dc*Dc/1024, 256>>>(Wz);
    qkv_mma<<<dim3(Sc/128, Hc, Bc), 256, SMEM_QP>>>(Xq, Xk, Xv);
    flash_attn<<<dim3(Sc/128, Hc, Bc), 256, SMEM_FL>>>();
    attn_mean_kernel<<<dim3(Sc, Bc), 256>>>(attn);
    out_proj_mma<<<dim3(Dc/128, (Bc*Sc)/128), 256, SMEM_OP>>>(bz, out);
}

// round 13
// speedup vs baseline: 10.3193x; 1.0153x over previous
#include <cuda_runtime.h>
#include <cuda_bf16.h>
#include <cuda_fp16.h>
#include <cstdint>

#define Bc 2
#define Sc 2048
#define Dc 1024
#define Hc 16
#define HDc 64

// ---------------- scratch globals (allocation-free) ----------------
__device__ __half g_Q [Bc*Hc*Sc*HDc];           // Q fp16 (scaled by inv4*log2e)
__device__ __half g_K [Bc*Hc*Sc*HDc];           // K fp16 (scaled by inv4)
__device__ __half g_Vt[Bc*Hc*Sc*HDc];           // V^T [b,h,e,s], fp16
__device__ __half g_Z [Bc*Sc*Dc];               // Z fp16 ([s][k])
__device__ __half g_Wz[Dc*Dc];                  // Wz fp16 ([n][k])
__device__ __half g_W3[3*Hc*HDc*HDc];           // Wq/Wk/Wv fp16 (concat)
__device__ __half g_S[134217728];               // [b,h,q,k] unnormalized exp(score)
__device__ float g_isum[Bc*Hc*Sc];              // 1/rowsum

// ---------------- warp MMA helpers (base ISA: valid on sm_103 plain) ----------------
__device__ __forceinline__ void ldm4(uint32_t addr, uint32_t* r) {
    asm volatile("ldmatrix.sync.aligned.m8n8.x4.shared.b16 {%0,%1,%2,%3}, [%4];"
                 : "=r"(r[0]), "=r"(r[1]), "=r"(r[2]), "=r"(r[3]) : "r"(addr));
}
__device__ __forceinline__ void mma16816h(float* c, const uint32_t* a, uint32_t b0, uint32_t b1) {
    asm volatile("mma.sync.aligned.m16n8k16.row.col.f32.f16.f16.f32 "
                 "{%0,%1,%2,%3}, {%4,%5,%6,%7}, {%8,%9}, {%0,%1,%2,%3};"
                 : "+f"(c[0]), "+f"(c[1]), "+f"(c[2]), "+f"(c[3])
                 : "r"(a[0]), "r"(a[1]), "r"(a[2]), "r"(a[3]), "r"(b0), "r"(b1));
}
__device__ __forceinline__ void split_h(float x, __half& hi, __half& lo) {
    hi = __float2half_rn(x);
    lo = __float2half_rn(x - __half2float(hi));
}
__device__ __forceinline__ void cpasync16(uint32_t daddr, const void* gptr) {
    asm volatile("cp.async.cg.shared.global [%0], [%1], 16;" :: "r"(daddr), "l"(gptr));
}
#define CP_COMMIT() asm volatile("cp.async.commit_group;" ::: "memory")
#define CP_WAIT1()  asm volatile("cp.async.wait_group 1;" ::: "memory")
#define CP_WAIT0()  asm volatile("cp.async.wait_group 0;" ::: "memory")

// ---------------- W converts (single fp16) ----------------
__global__ __launch_bounds__(256) void w3_convert(
    const float* __restrict__ Wq, const float* __restrict__ Wk, const float* __restrict__ Wv)
{
    const float* src = (blockIdx.y == 0) ? Wq : (blockIdx.y == 1 ? Wk : Wv);
    int i = (blockIdx.x*256 + threadIdx.x)*4;          // over 65536 elems
    int o = blockIdx.y*65536 + i;
    float4 v = *(const float4*)(src + i);
    __half2 a = __floats2half2_rn(v.x, v.y);
    __half2 b = __floats2half2_rn(v.z, v.w);
    *(uint32_t*)(g_W3 + o)     = *(uint32_t*)&a;
    *(uint32_t*)(g_W3 + o + 2) = *(uint32_t*)&b;
}
__global__ __launch_bounds__(256) void wz_convert(const float* __restrict__ Wz)
{
    int i = (blockIdx.x*256 + threadIdx.x)*4;
    float4 v = *(const float4*)(Wz + i);
    __half2 a = __floats2half2_rn(v.x, v.y);
    __half2 b = __floats2half2_rn(v.z, v.w);
    *(uint32_t*)(g_Wz + i)     = *(uint32_t*)&a;
    *(uint32_t*)(g_Wz + i + 2) = *(uint32_t*)&b;
}

// ---------------- QKV projection (warp HMMA, X hi/lo x W, 2-pass) ----------------
#define QP_XH 0
#define QP_XL 18432
#define QP_WH 36864
#define QP_XF 46080
#define SMEM_QP 80896

__global__ __launch_bounds__(256,1) void qkv_mma(
    const float* __restrict__ Xq, const float* __restrict__ Xk, const float* __restrict__ Xv)
{
    extern __shared__ char smem[];
    uint32_t sb = (uint32_t)__cvta_generic_to_shared(smem);
    int tid = threadIdx.x, wid = tid >> 5, lane = tid & 31;
    int s0 = blockIdx.x*128, h = blockIdx.y, b = blockIdx.z;
    size_t bh = (size_t)b*Hc + h;
    int tq = lane & 3;
    int row0 = 16*wid + (lane >> 2);

    const float inv4 = 0.35355339059327373f;
    const float l2e  = 1.4426950408889634f;
    const float* Xp[3] = {Xq, Xk, Xv};
    const float scl[3] = {inv4*l2e, inv4, 1.0f};

    for (int t = 0; t < 3; t++) {
        const float* X = Xp[t];
        for (int i = tid; i < 2048; i += 256) {
            int r = i >> 4, c = i & 15;
            cpasync16(sb + QP_XF + r*272 + c*16,
                      (const float4*)(X + ((size_t)(b*Sc + s0 + r))*Dc + h*64) + c);
        }
        int toff = t*65536 + h*4096;
        for (int i = tid; i < 512; i += 256) {
            int r = i >> 3, c = i & 7;
            cpasync16(sb + QP_WH + r*144 + c*16, (const float4*)(g_W3 + toff + r*64) + c);
        }
        CP_COMMIT(); CP_WAIT0();
        __syncthreads();

        const float* xf = (const float*)(smem + QP_XF);
        for (int p = tid; p < 4096; p += 256) {
            int r = p >> 5, dp = p & 31;
            float f0 = xf[r*68 + 2*dp], f1 = xf[r*68 + 2*dp + 1];
            __half h0,l0,h1,l1; split_h(f0,h0,l0); split_h(f1,h1,l1);
            __half2 hh = __halves2half2(h0,h1), ll = __halves2half2(l0,l1);
            *(uint32_t*)(smem + QP_XH + r*144 + 4*dp) = *(uint32_t*)&hh;
            *(uint32_t*)(smem + QP_XL + r*144 + 4*dp) = *(uint32_t*)&ll;
        }
        __syncthreads();

        uint32_t xh[4][4], xl[4][4];
        #pragma unroll
        for (int ks = 0; ks < 4; ks++) {
            uint32_t aaddr = sb + QP_XH + (16*wid + (lane & 15))*144 + ks*32 + ((lane >> 4) << 4);
            ldm4(aaddr, xh[ks]);
            ldm4(aaddr + (QP_XL - QP_XH), xl[ks]);
        }

        float s[32];
        #pragma unroll
        for (int i = 0; i < 32; i++) s[i] = 0.f;
        #pragma unroll
        for (int ks = 0; ks < 4; ks++) {
            #pragma unroll
            for (int nb2 = 0; nb2 < 4; nb2++) {
                uint32_t baddr = sb + QP_WH + (nb2*16 + (lane & 7) + ((lane >> 4) << 3))*144
                               + ks*32 + (((lane >> 3) & 1) << 4);
                uint32_t wh4[4];
                ldm4(baddr, wh4);
                mma16816h(s + 8*nb2,     xh[ks], wh4[0], wh4[1]);
                mma16816h(s + 8*nb2 + 4, xh[ks], wh4[2], wh4[3]);
                mma16816h(s + 8*nb2,     xl[ks], wh4[0], wh4[1]);
                mma16816h(s + 8*nb2 + 4, xl[ks], wh4[2], wh4[3]);
            }
        }

        if (t < 2) {
            __half* O = (t == 0 ? g_Q : g_K) + (bh*Sc + s0 + row0)*64;
            float sc = scl[t];
            #pragma unroll
            for (int nb = 0; nb < 8; nb++) {
                int col = nb*8 + 2*tq;
                __half2 a = __floats2half2_rn(s[4*nb+0]*sc, s[4*nb+1]*sc);
                __half2 c = __floats2half2_rn(s[4*nb+2]*sc, s[4*nb+3]*sc);
                *(uint32_t*)(O + col)          = *(uint32_t*)&a;
                *(uint32_t*)(O + 8*64 + col)   = *(uint32_t*)&c;
            }
        } else {
            __half* vb = (__half*)(smem + QP_XF);   // [64 e][136 s]
            #pragma unroll
            for (int nb = 0; nb < 8; nb++) {
                int col = nb*8 + 2*tq;
                vb[col*136 + row0]           = __float2half_rn(s[4*nb+0]);
                vb[(col+1)*136 + row0]       = __float2half_rn(s[4*nb+1]);
                vb[col*136 + row0 + 8]       = __float2half_rn(s[4*nb+2]);
                vb[(col+1)*136 + row0 + 8]   = __float2half_rn(s[4*nb+3]);
            }
            __syncthreads();
            __half* Ov = g_Vt + bh*(size_t)64*Sc;
            for (int u = tid; u < 4096; u += 256) {
                int e = u >> 6, sc2 = u & 63;
                uint32_t v = *(uint32_t*)&vb[e*136 + 2*sc2];
                *(uint32_t*)(Ov + (size_t)e*Sc + s0 + 2*sc2) = v;
            }
        }
        __syncthreads();
    }
}

// ---------------- flash attention (fp16 HMMA, M=32/warp, 256-q tile) -----------
// grid (S/256, H, B), 256 threads (8 warps x 32 q-rows), 36KB dyn smem.
// Buffer: K +0 (9216 = 64x144), V +9216 (9216). BUF_SZ 18432, two buffers.
// Prologue stages Q (256x144 = 36864) across the whole region.
#define BUF_SZ  18432
#define SMEM_FL 36864

__device__ __forceinline__ void stage_k_async(uint32_t dst, const float4* gsrc, int tid) {
    for (int i = tid; i < 512; i += 256) {
        int r = i >> 3, c = i & 7;
        cpasync16(dst + r*144 + c*16, gsrc + i);
    }
}
__device__ __forceinline__ void stage_v_async(uint32_t dst, const float4* gv, int kb, int tid) {
    for (int i = tid; i < 512; i += 256) {
        int e = i >> 3, c = i & 7;
        cpasync16(dst + e*144 + c*16, gv + e*256 + kb*8 + c);
    }
}
__device__ __forceinline__ void issue_tile(uint32_t buf, size_t bh, int kb,
                                           const float4* gv, int tid) {
    const float4* kh = (const float4*)g_K + ((bh*Sc + (size_t)kb*64) << 3);
    stage_k_async(buf,        kh, tid);
    stage_v_async(buf + 9216, gv, kb, tid);
    CP_COMMIT();
}

__global__ __launch_bounds__(256,1) void flash_attn()
{
    extern __shared__ char smem[];
    uint32_t sb = (uint32_t)__cvta_generic_to_shared(smem);
    int tid = threadIdx.x, wid = tid >> 5, lane = tid & 31;
    int q0 = blockIdx.x*256, h = blockIdx.y, b = blockIdx.z;
    size_t bh = (size_t)b*Hc + h;
    int t = lane & 3;
    int row0 = 32*wid + (lane >> 2);   // rows row0, +8, +16, +24

    const float4* gv = (const float4*)(g_Vt + bh*(size_t)64*Sc);

    // --- prologue: Q (256 rows) into full smem region, load fragments ---
    {
        const float4* gq = (const float4*)g_Q + ((bh*Sc + q0) << 3);
        for (int i = tid; i < 2048; i += 256) {
            int r = i >> 3, c = i & 7;
            cpasync16(sb + r*144 + c*16, gq + i);
        }
    }
    CP_COMMIT(); CP_WAIT0();
    __syncthreads();

    uint32_t qf[2][4][4];
    #pragma unroll
    for (int tl = 0; tl < 2; tl++)
        #pragma unroll
        for (int ks = 0; ks < 4; ks++) {
            uint32_t aaddr = sb + (32*wid + tl*16 + (lane & 15))*144 + ks*32 + ((lane >> 4) << 4);
            ldm4(aaddr, qf[tl][ks]);
        }
    __syncthreads();   // Q reads done before overwrite

    issue_tile(sb,          bh, 0, gv, tid);
    issue_tile(sb + BUF_SZ, bh, 1, gv, tid);

    float z0[32], z1[32];
    #pragma unroll
    for (int i = 0; i < 32; i++) { z0[i] = 0.f; z1[i] = 0.f; }
    float rs[4] = {0.f, 0.f, 0.f, 0.f};
    __half* gSr = g_S + (bh*Sc + q0 + row0)*Sc;   // rows +0, +8Sc, +16Sc, +24Sc

    for (int kb = 0; kb < Sc/64; kb++) {
        if (kb < Sc/64 - 1) { CP_WAIT1(); } else { CP_WAIT0(); }
        __syncthreads();
        uint32_t buf = sb + (kb & 1)*BUF_SZ;

        // ---- scores: S = Q*K  (256x64, contraction 64) ----
        float s0[32], s1[32];
        #pragma unroll
        for (int i = 0; i < 32; i++) { s0[i] = 0.f; s1[i] = 0.f; }
        #pragma unroll
        for (int ks = 0; ks < 4; ks++) {
            #pragma unroll
            for (int nb2 = 0; nb2 < 4; nb2++) {
                uint32_t baddr = buf + (nb2*16 + (lane & 7) + ((lane >> 4) << 3))*144
                               + ks*32 + (((lane >> 3) & 1) << 4);
                uint32_t bhf[4];
                ldm4(baddr, bhf);
                mma16816h(s0 + 8*nb2,     qf[0][ks], bhf[0], bhf[1]);
                mma16816h(s0 + 8*nb2 + 4, qf[0][ks], bhf[2], bhf[3]);
                mma16816h(s1 + 8*nb2,     qf[1][ks], bhf[0], bhf[1]);
                mma16816h(s1 + 8*nb2 + 4, qf[1][ks], bhf[2], bhf[3]);
            }
        }

        // ---- fused epilogue + fp16 PV, per 16-key chunk m (C-frag == A-frag) ----
        #pragma unroll
        for (int m = 0; m < 4; m++) {
            int col = kb*64 + 16*m + 2*t;
            // tile 0 (rows row0, row0+8)
            float a0 = exp2f(s0[8*m+0]), a1 = exp2f(s0[8*m+1]);
            float a2 = exp2f(s0[8*m+2]), a3 = exp2f(s0[8*m+3]);
            float b0 = exp2f(s0[8*m+4]), b1 = exp2f(s0[8*m+5]);
            float b2 = exp2f(s0[8*m+6]), b3 = exp2f(s0[8*m+7]);
            rs[0] += a0 + a1 + b0 + b1;
            rs[1] += a2 + a3 + b2 + b3;
            uint32_t af0[4];
            __half2 p0 = __floats2half2_rn(a0, a1);
            __half2 p1 = __floats2half2_rn(a2, a3);
            __half2 p2 = __floats2half2_rn(b0, b1);
            __half2 p3 = __floats2half2_rn(b2, b3);
            af0[0] = *(uint32_t*)&p0; af0[1] = *(uint32_t*)&p1;
            af0[2] = *(uint32_t*)&p2; af0[3] = *(uint32_t*)&p3;
            *(__half2*)(gSr + col)              = p0;
            *(__half2*)(gSr + (size_t)8*Sc + col)  = p1;
            *(__half2*)(gSr + col + 8)          = p2;
            *(__half2*)(gSr + (size_t)8*Sc + col + 8) = p3;
            // tile 1 (rows row0+16, row0+24)
            float c0 = exp2f(s1[8*m+0]), c1 = exp2f(s1[8*m+1]);
            float c2 = exp2f(s1[8*m+2]), c3 = exp2f(s1[8*m+3]);
            float d0 = exp2f(s1[8*m+4]), d1 = exp2f(s1[8*m+5]);
            float d2 = exp2f(s1[8*m+6]), d3 = exp2f(s1[8*m+7]);
            rs[2] += c0 + c1 + d0 + d1;
            rs[3] += c2 + c3 + d2 + d3;
            uint32_t af1[4];
            __half2 q0h = __floats2half2_rn(c0, c1);
            __half2 q1h = __floats2half2_rn(c2, c3);
            __half2 q2h = __floats2half2_rn(d0, d1);
            __half2 q3h = __floats2half2_rn(d2, d3);
            af1[0] = *(uint32_t*)&q0h; af1[1] = *(uint32_t*)&q1h;
            af1[2] = *(uint32_t*)&q2h; af1[3] = *(uint32_t*)&q3h;
            *(__half2*)(gSr + (size_t)16*Sc + col)     = q0h;
            *(__half2*)(gSr + (size_t)24*Sc + col)     = q1h;
            *(__half2*)(gSr + (size_t)16*Sc + col + 8) = q2h;
            *(__half2*)(gSr + (size_t)24*Sc + col + 8) = q3h;

            #pragma unroll
            for (int nb2 = 0; nb2 < 4; nb2++) {
                uint32_t vaddr = buf + 9216 + (nb2*16 + (lane & 7) + ((lane >> 4) << 3))*144
                               + m*32 + (((lane >> 3) & 1) << 4);
                uint32_t bhf[4];
                ldm4(vaddr, bhf);
                mma16816h(z0 + 8*nb2,     af0, bhf[0], bhf[1]);
                mma16816h(z0 + 8*nb2 + 4, af0, bhf[2], bhf[3]);
                mma16816h(z1 + 8*nb2,     af1, bhf[0], bhf[1]);
                mma16816h(z1 + 8*nb2 + 4, af1, bhf[2], bhf[3]);
            }
        }
        __syncthreads();   // all warps done with this buffer
        if (kb + 2 < Sc/64)
            issue_tile(sb + (kb & 1)*BUF_SZ, bh, kb + 2, gv, tid);
    }

    // rowsum reduce within quad
    #pragma unroll
    for (int r = 0; r < 4; r++)
        #pragma unroll
        for (int o = 1; o <= 2; o <<= 1)
            rs[r] += __shfl_xor_sync(0xffffffffu, rs[r], o);
    float inv0 = 1.f/rs[0], inv1 = 1.f/rs[1], inv2 = 1.f/rs[2], inv3 = 1.f/rs[3];
    __half* zo = g_Z + ((size_t)b*Sc + q0 + row0)*Dc + h*64;
    #pragma unroll
    for (int nb = 0; nb < 8; nb++) {
        int col = nb*8 + 2*t;
        __half2 a = __floats2half2_rn(z0[nb*4+0]*inv0, z0[nb*4+1]*inv0);
        __half2 c = __floats2half2_rn(z0[nb*4+2]*inv1, z0[nb*4+3]*inv1);
        __half2 e = __floats2half2_rn(z1[nb*4+0]*inv2, z1[nb*4+1]*inv2);
        __half2 f = __floats2half2_rn(z1[nb*4+2]*inv3, z1[nb*4+3]*inv3);
        *(uint32_t*)(zo + col)                    = *(uint32_t*)&a;
        *(uint32_t*)(zo + (size_t)8*Dc + col)     = *(uint32_t*)&c;
        *(uint32_t*)(zo + (size_t)16*Dc + col)    = *(uint32_t*)&e;
        *(uint32_t*)(zo + (size_t)24*Dc + col)    = *(uint32_t*)&f;
    }
    if (t == 0) {
        g_isum[bh*Sc + q0 + row0]      = inv0;
        g_isum[bh*Sc + q0 + row0 + 8]  = inv1;
        g_isum[bh*Sc + q0 + row0 + 16] = inv2;
        g_isum[bh*Sc + q0 + row0 + 24] = inv3;
    }
}

// ---------------- attn_mean: am[b,q,k] = (1/H) sum_h g_S[b,h,q,k]*isum[b,h,q] ----------------
__global__ __launch_bounds__(256) void attn_mean_kernel(float* __restrict__ am)
{
    int q = blockIdx.x, b = blockIdx.y, t = threadIdx.x;
    float a[8] = {0.f,0.f,0.f,0.f,0.f,0.f,0.f,0.f};
    #pragma unroll 1
    for (int h = 0; h < Hc; h++) {
        size_t bh = (size_t)b*Hc + h;
        float w = g_isum[bh*Sc + q];
        const float4* row = (const float4*)(g_S + (bh*Sc + q)*Sc);
        float4 v = row[t];
        const __half2* hp = (const __half2*)&v;
        #pragma unroll
        for (int j = 0; j < 4; j++) {
            float2 f = __half22float2(hp[j]);
            a[2*j]   += f.x*w;
            a[2*j+1] += f.y*w;
        }
    }
    const float invH = 1.0f/Hc;
    float4* dst = (float4*)(am + ((size_t)b*Sc + q)*Sc);
    dst[2*t]   = make_float4(a[0]*invH, a[1]*invH, a[2]*invH, a[3]*invH);
    dst[2*t+1] = make_float4(a[4]*invH, a[5]*invH, a[6]*invH, a[7]*invH);
}

// ---------------- Output projection (fp16 HMMA, single pass Z x W) ----------------
#define SM_Z 0
#define SM_W 18432
#define SMEM_OP 36864

__device__ __forceinline__ void stage_op(char* smem, int off, const float4* gs,
                                         int base_row, int kc, int tid) {
    #pragma unroll
    for (int it = 0; it < 4; it++) {
        int i = tid + it*256;
        int r = i >> 3, c = i & 7;
        *(float4*)(smem + off + r*144 + c*16) = gs[(size_t)(base_row + r)*128 + kc*8 + c];
    }
}

__global__ __launch_bounds__(256,1) void out_proj_mma(
    const float* __restrict__ bz, float* __restrict__ out)
{
    extern __shared__ char smem[];
    uint32_t sb = (uint32_t)__cvta_generic_to_shared(smem);
    int tid = threadIdx.x, wid = tid >> 5, lane = tid & 31;
    int n0 = blockIdx.x*128, s0 = blockIdx.y*128;
    int t = lane & 3;
    int row0 = 16*wid + (lane >> 2);

    const float4* gz = (const float4*)g_Z;
    const float4* gw = (const float4*)g_Wz;

    float s[64];
    #pragma unroll
    for (int i = 0; i < 64; i++) s[i] = 0.f;

    for (int kc = 0; kc < 16; kc++) {
        if (kc) __syncthreads();
        stage_op(smem, SM_Z, gz, s0, kc, tid);
        stage_op(smem, SM_W, gw, n0, kc, tid);
        __syncthreads();

        #pragma unroll
        for (int ks = 0; ks < 4; ks++) {
            uint32_t aaddr = sb + SM_Z + (16*wid + (lane & 15))*144 + ks*32 + ((lane >> 4) << 4);
            uint32_t ah[4];
            ldm4(aaddr, ah);
            #pragma unroll
            for (int nb2 = 0; nb2 < 8; nb2++) {
                uint32_t baddr = sb + SM_W + (nb2*16 + (lane & 7) + ((lane >> 4) << 3))*144
                               + ks*32 + (((lane >> 3) & 1) << 4);
                uint32_t bhf[4];
                ldm4(baddr, bhf);
                mma16816h(s + (2*nb2)*4,   ah, bhf[0], bhf[1]);
                mma16816h(s + (2*nb2+1)*4, ah, bhf[2], bhf[3]);
            }
        }
    }

    float* o0 = out + (size_t)(s0 + row0)*Dc + n0;
    float* o1 = o0 + (size_t)8*Dc;
    #pragma unroll
    for (int nb = 0; nb < 16; nb++) {
        int col = nb*8 + 2*t;
        float b0 = bz[n0 + col], b1 = bz[n0 + col + 1];
        *(float2*)(o0 + col) = make_float2(s[nb*4+0] + b0, s[nb*4+1] + b1);
        *(float2*)(o1 + col) = make_float2(s[nb*4+2] + b0, s[nb*4+3] + b1);
    }
}

extern "C" void kernel_launch(void* const* d_in, const int* in_sizes, int n_in,
                              void* d_out, int out_size)
{
    const float* Xq = (const float*)d_in[0];
    const float* Xk = (const float*)d_in[1];
    const float* Xv = (const float*)d_in[2];
    const float* Wq = (const float*)d_in[3];
    const float* Wk = (const float*)d_in[4];
    const float* Wv = (const float*)d_in[5];
    const float* Wz = (const float*)d_in[6];
    const float* bz = (const float*)d_in[7];
    float* out  = (float*)d_out;
    float* attn = out + (size_t)Bc*Sc*Dc;   // out first, then attn_mean

    cudaFuncSetAttribute((const void*)qkv_mma,
                         cudaFuncAttributeMaxDynamicSharedMemorySize, SMEM_QP);
    cudaFuncSetAttribute((const void*)flash_attn,
                         cudaFuncAttributeMaxDynamicSharedMemorySize, SMEM_FL);
    cudaFuncSetAttribute((const void*)out_proj_mma,
                         cudaFuncAttributeMaxDynamicSharedMemorySize, SMEM_OP);

    w3_convert<<<dim3(64, 3), 256>>>(Wq, Wk, Wv);
    wz_convert<<<Dc*Dc/1024, 256>>>(Wz);
    qkv_mma<<<dim3(Sc/128, Hc, Bc), 256, SMEM_QP>>>(Xq, Xk, Xv);
    flash_attn<<<dim3(Sc/256, Hc, Bc), 256, SMEM_FL>>>();
    attn_mean_kernel<<<dim3(Sc, Bc), 256>>>(attn);
    out_proj_mma<<<dim3(Dc/128, (Bc*Sc)/128), 256, SMEM_OP>>>(bz, out);
}

// round 14
// speedup vs baseline: 11.1997x; 1.0853x over previous
#include <cuda_runtime.h>
#include <cuda_bf16.h>
#include <cuda_fp16.h>
#include <cstdint>

#define Bc 2
#define Sc 2048
#define Dc 1024
#define Hc 16
#define HDc 64

// ---------------- scratch globals (allocation-free) ----------------
__device__ __half g_Q [Bc*Hc*Sc*HDc];           // Q fp16 (scaled by inv4*log2e)
__device__ __half g_K [Bc*Hc*Sc*HDc];           // K fp16 (scaled by inv4)
__device__ __half g_Vt[Bc*Hc*Sc*HDc];           // V^T [b,h,e,s], fp16
__device__ __half g_Z [Bc*Sc*Dc];               // Z fp16 ([s][k])
__device__ __half g_Wz[Dc*Dc];                  // Wz fp16 ([n][k])
__device__ __half g_W3[3*Hc*HDc*HDc];           // Wq/Wk/Wv fp16 (concat)
__device__ __half g_S[134217728];               // [b,h,q,k] unnormalized exp(score)
__device__ float g_isum[Bc*Hc*Sc];              // 1/rowsum

// ---------------- warp MMA helpers (base ISA: valid on sm_103 plain) ----------------
__device__ __forceinline__ void ldm4(uint32_t addr, uint32_t* r) {
    asm volatile("ldmatrix.sync.aligned.m8n8.x4.shared.b16 {%0,%1,%2,%3}, [%4];"
                 : "=r"(r[0]), "=r"(r[1]), "=r"(r[2]), "=r"(r[3]) : "r"(addr));
}
__device__ __forceinline__ void mma16816h(float* c, const uint32_t* a, uint32_t b0, uint32_t b1) {
    asm volatile("mma.sync.aligned.m16n8k16.row.col.f32.f16.f16.f32 "
                 "{%0,%1,%2,%3}, {%4,%5,%6,%7}, {%8,%9}, {%0,%1,%2,%3};"
                 : "+f"(c[0]), "+f"(c[1]), "+f"(c[2]), "+f"(c[3])
                 : "r"(a[0]), "r"(a[1]), "r"(a[2]), "r"(a[3]), "r"(b0), "r"(b1));
}
__device__ __forceinline__ void split_h(float x, __half& hi, __half& lo) {
    hi = __float2half_rn(x);
    lo = __float2half_rn(x - __half2float(hi));
}
__device__ __forceinline__ void cpasync16(uint32_t daddr, const void* gptr) {
    asm volatile("cp.async.cg.shared.global [%0], [%1], 16;" :: "r"(daddr), "l"(gptr));
}
#define CP_COMMIT() asm volatile("cp.async.commit_group;" ::: "memory")
#define CP_WAIT1()  asm volatile("cp.async.wait_group 1;" ::: "memory")
#define CP_WAIT0()  asm volatile("cp.async.wait_group 0;" ::: "memory")

// ---------------- W converts (single fp16) ----------------
__global__ __launch_bounds__(256) void w3_convert(
    const float* __restrict__ Wq, const float* __restrict__ Wk, const float* __restrict__ Wv)
{
    const float* src = (blockIdx.y == 0) ? Wq : (blockIdx.y == 1 ? Wk : Wv);
    int i = (blockIdx.x*256 + threadIdx.x)*4;          // over 65536 elems
    int o = blockIdx.y*65536 + i;
    float4 v = *(const float4*)(src + i);
    __half2 a = __floats2half2_rn(v.x, v.y);
    __half2 b = __floats2half2_rn(v.z, v.w);
    *(uint32_t*)(g_W3 + o)     = *(uint32_t*)&a;
    *(uint32_t*)(g_W3 + o + 2) = *(uint32_t*)&b;
}
__global__ __launch_bounds__(256) void wz_convert(const float* __restrict__ Wz)
{
    int i = (blockIdx.x*256 + threadIdx.x)*4;
    float4 v = *(const float4*)(Wz + i);
    __half2 a = __floats2half2_rn(v.x, v.y);
    __half2 b = __floats2half2_rn(v.z, v.w);
    *(uint32_t*)(g_Wz + i)     = *(uint32_t*)&a;
    *(uint32_t*)(g_Wz + i + 2) = *(uint32_t*)&b;
}

// ---------------- QKV projection (warp HMMA, X hi/lo x W, 2-pass) ----------------
#define QP_XH 0
#define QP_XL 18432
#define QP_WH 36864
#define QP_XF 46080
#define SMEM_QP 80896

__global__ __launch_bounds__(256,1) void qkv_mma(
    const float* __restrict__ Xq, const float* __restrict__ Xk, const float* __restrict__ Xv)
{
    extern __shared__ char smem[];
    uint32_t sb = (uint32_t)__cvta_generic_to_shared(smem);
    int tid = threadIdx.x, wid = tid >> 5, lane = tid & 31;
    int s0 = blockIdx.x*128, h = blockIdx.y, b = blockIdx.z;
    size_t bh = (size_t)b*Hc + h;
    int tq = lane & 3;
    int row0 = 16*wid + (lane >> 2);

    const float inv4 = 0.35355339059327373f;
    const float l2e  = 1.4426950408889634f;
    const float* Xp[3] = {Xq, Xk, Xv};
    const float scl[3] = {inv4*l2e, inv4, 1.0f};

    for (int t = 0; t < 3; t++) {
        const float* X = Xp[t];
        for (int i = tid; i < 2048; i += 256) {
            int r = i >> 4, c = i & 15;
            cpasync16(sb + QP_XF + r*272 + c*16,
                      (const float4*)(X + ((size_t)(b*Sc + s0 + r))*Dc + h*64) + c);
        }
        int toff = t*65536 + h*4096;
        for (int i = tid; i < 512; i += 256) {
            int r = i >> 3, c = i & 7;
            cpasync16(sb + QP_WH + r*144 + c*16, (const float4*)(g_W3 + toff + r*64) + c);
        }
        CP_COMMIT(); CP_WAIT0();
        __syncthreads();

        const float* xf = (const float*)(smem + QP_XF);
        for (int p = tid; p < 4096; p += 256) {
            int r = p >> 5, dp = p & 31;
            float f0 = xf[r*68 + 2*dp], f1 = xf[r*68 + 2*dp + 1];
            __half h0,l0,h1,l1; split_h(f0,h0,l0); split_h(f1,h1,l1);
            __half2 hh = __halves2half2(h0,h1), ll = __halves2half2(l0,l1);
            *(uint32_t*)(smem + QP_XH + r*144 + 4*dp) = *(uint32_t*)&hh;
            *(uint32_t*)(smem + QP_XL + r*144 + 4*dp) = *(uint32_t*)&ll;
        }
        __syncthreads();

        uint32_t xh[4][4], xl[4][4];
        #pragma unroll
        for (int ks = 0; ks < 4; ks++) {
            uint32_t aaddr = sb + QP_XH + (16*wid + (lane & 15))*144 + ks*32 + ((lane >> 4) << 4);
            ldm4(aaddr, xh[ks]);
            ldm4(aaddr + (QP_XL - QP_XH), xl[ks]);
        }

        float s[32];
        #pragma unroll
        for (int i = 0; i < 32; i++) s[i] = 0.f;
        #pragma unroll
        for (int ks = 0; ks < 4; ks++) {
            #pragma unroll
            for (int nb2 = 0; nb2 < 4; nb2++) {
                uint32_t baddr = sb + QP_WH + (nb2*16 + (lane & 7) + ((lane >> 4) << 3))*144
                               + ks*32 + (((lane >> 3) & 1) << 4);
                uint32_t wh4[4];
                ldm4(baddr, wh4);
                mma16816h(s + 8*nb2,     xh[ks], wh4[0], wh4[1]);
                mma16816h(s + 8*nb2 + 4, xh[ks], wh4[2], wh4[3]);
                mma16816h(s + 8*nb2,     xl[ks], wh4[0], wh4[1]);
                mma16816h(s + 8*nb2 + 4, xl[ks], wh4[2], wh4[3]);
            }
        }

        if (t < 2) {
            __half* O = (t == 0 ? g_Q : g_K) + (bh*Sc + s0 + row0)*64;
            float sc = scl[t];
            #pragma unroll
            for (int nb = 0; nb < 8; nb++) {
                int col = nb*8 + 2*tq;
                __half2 a = __floats2half2_rn(s[4*nb+0]*sc, s[4*nb+1]*sc);
                __half2 c = __floats2half2_rn(s[4*nb+2]*sc, s[4*nb+3]*sc);
                *(uint32_t*)(O + col)          = *(uint32_t*)&a;
                *(uint32_t*)(O + 8*64 + col)   = *(uint32_t*)&c;
            }
        } else {
            __half* vb = (__half*)(smem + QP_XF);   // [64 e][136 s]
            #pragma unroll
            for (int nb = 0; nb < 8; nb++) {
                int col = nb*8 + 2*tq;
                vb[col*136 + row0]           = __float2half_rn(s[4*nb+0]);
                vb[(col+1)*136 + row0]       = __float2half_rn(s[4*nb+1]);
                vb[col*136 + row0 + 8]       = __float2half_rn(s[4*nb+2]);
                vb[(col+1)*136 + row0 + 8]   = __float2half_rn(s[4*nb+3]);
            }
            __syncthreads();
            __half* Ov = g_Vt + bh*(size_t)64*Sc;
            for (int u = tid; u < 4096; u += 256) {
                int e = u >> 6, sc2 = u & 63;
                uint32_t v = *(uint32_t*)&vb[e*136 + 2*sc2];
                *(uint32_t*)(Ov + (size_t)e*Sc + s0 + 2*sc2) = v;
            }
        }
        __syncthreads();
    }
}

// ---------------- flash attention (fp16 HMMA, M=32/warp, chunk-interleaved, 2 blk/SM) --
// grid (S/256, H, B), 256 threads (8 warps x 32 q-rows), 36KB dyn smem.
// Buffer: K +0 (9216 = 64x144), V +9216 (9216). BUF_SZ 18432, two buffers.
// Prologue stages Q (256x144 = 36864) across the whole region.
#define BUF_SZ  18432
#define SMEM_FL 36864

__device__ __forceinline__ void stage_k_async(uint32_t dst, const float4* gsrc, int tid) {
    for (int i = tid; i < 512; i += 256) {
        int r = i >> 3, c = i & 7;
        cpasync16(dst + r*144 + c*16, gsrc + i);
    }
}
__device__ __forceinline__ void stage_v_async(uint32_t dst, const float4* gv, int kb, int tid) {
    for (int i = tid; i < 512; i += 256) {
        int e = i >> 3, c = i & 7;
        cpasync16(dst + e*144 + c*16, gv + e*256 + kb*8 + c);
    }
}
__device__ __forceinline__ void issue_tile(uint32_t buf, size_t bh, int kb,
                                           const float4* gv, int tid) {
    const float4* kh = (const float4*)g_K + ((bh*Sc + (size_t)kb*64) << 3);
    stage_k_async(buf,        kh, tid);
    stage_v_async(buf + 9216, gv, kb, tid);
    CP_COMMIT();
}

__global__ __launch_bounds__(256,2) void flash_attn()
{
    extern __shared__ char smem[];
    uint32_t sb = (uint32_t)__cvta_generic_to_shared(smem);
    int tid = threadIdx.x, wid = tid >> 5, lane = tid & 31;
    int q0 = blockIdx.x*256, h = blockIdx.y, b = blockIdx.z;
    size_t bh = (size_t)b*Hc + h;
    int t = lane & 3;
    int row0 = 32*wid + (lane >> 2);   // rows row0, +8, +16, +24

    const float4* gv = (const float4*)(g_Vt + bh*(size_t)64*Sc);

    // --- prologue: Q (256 rows) into full smem region, load fragments ---
    {
        const float4* gq = (const float4*)g_Q + ((bh*Sc + q0) << 3);
        for (int i = tid; i < 2048; i += 256) {
            int r = i >> 3, c = i & 7;
            cpasync16(sb + r*144 + c*16, gq + i);
        }
    }
    CP_COMMIT(); CP_WAIT0();
    __syncthreads();

    uint32_t qf[2][4][4];
    #pragma unroll
    for (int tl = 0; tl < 2; tl++)
        #pragma unroll
        for (int ks = 0; ks < 4; ks++) {
            uint32_t aaddr = sb + (32*wid + tl*16 + (lane & 15))*144 + ks*32 + ((lane >> 4) << 4);
            ldm4(aaddr, qf[tl][ks]);
        }
    __syncthreads();   // Q reads done before overwrite

    issue_tile(sb,          bh, 0, gv, tid);
    issue_tile(sb + BUF_SZ, bh, 1, gv, tid);

    float z0[32], z1[32];
    #pragma unroll
    for (int i = 0; i < 32; i++) { z0[i] = 0.f; z1[i] = 0.f; }
    float rs[4] = {0.f, 0.f, 0.f, 0.f};
    __half* gSr = g_S + (bh*Sc + q0 + row0)*Sc;   // rows +0, +8Sc, +16Sc, +24Sc

    for (int kb = 0; kb < Sc/64; kb++) {
        if (kb < Sc/64 - 1) { CP_WAIT1(); } else { CP_WAIT0(); }
        __syncthreads();
        uint32_t buf = sb + (kb & 1)*BUF_SZ;

        // ---- per 16-key chunk: QK -> epilogue -> PV (small live score set) ----
        #pragma unroll
        for (int m = 0; m < 4; m++) {
            float s0[8], s1[8];
            #pragma unroll
            for (int i = 0; i < 8; i++) { s0[i] = 0.f; s1[i] = 0.f; }
            #pragma unroll
            for (int ks = 0; ks < 4; ks++) {
                uint32_t baddr = buf + (m*16 + (lane & 7) + ((lane >> 4) << 3))*144
                               + ks*32 + (((lane >> 3) & 1) << 4);
                uint32_t bhf[4];
                ldm4(baddr, bhf);
                mma16816h(s0,     qf[0][ks], bhf[0], bhf[1]);
                mma16816h(s0 + 4, qf[0][ks], bhf[2], bhf[3]);
                mma16816h(s1,     qf[1][ks], bhf[0], bhf[1]);
                mma16816h(s1 + 4, qf[1][ks], bhf[2], bhf[3]);
            }

            int col = kb*64 + 16*m + 2*t;
            // tile 0 (rows row0, row0+8)
            float a0 = exp2f(s0[0]), a1 = exp2f(s0[1]);
            float a2 = exp2f(s0[2]), a3 = exp2f(s0[3]);
            float b0 = exp2f(s0[4]), b1 = exp2f(s0[5]);
            float b2 = exp2f(s0[6]), b3 = exp2f(s0[7]);
            rs[0] += a0 + a1 + b0 + b1;
            rs[1] += a2 + a3 + b2 + b3;
            uint32_t af0[4];
            __half2 p0 = __floats2half2_rn(a0, a1);
            __half2 p1 = __floats2half2_rn(a2, a3);
            __half2 p2 = __floats2half2_rn(b0, b1);
            __half2 p3 = __floats2half2_rn(b2, b3);
            af0[0] = *(uint32_t*)&p0; af0[1] = *(uint32_t*)&p1;
            af0[2] = *(uint32_t*)&p2; af0[3] = *(uint32_t*)&p3;
            *(__half2*)(gSr + col)                    = p0;
            *(__half2*)(gSr + (size_t)8*Sc + col)     = p1;
            *(__half2*)(gSr + col + 8)                = p2;
            *(__half2*)(gSr + (size_t)8*Sc + col + 8) = p3;
            // tile 1 (rows row0+16, row0+24)
            float c0 = exp2f(s1[0]), c1 = exp2f(s1[1]);
            float c2 = exp2f(s1[2]), c3 = exp2f(s1[3]);
            float d0 = exp2f(s1[4]), d1 = exp2f(s1[5]);
            float d2 = exp2f(s1[6]), d3 = exp2f(s1[7]);
            rs[2] += c0 + c1 + d0 + d1;
            rs[3] += c2 + c3 + d2 + d3;
            uint32_t af1[4];
            __half2 q0h = __floats2half2_rn(c0, c1);
            __half2 q1h = __floats2half2_rn(c2, c3);
            __half2 q2h = __floats2half2_rn(d0, d1);
            __half2 q3h = __floats2half2_rn(d2, d3);
            af1[0] = *(uint32_t*)&q0h; af1[1] = *(uint32_t*)&q1h;
            af1[2] = *(uint32_t*)&q2h; af1[3] = *(uint32_t*)&q3h;
            *(__half2*)(gSr + (size_t)16*Sc + col)     = q0h;
            *(__half2*)(gSr + (size_t)24*Sc + col)     = q1h;
            *(__half2*)(gSr + (size_t)16*Sc + col + 8) = q2h;
            *(__half2*)(gSr + (size_t)24*Sc + col + 8) = q3h;

            #pragma unroll
            for (int nb2 = 0; nb2 < 4; nb2++) {
                uint32_t vaddr = buf + 9216 + (nb2*16 + (lane & 7) + ((lane >> 4) << 3))*144
                               + m*32 + (((lane >> 3) & 1) << 4);
                uint32_t bhf[4];
                ldm4(vaddr, bhf);
                mma16816h(z0 + 8*nb2,     af0, bhf[0], bhf[1]);
                mma16816h(z0 + 8*nb2 + 4, af0, bhf[2], bhf[3]);
                mma16816h(z1 + 8*nb2,     af1, bhf[0], bhf[1]);
                mma16816h(z1 + 8*nb2 + 4, af1, bhf[2], bhf[3]);
            }
        }
        __syncthreads();   // all warps done with this buffer
        if (kb + 2 < Sc/64)
            issue_tile(sb + (kb & 1)*BUF_SZ, bh, kb + 2, gv, tid);
    }

    // rowsum reduce within quad
    #pragma unroll
    for (int r = 0; r < 4; r++)
        #pragma unroll
        for (int o = 1; o <= 2; o <<= 1)
            rs[r] += __shfl_xor_sync(0xffffffffu, rs[r], o);
    float inv0 = 1.f/rs[0], inv1 = 1.f/rs[1], inv2 = 1.f/rs[2], inv3 = 1.f/rs[3];
    __half* zo = g_Z + ((size_t)b*Sc + q0 + row0)*Dc + h*64;
    #pragma unroll
    for (int nb = 0; nb < 8; nb++) {
        int col = nb*8 + 2*t;
        __half2 a = __floats2half2_rn(z0[nb*4+0]*inv0, z0[nb*4+1]*inv0);
        __half2 c = __floats2half2_rn(z0[nb*4+2]*inv1, z0[nb*4+3]*inv1);
        __half2 e = __floats2half2_rn(z1[nb*4+0]*inv2, z1[nb*4+1]*inv2);
        __half2 f = __floats2half2_rn(z1[nb*4+2]*inv3, z1[nb*4+3]*inv3);
        *(uint32_t*)(zo + col)                    = *(uint32_t*)&a;
        *(uint32_t*)(zo + (size_t)8*Dc + col)     = *(uint32_t*)&c;
        *(uint32_t*)(zo + (size_t)16*Dc + col)    = *(uint32_t*)&e;
        *(uint32_t*)(zo + (size_t)24*Dc + col)    = *(uint32_t*)&f;
    }
    if (t == 0) {
        g_isum[bh*Sc + q0 + row0]      = inv0;
        g_isum[bh*Sc + q0 + row0 + 8]  = inv1;
        g_isum[bh*Sc + q0 + row0 + 16] = inv2;
        g_isum[bh*Sc + q0 + row0 + 24] = inv3;
    }
}

// ---------------- attn_mean: am[b,q,k] = (1/H) sum_h g_S[b,h,q,k]*isum[b,h,q] ----------------
__global__ __launch_bounds__(256) void attn_mean_kernel(float* __restrict__ am)
{
    int q = blockIdx.x, b = blockIdx.y, t = threadIdx.x;
    float a[8] = {0.f,0.f,0.f,0.f,0.f,0.f,0.f,0.f};
    #pragma unroll 1
    for (int h = 0; h < Hc; h++) {
        size_t bh = (size_t)b*Hc + h;
        float w = g_isum[bh*Sc + q];
        const float4* row = (const float4*)(g_S + (bh*Sc + q)*Sc);
        float4 v = row[t];
        const __half2* hp = (const __half2*)&v;
        #pragma unroll
        for (int j = 0; j < 4; j++) {
            float2 f = __half22float2(hp[j]);
            a[2*j]   += f.x*w;
            a[2*j+1] += f.y*w;
        }
    }
    const float invH = 1.0f/Hc;
    float4* dst = (float4*)(am + ((size_t)b*Sc + q)*Sc);
    dst[2*t]   = make_float4(a[0]*invH, a[1]*invH, a[2]*invH, a[3]*invH);
    dst[2*t+1] = make_float4(a[4]*invH, a[5]*invH, a[6]*invH, a[7]*invH);
}

// ---------------- Output projection (fp16 HMMA, single pass Z x W) ----------------
#define SM_Z 0
#define SM_W 18432
#define SMEM_OP 36864

__device__ __forceinline__ void stage_op(char* smem, int off, const float4* gs,
                                         int base_row, int kc, int tid) {
    #pragma unroll
    for (int it = 0; it < 4; it++) {
        int i = tid + it*256;
        int r = i >> 3, c = i & 7;
        *(float4*)(smem + off + r*144 + c*16) = gs[(size_t)(base_row + r)*128 + kc*8 + c];
    }
}

__global__ __launch_bounds__(256,1) void out_proj_mma(
    const float* __restrict__ bz, float* __restrict__ out)
{
    extern __shared__ char smem[];
    uint32_t sb = (uint32_t)__cvta_generic_to_shared(smem);
    int tid = threadIdx.x, wid = tid >> 5, lane = tid & 31;
    int n0 = blockIdx.x*128, s0 = blockIdx.y*128;
    int t = lane & 3;
    int row0 = 16*wid + (lane >> 2);

    const float4* gz = (const float4*)g_Z;
    const float4* gw = (const float4*)g_Wz;

    float s[64];
    #pragma unroll
    for (int i = 0; i < 64; i++) s[i] = 0.f;

    for (int kc = 0; kc < 16; kc++) {
        if (kc) __syncthreads();
        stage_op(smem, SM_Z, gz, s0, kc, tid);
        stage_op(smem, SM_W, gw, n0, kc, tid);
        __syncthreads();

        #pragma unroll
        for (int ks = 0; ks < 4; ks++) {
            uint32_t aaddr = sb + SM_Z + (16*wid + (lane & 15))*144 + ks*32 + ((lane >> 4) << 4);
            uint32_t ah[4];
            ldm4(aaddr, ah);
            #pragma unroll
            for (int nb2 = 0; nb2 < 8; nb2++) {
                uint32_t baddr = sb + SM_W + (nb2*16 + (lane & 7) + ((lane >> 4) << 3))*144
                               + ks*32 + (((lane >> 3) & 1) << 4);
                uint32_t bhf[4];
                ldm4(baddr, bhf);
                mma16816h(s + (2*nb2)*4,   ah, bhf[0], bhf[1]);
                mma16816h(s + (2*nb2+1)*4, ah, bhf[2], bhf[3]);
            }
        }
    }

    float* o0 = out + (size_t)(s0 + row0)*Dc + n0;
    float* o1 = o0 + (size_t)8*Dc;
    #pragma unroll
    for (int nb = 0; nb < 16; nb++) {
        int col = nb*8 + 2*t;
        float b0 = bz[n0 + col], b1 = bz[n0 + col + 1];
        *(float2*)(o0 + col) = make_float2(s[nb*4+0] + b0, s[nb*4+1] + b1);
        *(float2*)(o1 + col) = make_float2(s[nb*4+2] + b0, s[nb*4+3] + b1);
    }
}

extern "C" void kernel_launch(void* const* d_in, const int* in_sizes, int n_in,
                              void* d_out, int out_size)
{
    const float* Xq = (const float*)d_in[0];
    const float* Xk = (const float*)d_in[1];
    const float* Xv = (const float*)d_in[2];
    const float* Wq = (const float*)d_in[3];
    const float* Wk = (const float*)d_in[4];
    const float* Wv = (const float*)d_in[5];
    const float* Wz = (const float*)d_in[6];
    const float* bz = (const float*)d_in[7];
    float* out  = (float*)d_out;
    float* attn = out + (size_t)Bc*Sc*Dc;   // out first, then attn_mean

    cudaFuncSetAttribute((const void*)qkv_mma,
                         cudaFuncAttributeMaxDynamicSharedMemorySize, SMEM_QP);
    cudaFuncSetAttribute((const void*)flash_attn,
                         cudaFuncAttributeMaxDynamicSharedMemorySize, SMEM_FL);
    cudaFuncSetAttribute((const void*)out_proj_mma,
                         cudaFuncAttributeMaxDynamicSharedMemorySize, SMEM_OP);

    w3_convert<<<dim3(64, 3), 256>>>(Wq, Wk, Wv);
    wz_convert<<<Dc*Dc/1024, 256>>>(Wz);
    qkv_mma<<<dim3(Sc/128, Hc, Bc), 256, SMEM_QP>>>(Xq, Xk, Xv);
    flash_attn<<<dim3(Sc/256, Hc, Bc), 256, SMEM_FL>>>();
    attn_mean_kernel<<<dim3(Sc, Bc), 256>>>(attn);
    out_proj_mma<<<dim3(Dc/128, (Bc*Sc)/128), 256, SMEM_OP>>>(bz, out);
}